// round 1
// baseline (speedup 1.0000x reference)
#include <cuda_runtime.h>

// ---------------------------------------------------------------------------
// Quaternion Hamilton-product tables: output comp t, input comp s
//   y_t = sum_s sgn[t][s] * cc(x_s, w_{cmp[t][s]})
// ---------------------------------------------------------------------------
__constant__ int   c_cmp[16] = {0,1,2,3,  1,0,3,2,  2,3,0,1,  3,2,1,0};
__constant__ float c_sgn[16] = {1.f,-1.f,-1.f,-1.f,
                                1.f, 1.f, 1.f,-1.f,
                                1.f,-1.f, 1.f, 1.f,
                                1.f, 1.f,-1.f, 1.f};

// ---------------------------------------------------------------------------
// Scratch (device globals; no allocation in kernel_launch)
// ---------------------------------------------------------------------------
__device__ float g_buf1[4*512*1024];  // stage1 output (rows 0..255 = a, 256..511 = b); later ffn2 out reuses rows 0..255
__device__ float g_buf2[4*768*1024];  // qkv out / ffn1 out / cv2 out
__device__ float g_buf3[4*256*1024];  // attn out / proj out
__device__ float g_buf4[4*256*1024];  // pe-added
__device__ float g_W[1048576];        // expanded weights
__device__ float g_scale[768];
__device__ float g_shift[768];

#define OFF_W1 0
#define OFF_WQ (OFF_W1 + 512*512)
#define OFF_WP (OFF_WQ + 768*256)
#define OFF_F1 (OFF_WP + 256*256)
#define OFF_F2 (OFF_F1 + 512*256)
#define OFF_C2 (OFF_F2 + 256*512)

// ---------------------------------------------------------------------------
// Expand quaternion 1x1 conv weight w[4][Cout][Cin] -> W4[4Cout][4Cin]
//   W4[co*4+t][ci*4+s] = sgn(t,s) * w[cmp(t,s)][co][ci]
// ---------------------------------------------------------------------------
__global__ void expand_w_kernel(const float* __restrict__ w, float* __restrict__ W4,
                                int Cout, int Cin) {
    int total = 16 * Cout * Cin;
    for (int i = blockIdx.x * blockDim.x + threadIdx.x; i < total;
         i += gridDim.x * blockDim.x) {
        int s = i & 3, t = (i >> 2) & 3;
        int rest = i >> 4;
        int ci = rest % Cin, co = rest / Cin;
        W4[(co*4 + t) * (4*Cin) + ci*4 + s] =
            c_sgn[t*4 + s] * w[c_cmp[t*4 + s] * Cout * Cin + co * Cin + ci];
    }
}

// ---------------------------------------------------------------------------
// SGEMM: Y[b] (MxN) = W (MxK) * X[b] (KxN) + bias[m], N = 1024 fixed.
// Tile 64x64, BK=16, 256 threads, 4x4 per thread, float4 smem paths.
// ---------------------------------------------------------------------------
__global__ void sgemm_kernel(const float* __restrict__ W, const float* __restrict__ X,
                             float* __restrict__ Y, const float* __restrict__ bias,
                             int M, int K, long sX, long sY) {
    __shared__ float As[16][68];   // [k][m], padded
    __shared__ float Bs[16][64];   // [k][n]
    const float* Xb = X + blockIdx.z * sX;
    float*       Yb = Y + blockIdx.z * sY;
    int mo = blockIdx.y * 64, no = blockIdx.x * 64;
    int tid = threadIdx.x;
    int tx = tid & 15, ty = tid >> 4;
    int am = tid >> 2, ak = (tid & 3) * 4;  // A tile load: 64 rows x 16 k
    int bk = tid >> 4, bn = (tid & 15) * 4; // B tile load: 16 k x 64 n
    float acc[4][4] = {};
    for (int kt = 0; kt < K; kt += 16) {
        float4 a4 = *(const float4*)(W + (long)(mo + am) * K + kt + ak);
        As[ak + 0][am] = a4.x; As[ak + 1][am] = a4.y;
        As[ak + 2][am] = a4.z; As[ak + 3][am] = a4.w;
        *(float4*)&Bs[bk][bn] = *(const float4*)(Xb + (long)(kt + bk) * 1024 + no + bn);
        __syncthreads();
#pragma unroll
        for (int k = 0; k < 16; k++) {
            float4 av = *(const float4*)&As[k][ty * 4];
            float4 bv = *(const float4*)&Bs[k][tx * 4];
            float aa[4] = {av.x, av.y, av.z, av.w};
            float bb[4] = {bv.x, bv.y, bv.z, bv.w};
#pragma unroll
            for (int i = 0; i < 4; i++)
#pragma unroll
                for (int j = 0; j < 4; j++)
                    acc[i][j] += aa[i] * bb[j];
        }
        __syncthreads();
    }
#pragma unroll
    for (int i = 0; i < 4; i++) {
        int row = mo + ty * 4 + i;
        float bi = bias ? bias[row] : 0.f;
        float4 v = make_float4(acc[i][0] + bi, acc[i][1] + bi,
                               acc[i][2] + bi, acc[i][3] + bi);
        *(float4*)(Yb + (long)row * 1024 + no + tx * 4) = v;
    }
}

// ---------------------------------------------------------------------------
// Per-row batchnorm stats over (batch=4, 1024 pixels); fold gamma/beta into
// scale/shift. One CTA per row m. Deterministic (no atomics).
// ---------------------------------------------------------------------------
__global__ void stats_kernel(const float* __restrict__ X, long bstride,
                             const float* __restrict__ g, const float* __restrict__ be,
                             float* __restrict__ scale, float* __restrict__ shift) {
    int m = blockIdx.x;
    int tid = threadIdx.x;
    float s = 0.f, sq = 0.f;
    for (int b = 0; b < 4; b++) {
        const float* p = X + b * bstride + (long)m * 1024;
        for (int i = tid; i < 1024; i += 256) {
            float v = p[i];
            s += v; sq += v * v;
        }
    }
    __shared__ float rs[256], rq[256];
    rs[tid] = s; rq[tid] = sq;
    __syncthreads();
    for (int o = 128; o > 0; o >>= 1) {
        if (tid < o) { rs[tid] += rs[tid + o]; rq[tid] += rq[tid + o]; }
        __syncthreads();
    }
    if (tid == 0) {
        float mean = rs[0] * (1.f / 4096.f);
        float var  = rq[0] * (1.f / 4096.f) - mean * mean;
        float rstd = rsqrtf(var + 1e-5f);
        float sc = g[m] * rstd;
        scale[m] = sc;
        shift[m] = be[m] - mean * sc;
    }
}

__global__ void bn_apply_kernel(const float* __restrict__ X, float* __restrict__ Y,
                                const float* __restrict__ scale,
                                const float* __restrict__ shift,
                                int M, long bsX, long bsY, int relu) {
    long per = (long)M * 1024;
    long total = 4 * per;
    for (long i = blockIdx.x * (long)blockDim.x + threadIdx.x; i < total;
         i += (long)gridDim.x * blockDim.x) {
        long b = i / per;
        long r = i - b * per;
        int m = (int)(r >> 10);
        float v = X[b * bsX + r] * scale[m] + shift[m];
        if (relu) v = fmaxf(v, 0.f);
        Y[b * bsY + r] = v;
    }
}

// ---------------------------------------------------------------------------
// Attention: per slice (b, head, t): S = Q^T K * 0.25 (d=16), softmax over m,
// O = P V^T. Scores kept entirely in SMEM (32 rows x 1024, pitch 1028).
// grid = (32 row-tiles, head*4+t = 16, batch = 4), 256 threads.
// ---------------------------------------------------------------------------
#define SPITCH 1028
#define ATTN_SMEM_FLOATS (32*SPITCH + 16*128 + 32*16 + 32)

__global__ void attn_kernel(const float* __restrict__ Yq, float* __restrict__ O) {
    extern __shared__ float sm[];
    float* S    = sm;                      // 32 x 1028
    float* kv   = S + 32 * SPITCH;         // 16 x 128 chunk (K then V)
    float* qs   = kv + 16 * 128;           // 32 rows x 16 d
    float* rinv = qs + 32 * 16;            // 32 inverse sums

    int b = blockIdx.z;
    int head = blockIdx.y >> 2, t = blockIdx.y & 3;
    int r0 = blockIdx.x * 32;
    const float* Yb = Yq + (long)b * 768 * 1024;
    int tid = threadIdx.x;

    // load Q rows (32 queries x 16 dims)
    for (int i = tid; i < 512; i += 256) {
        int dd = i >> 5, n = i & 31;
        qs[n * 16 + dd] = Yb[(head * 192 + dd * 4 + t) * 1024 + r0 + n];
    }

    int ty = tid >> 4, tx = tid & 15;
    const float sc = 0.25f;

    // Phase 1: scores
    for (int ch = 0; ch < 8; ch++) {
        __syncthreads();
        for (int i = tid; i < 2048; i += 256) {
            int dd = i >> 7, mm = i & 127;
            kv[i] = Yb[(head * 192 + 64 + dd * 4 + t) * 1024 + ch * 128 + mm];
        }
        __syncthreads();
        float a0[8] = {}, a1[8] = {};
#pragma unroll
        for (int dd = 0; dd < 16; dd++) {
            float q0 = qs[ty * 16 + dd];
            float q1 = qs[(ty + 16) * 16 + dd];
            float4 kA = *(float4*)&kv[dd * 128 + tx * 8];
            float4 kB = *(float4*)&kv[dd * 128 + tx * 8 + 4];
            float kk[8] = {kA.x, kA.y, kA.z, kA.w, kB.x, kB.y, kB.z, kB.w};
#pragma unroll
            for (int j = 0; j < 8; j++) { a0[j] += q0 * kk[j]; a1[j] += q1 * kk[j]; }
        }
        int base0 = ty * SPITCH + ch * 128 + tx * 8;
        int base1 = (ty + 16) * SPITCH + ch * 128 + tx * 8;
        *(float4*)&S[base0]     = make_float4(a0[0]*sc, a0[1]*sc, a0[2]*sc, a0[3]*sc);
        *(float4*)&S[base0 + 4] = make_float4(a0[4]*sc, a0[5]*sc, a0[6]*sc, a0[7]*sc);
        *(float4*)&S[base1]     = make_float4(a1[0]*sc, a1[1]*sc, a1[2]*sc, a1[3]*sc);
        *(float4*)&S[base1 + 4] = make_float4(a1[4]*sc, a1[5]*sc, a1[6]*sc, a1[7]*sc);
    }
    __syncthreads();

    // Phase 2: softmax per row (8 warps x 4 rows)
    int lane = tid & 31, warp = tid >> 5;
    for (int rr = warp; rr < 32; rr += 8) {
        float* Sr = S + rr * SPITCH;
        float mx = -1e30f;
        for (int m = lane; m < 1024; m += 32) mx = fmaxf(mx, Sr[m]);
#pragma unroll
        for (int o = 16; o; o >>= 1) mx = fmaxf(mx, __shfl_xor_sync(0xffffffffu, mx, o));
        float sum = 0.f;
        for (int m = lane; m < 1024; m += 32) {
            float e = __expf(Sr[m] - mx);
            Sr[m] = e; sum += e;
        }
#pragma unroll
        for (int o = 16; o; o >>= 1) sum += __shfl_xor_sync(0xffffffffu, sum, o);
        if (lane == 0) rinv[rr] = 1.f / sum;
    }
    __syncthreads();

    // Phase 3: O = P V^T ; lane = local row r, warp = dd (and dd+8)
    int r = tid & 31, dd = tid >> 5;
    float o0 = 0.f, o1 = 0.f;
    for (int ch = 0; ch < 8; ch++) {
        __syncthreads();
        for (int i = tid; i < 2048; i += 256) {
            int d2 = i >> 7, mm = i & 127;
            kv[i] = Yb[(head * 192 + 128 + d2 * 4 + t) * 1024 + ch * 128 + mm];
        }
        __syncthreads();
        float* Sr = S + r * SPITCH + ch * 128;
#pragma unroll
        for (int m4 = 0; m4 < 128; m4 += 4) {
            float4 p  = *(float4*)&Sr[m4];
            float4 v0 = *(float4*)&kv[dd * 128 + m4];
            float4 v1 = *(float4*)&kv[(dd + 8) * 128 + m4];
            o0 += p.x*v0.x + p.y*v0.y + p.z*v0.z + p.w*v0.w;
            o1 += p.x*v1.x + p.y*v1.y + p.z*v1.z + p.w*v1.w;
        }
    }
    float* Ob = O + (long)b * 256 * 1024;
    float inv = rinv[r];
    Ob[(head * 64 + dd * 4 + t) * 1024 + r0 + r]       = o0 * inv;
    Ob[(head * 64 + (dd + 8) * 4 + t) * 1024 + r0 + r] = o1 * inv;
}

// ---------------------------------------------------------------------------
// Positional-encoding conv: grouped quaternion 3x3 pad 1 (groups=16, Cin/g=4),
// out = in + pe(in) + pe_b. One thread per output element.
// ---------------------------------------------------------------------------
__global__ void pe_kernel(const float* __restrict__ I, const float* __restrict__ pw,
                          const float* __restrict__ pb, float* __restrict__ Out) {
    int idx = blockIdx.x * 256 + threadIdx.x;
    if (idx >= 4 * 256 * 1024) return;
    int p = idx & 1023;
    int m = (idx >> 10) & 255;
    int b = idx >> 18;
    int h = p >> 5, w = p & 31;
    int co = m >> 2, t = m & 3, g = co >> 2;
    const float* Ib = I + (long)b * 256 * 1024;
    float acc = Ib[m * 1024 + p] + pb[m];
#pragma unroll
    for (int s = 0; s < 4; s++) {
        float sg = c_sgn[t * 4 + s];
        const float* wc = pw + ((long)c_cmp[t * 4 + s] * 64 + co) * 36;
#pragma unroll
        for (int cil = 0; cil < 4; cil++) {
            const float* in = Ib + ((g * 4 + cil) * 4 + s) * 1024;
            const float* wk = wc + cil * 9;
            float part = 0.f;
#pragma unroll
            for (int kh = 0; kh < 3; kh++) {
                int hh = h + kh - 1;
                if (hh < 0 || hh > 31) continue;
#pragma unroll
                for (int kw = 0; kw < 3; kw++) {
                    int ww = w + kw - 1;
                    if (ww < 0 || ww > 31) continue;
                    part += in[hh * 32 + ww] * wk[kh * 3 + kw];
                }
            }
            acc += sg * part;
        }
    }
    Out[idx] = acc;
}

// ---------------------------------------------------------------------------
extern "C" void kernel_launch(void* const* d_in, const int* in_sizes, int n_in,
                              void* d_out, int out_size) {
    const float* x      = (const float*)d_in[0];
    const float* cv1_w  = (const float*)d_in[1];
    const float* bn1_g  = (const float*)d_in[2];
    const float* bn1_b  = (const float*)d_in[3];
    const float* qkv_w  = (const float*)d_in[4];
    const float* qkv_b  = (const float*)d_in[5];
    const float* proj_w = (const float*)d_in[6];
    const float* proj_b = (const float*)d_in[7];
    const float* pe_w   = (const float*)d_in[8];
    const float* pe_b   = (const float*)d_in[9];
    const float* ang    = (const float*)d_in[10];
    const float* anb    = (const float*)d_in[11];
    const float* f1w    = (const float*)d_in[12];
    const float* f1g    = (const float*)d_in[13];
    const float* f1b    = (const float*)d_in[14];
    const float* f2w    = (const float*)d_in[15];
    const float* f2g    = (const float*)d_in[16];
    const float* f2b    = (const float*)d_in[17];
    const float* cv2_w  = (const float*)d_in[18];
    const float* bn2_g  = (const float*)d_in[19];
    const float* bn2_b  = (const float*)d_in[20];

    float *buf1, *buf2, *buf3, *buf4, *Wx, *scale, *shift;
    cudaGetSymbolAddress((void**)&buf1, g_buf1);
    cudaGetSymbolAddress((void**)&buf2, g_buf2);
    cudaGetSymbolAddress((void**)&buf3, g_buf3);
    cudaGetSymbolAddress((void**)&buf4, g_buf4);
    cudaGetSymbolAddress((void**)&Wx,   g_W);
    cudaGetSymbolAddress((void**)&scale, g_scale);
    cudaGetSymbolAddress((void**)&shift, g_shift);

    const long S512 = 512L * 1024, S768 = 768L * 1024, S256 = 256L * 1024;

    // Expand quaternion weights -> dense GEMM weights
    expand_w_kernel<<<256, 256>>>(cv1_w, Wx + OFF_W1, 128, 128);
    expand_w_kernel<<<192, 256>>>(qkv_w, Wx + OFF_WQ, 192, 64);
    expand_w_kernel<<<64,  256>>>(proj_w, Wx + OFF_WP, 64, 64);
    expand_w_kernel<<<128, 256>>>(f1w,   Wx + OFF_F1, 128, 64);
    expand_w_kernel<<<128, 256>>>(f2w,   Wx + OFF_F2, 64, 128);
    expand_w_kernel<<<256, 256>>>(cv2_w, Wx + OFF_C2, 128, 128);

    // Stage 1: cv1 + iqbn + relu
    sgemm_kernel<<<dim3(16, 8, 4), 256>>>(Wx + OFF_W1, x, buf1, nullptr, 512, 512, S512, S512);
    stats_kernel<<<512, 256>>>(buf1, S512, bn1_g, bn1_b, scale, shift);
    bn_apply_kernel<<<8192, 256>>>(buf1, buf1, scale, shift, 512, S512, S512, 1);

    // qkv (reads a = rows 0..255 of buf1)
    sgemm_kernel<<<dim3(16, 12, 4), 256>>>(Wx + OFF_WQ, buf1, buf2, qkv_b, 768, 256, S512, S768);

    // attention
    cudaFuncSetAttribute(attn_kernel, cudaFuncAttributeMaxDynamicSharedMemorySize,
                         ATTN_SMEM_FLOATS * 4);
    attn_kernel<<<dim3(32, 16, 4), 256, ATTN_SMEM_FLOATS * 4>>>(buf2, buf3);

    // pe conv + residual add
    pe_kernel<<<4096, 256>>>(buf3, pe_w, pe_b, buf4);

    // proj + attn_norm
    sgemm_kernel<<<dim3(16, 4, 4), 256>>>(Wx + OFF_WP, buf4, buf3, proj_b, 256, 256, S256, S256);
    stats_kernel<<<256, 256>>>(buf3, S256, ang, anb, scale, shift);
    bn_apply_kernel<<<4096, 256>>>(buf3, buf3, scale, shift, 256, S256, S256, 0);

    // ffn1 + bn + relu
    sgemm_kernel<<<dim3(16, 8, 4), 256>>>(Wx + OFF_F1, buf3, buf2, nullptr, 512, 256, S256, S512);
    stats_kernel<<<512, 256>>>(buf2, S512, f1g, f1b, scale, shift);
    bn_apply_kernel<<<8192, 256>>>(buf2, buf2, scale, shift, 512, S512, S512, 1);

    // ffn2 + bn (writes rows 0..255 of buf1; rows 256..511 still hold b)
    sgemm_kernel<<<dim3(16, 4, 4), 256>>>(Wx + OFF_F2, buf2, buf1, nullptr, 256, 512, S512, S512);
    stats_kernel<<<256, 256>>>(buf1, S512, f2g, f2b, scale, shift);
    bn_apply_kernel<<<4096, 256>>>(buf1, buf1, scale, shift, 256, S512, S512, 0);

    // cv2 on concat [a; b] + bn + relu -> d_out
    sgemm_kernel<<<dim3(16, 8, 4), 256>>>(Wx + OFF_C2, buf1, buf2, nullptr, 512, 512, S512, S512);
    stats_kernel<<<512, 256>>>(buf2, S512, bn2_g, bn2_b, scale, shift);
    bn_apply_kernel<<<8192, 256>>>(buf2, (float*)d_out, scale, shift, 512, S512, S512, 1);
}

// round 3
// speedup vs baseline: 1.0687x; 1.0687x over previous
#include <cuda_runtime.h>
#include <cuda_bf16.h>
#include <cstdint>

// ---------------------------------------------------------------------------
// Quaternion Hamilton-product tables
// ---------------------------------------------------------------------------
__constant__ int   c_cmp[16] = {0,1,2,3,  1,0,3,2,  2,3,0,1,  3,2,1,0};
__constant__ float c_sgn[16] = {1.f,-1.f,-1.f,-1.f,
                                1.f, 1.f, 1.f,-1.f,
                                1.f,-1.f, 1.f, 1.f,
                                1.f, 1.f,-1.f, 1.f};

// ---------------------------------------------------------------------------
// Scratch (device globals)
// ---------------------------------------------------------------------------
__device__ float g_buf1[4*512*1024];
__device__ float g_buf2[4*768*1024];
__device__ float g_buf3[4*256*1024];
__device__ float g_buf4[4*256*1024];
__device__ float g_W[1048576];
__device__ float g_scale[768];
__device__ float g_shift[768];

#define OFF_W1 0
#define OFF_WQ (OFF_W1 + 512*512)
#define OFF_WP (OFF_WQ + 768*256)
#define OFF_F1 (OFF_WP + 256*256)
#define OFF_F2 (OFF_F1 + 512*256)
#define OFF_C2 (OFF_F2 + 256*512)

// ---------------------------------------------------------------------------
// One fused expansion kernel for all six quaternion weights
// ---------------------------------------------------------------------------
__global__ void expand_all_kernel(const float* __restrict__ w0, const float* __restrict__ w1,
                                  const float* __restrict__ w2, const float* __restrict__ w3,
                                  const float* __restrict__ w4, const float* __restrict__ w5,
                                  float* __restrict__ W4base) {
    const int Couts[6] = {128,192,64,128,64,128};
    const int Cins [6] = {128, 64,64, 64,128,128};
    const int offs [6] = {OFF_W1,OFF_WQ,OFF_WP,OFF_F1,OFF_F2,OFF_C2};
    const float* srcs[6] = {w0,w1,w2,w3,w4,w5};
    int q = blockIdx.y;
    int Cout = Couts[q], Cin = Cins[q];
    const float* w = srcs[q];
    float* W4 = W4base + offs[q];
    int total = 16 * Cout * Cin;
    for (int i = blockIdx.x * blockDim.x + threadIdx.x; i < total;
         i += gridDim.x * blockDim.x) {
        int s = i & 3, t = (i >> 2) & 3;
        int rest = i >> 4;
        int ci = rest % Cin, co = rest / Cin;
        W4[(co*4 + t) * (4*Cin) + ci*4 + s] =
            c_sgn[t*4 + s] * w[c_cmp[t*4 + s] * Cout * Cin + co * Cin + ci];
    }
}

// ---------------------------------------------------------------------------
// HMMA bf16-split GEMM: Y[b](MxN) = W(MxK) * X[b](KxN) + bias, N = 1024.
// CTA 128x128 tile, 8 warps (4 m x 2 n), warp tile 32x64, K-chunk 32.
// fp32 = hi + lo (bf16); D = Ahi*Bhi + Alo*Bhi + Ahi*Blo, fp32 accum.
// Smem layout [row][k] pitch 40 halfwords -> every fragment reg is one
// aligned 32-bit LDS, conflict-free.
// ---------------------------------------------------------------------------
#define PITCH 40

__device__ __forceinline__ void split2(float x, float y, uint32_t& hi, uint32_t& lo) {
    __nv_bfloat16 hx = __float2bfloat16(x);
    __nv_bfloat16 hy = __float2bfloat16(y);
    float rx = x - __bfloat162float(hx);
    float ry = y - __bfloat162float(hy);
    __nv_bfloat16 lx = __float2bfloat16(rx);
    __nv_bfloat16 ly = __float2bfloat16(ry);
    hi = (uint32_t)*(unsigned short*)&hx | ((uint32_t)*(unsigned short*)&hy << 16);
    lo = (uint32_t)*(unsigned short*)&lx | ((uint32_t)*(unsigned short*)&ly << 16);
}

__device__ __forceinline__ void mma16816(float* d, uint32_t a0, uint32_t a1,
                                         uint32_t a2, uint32_t a3,
                                         uint32_t b0, uint32_t b1) {
    asm volatile(
        "mma.sync.aligned.m16n8k16.row.col.f32.bf16.bf16.f32 "
        "{%0,%1,%2,%3}, {%4,%5,%6,%7}, {%8,%9}, {%0,%1,%2,%3};"
        : "+f"(d[0]), "+f"(d[1]), "+f"(d[2]), "+f"(d[3])
        : "r"(a0), "r"(a1), "r"(a2), "r"(a3), "r"(b0), "r"(b1));
}

__global__ __launch_bounds__(256, 2) void mma_gemm_kernel(
    const float* __restrict__ W, const float* __restrict__ X, float* __restrict__ Y,
    const float* __restrict__ bias, int M, int K, long sX, long sY)
{
    __shared__ __nv_bfloat16 sm[4 * 128 * PITCH];
    __nv_bfloat16* AsH = sm;
    __nv_bfloat16* AsL = sm + 128 * PITCH;
    __nv_bfloat16* BsH = sm + 2 * 128 * PITCH;
    __nv_bfloat16* BsL = sm + 3 * 128 * PITCH;

    const int tid = threadIdx.x;
    const int wid = tid >> 5, lane = tid & 31;
    const int wm = wid & 3, wn = wid >> 2;        // 4 m-warps x 2 n-warps
    const int g = lane >> 2, tg = lane & 3;
    const int mo = blockIdx.y * 128, no = blockIdx.x * 128;
    const float* Xb = X + blockIdx.z * sX;
    float* Yb = Y + blockIdx.z * sY;

    // loader coords
    const int am = tid >> 1, ak = (tid & 1) * 16;   // A: one row, 16 k's

    float acc[2][8][4] = {};

    const int nch = K >> 5;
    for (int ch = 0; ch < nch; ch++) {
        int kt = ch * 32;

        // ---- stage gmem -> regs ----
        float4 ar4[4];
        {
            const float* Ap = W + (long)(mo + am) * K + kt + ak;
#pragma unroll
            for (int j = 0; j < 4; j++) ar4[j] = *(const float4*)(Ap + j * 4);
        }
        float4 br4[2][2];   // [unit][k of pair]
#pragma unroll
        for (int it = 0; it < 2; it++) {
            int u = tid + it * 256;
            int kk = (u & 15) * 2, nn = (u >> 4) * 4;
            br4[it][0] = *(const float4*)(Xb + (long)(kt + kk) * 1024 + no + nn);
            br4[it][1] = *(const float4*)(Xb + (long)(kt + kk + 1) * 1024 + no + nn);
        }

        __syncthreads();   // previous chunk's compute done

        // ---- A rows: pack 16 k's -> 8 b32 hi + 8 lo ----
        {
            uint32_t h[8], l[8];
            const float* f = (const float*)ar4;
#pragma unroll
            for (int p = 0; p < 8; p++) split2(f[2*p], f[2*p+1], h[p], l[p]);
            uint32_t* dH = (uint32_t*)(AsH + am * PITCH + ak);
            uint32_t* dL = (uint32_t*)(AsL + am * PITCH + ak);
            *(uint4*)dH     = make_uint4(h[0], h[1], h[2], h[3]);
            *(uint4*)(dH+4) = make_uint4(h[4], h[5], h[6], h[7]);
            *(uint4*)dL     = make_uint4(l[0], l[1], l[2], l[3]);
            *(uint4*)(dL+4) = make_uint4(l[4], l[5], l[6], l[7]);
        }
        // ---- B: transpose (2k x 4n) blocks into [n][k] ----
#pragma unroll
        for (int it = 0; it < 2; it++) {
            int u = tid + it * 256;
            int kk = (u & 15) * 2, nn = (u >> 4) * 4;
            const float* f0 = (const float*)&br4[it][0];
            const float* f1 = (const float*)&br4[it][1];
#pragma unroll
            for (int j = 0; j < 4; j++) {
                uint32_t h, l;
                split2(f0[j], f1[j], h, l);
                *(uint32_t*)(BsH + (nn + j) * PITCH + kk) = h;
                *(uint32_t*)(BsL + (nn + j) * PITCH + kk) = l;
            }
        }
        __syncthreads();

        // ---- compute: 2 k16 steps ----
#pragma unroll
        for (int k0 = 0; k0 < 32; k0 += 16) {
            uint32_t ah[2][4], al[2][4];
#pragma unroll
            for (int mt = 0; mt < 2; mt++) {
                int r = wm * 32 + mt * 16;
                const __nv_bfloat16* pH = AsH + k0 + 2 * tg;
                const __nv_bfloat16* pL = AsL + k0 + 2 * tg;
                ah[mt][0] = *(const uint32_t*)(pH + (r + g) * PITCH);
                ah[mt][1] = *(const uint32_t*)(pH + (r + g + 8) * PITCH);
                ah[mt][2] = *(const uint32_t*)(pH + (r + g) * PITCH + 8);
                ah[mt][3] = *(const uint32_t*)(pH + (r + g + 8) * PITCH + 8);
                al[mt][0] = *(const uint32_t*)(pL + (r + g) * PITCH);
                al[mt][1] = *(const uint32_t*)(pL + (r + g + 8) * PITCH);
                al[mt][2] = *(const uint32_t*)(pL + (r + g) * PITCH + 8);
                al[mt][3] = *(const uint32_t*)(pL + (r + g + 8) * PITCH + 8);
            }
#pragma unroll
            for (int nt = 0; nt < 8; nt++) {
                int nb = wn * 64 + nt * 8 + g;
                uint32_t bh0 = *(const uint32_t*)(BsH + nb * PITCH + k0 + 2 * tg);
                uint32_t bh1 = *(const uint32_t*)(BsH + nb * PITCH + k0 + 2 * tg + 8);
                uint32_t bl0 = *(const uint32_t*)(BsL + nb * PITCH + k0 + 2 * tg);
                uint32_t bl1 = *(const uint32_t*)(BsL + nb * PITCH + k0 + 2 * tg + 8);
#pragma unroll
                for (int mt = 0; mt < 2; mt++) {
                    mma16816(acc[mt][nt], ah[mt][0], ah[mt][1], ah[mt][2], ah[mt][3], bh0, bh1);
                    mma16816(acc[mt][nt], al[mt][0], al[mt][1], al[mt][2], al[mt][3], bh0, bh1);
                    mma16816(acc[mt][nt], ah[mt][0], ah[mt][1], ah[mt][2], ah[mt][3], bl0, bl1);
                }
            }
        }
    }

    // ---- epilogue: direct float2 stores + bias ----
#pragma unroll
    for (int mt = 0; mt < 2; mt++) {
        int r0 = mo + wm * 32 + mt * 16 + g;
        int r1 = r0 + 8;
        float bv0 = bias ? bias[r0] : 0.f;
        float bv1 = bias ? bias[r1] : 0.f;
#pragma unroll
        for (int nt = 0; nt < 8; nt++) {
            int c = no + wn * 64 + nt * 8 + 2 * tg;
            float* d = acc[mt][nt];
            *(float2*)(Yb + (long)r0 * 1024 + c) = make_float2(d[0] + bv0, d[1] + bv0);
            *(float2*)(Yb + (long)r1 * 1024 + c) = make_float2(d[2] + bv1, d[3] + bv1);
        }
    }
}

// ---------------------------------------------------------------------------
// Batchnorm stats + apply (unchanged)
// ---------------------------------------------------------------------------
__global__ void stats_kernel(const float* __restrict__ X, long bstride,
                             const float* __restrict__ g, const float* __restrict__ be,
                             float* __restrict__ scale, float* __restrict__ shift) {
    int m = blockIdx.x;
    int tid = threadIdx.x;
    float s = 0.f, sq = 0.f;
    for (int b = 0; b < 4; b++) {
        const float* p = X + b * bstride + (long)m * 1024;
        for (int i = tid; i < 1024; i += 256) {
            float v = p[i];
            s += v; sq += v * v;
        }
    }
    __shared__ float rs[256], rq[256];
    rs[tid] = s; rq[tid] = sq;
    __syncthreads();
    for (int o = 128; o > 0; o >>= 1) {
        if (tid < o) { rs[tid] += rs[tid + o]; rq[tid] += rq[tid + o]; }
        __syncthreads();
    }
    if (tid == 0) {
        float mean = rs[0] * (1.f / 4096.f);
        float var  = rq[0] * (1.f / 4096.f) - mean * mean;
        float rstd = rsqrtf(var + 1e-5f);
        float sc = g[m] * rstd;
        scale[m] = sc;
        shift[m] = be[m] - mean * sc;
    }
}

__global__ void bn_apply_kernel(const float* __restrict__ X, float* __restrict__ Y,
                                const float* __restrict__ scale,
                                const float* __restrict__ shift,
                                int M, long bsX, long bsY, int relu) {
    long per = (long)M * 1024;
    long total = 4 * per;
    for (long i = blockIdx.x * (long)blockDim.x + threadIdx.x; i < total;
         i += (long)gridDim.x * blockDim.x) {
        long b = i / per;
        long r = i - b * per;
        int m = (int)(r >> 10);
        float v = X[b * bsX + r] * scale[m] + shift[m];
        if (relu) v = fmaxf(v, 0.f);
        Y[b * bsY + r] = v;
    }
}

// ---------------------------------------------------------------------------
// Attention (unchanged from R1 — known good)
// ---------------------------------------------------------------------------
#define SPITCH 1028
#define ATTN_SMEM_FLOATS (32*SPITCH + 16*128 + 32*16 + 32)

__global__ void attn_kernel(const float* __restrict__ Yq, float* __restrict__ O) {
    extern __shared__ float smf[];
    float* S    = smf;
    float* kv   = S + 32 * SPITCH;
    float* qs   = kv + 16 * 128;
    float* rinv = qs + 32 * 16;

    int b = blockIdx.z;
    int head = blockIdx.y >> 2, t = blockIdx.y & 3;
    int r0 = blockIdx.x * 32;
    const float* Yb = Yq + (long)b * 768 * 1024;
    int tid = threadIdx.x;

    for (int i = tid; i < 512; i += 256) {
        int dd = i >> 5, n = i & 31;
        qs[n * 16 + dd] = Yb[(head * 192 + dd * 4 + t) * 1024 + r0 + n];
    }

    int ty = tid >> 4, tx = tid & 15;
    const float sc = 0.25f;

    for (int ch = 0; ch < 8; ch++) {
        __syncthreads();
        for (int i = tid; i < 2048; i += 256) {
            int dd = i >> 7, mm = i & 127;
            kv[i] = Yb[(head * 192 + 64 + dd * 4 + t) * 1024 + ch * 128 + mm];
        }
        __syncthreads();
        float a0[8] = {}, a1[8] = {};
#pragma unroll
        for (int dd = 0; dd < 16; dd++) {
            float q0 = qs[ty * 16 + dd];
            float q1 = qs[(ty + 16) * 16 + dd];
            float4 kA = *(float4*)&kv[dd * 128 + tx * 8];
            float4 kB = *(float4*)&kv[dd * 128 + tx * 8 + 4];
            float kk[8] = {kA.x, kA.y, kA.z, kA.w, kB.x, kB.y, kB.z, kB.w};
#pragma unroll
            for (int j = 0; j < 8; j++) { a0[j] += q0 * kk[j]; a1[j] += q1 * kk[j]; }
        }
        int base0 = ty * SPITCH + ch * 128 + tx * 8;
        int base1 = (ty + 16) * SPITCH + ch * 128 + tx * 8;
        *(float4*)&S[base0]     = make_float4(a0[0]*sc, a0[1]*sc, a0[2]*sc, a0[3]*sc);
        *(float4*)&S[base0 + 4] = make_float4(a0[4]*sc, a0[5]*sc, a0[6]*sc, a0[7]*sc);
        *(float4*)&S[base1]     = make_float4(a1[0]*sc, a1[1]*sc, a1[2]*sc, a1[3]*sc);
        *(float4*)&S[base1 + 4] = make_float4(a1[4]*sc, a1[5]*sc, a1[6]*sc, a1[7]*sc);
    }
    __syncthreads();

    int lane = tid & 31, warp = tid >> 5;
    for (int rr = warp; rr < 32; rr += 8) {
        float* Sr = S + rr * SPITCH;
        float mx = -1e30f;
        for (int m = lane; m < 1024; m += 32) mx = fmaxf(mx, Sr[m]);
#pragma unroll
        for (int o = 16; o; o >>= 1) mx = fmaxf(mx, __shfl_xor_sync(0xffffffffu, mx, o));
        float sum = 0.f;
        for (int m = lane; m < 1024; m += 32) {
            float e = __expf(Sr[m] - mx);
            Sr[m] = e; sum += e;
        }
#pragma unroll
        for (int o = 16; o; o >>= 1) sum += __shfl_xor_sync(0xffffffffu, sum, o);
        if (lane == 0) rinv[rr] = 1.f / sum;
    }
    __syncthreads();

    int r = tid & 31, dd = tid >> 5;
    float o0 = 0.f, o1 = 0.f;
    for (int ch = 0; ch < 8; ch++) {
        __syncthreads();
        for (int i = tid; i < 2048; i += 256) {
            int d2 = i >> 7, mm = i & 127;
            kv[i] = Yb[(head * 192 + 128 + d2 * 4 + t) * 1024 + ch * 128 + mm];
        }
        __syncthreads();
        float* Sr = S + r * SPITCH + ch * 128;
#pragma unroll
        for (int m4 = 0; m4 < 128; m4 += 4) {
            float4 p  = *(float4*)&Sr[m4];
            float4 v0 = *(float4*)&kv[dd * 128 + m4];
            float4 v1 = *(float4*)&kv[(dd + 8) * 128 + m4];
            o0 += p.x*v0.x + p.y*v0.y + p.z*v0.z + p.w*v0.w;
            o1 += p.x*v1.x + p.y*v1.y + p.z*v1.z + p.w*v1.w;
        }
    }
    float* Ob = O + (long)b * 256 * 1024;
    float inv = rinv[r];
    Ob[(head * 64 + dd * 4 + t) * 1024 + r0 + r]       = o0 * inv;
    Ob[(head * 64 + (dd + 8) * 4 + t) * 1024 + r0 + r] = o1 * inv;
}

// ---------------------------------------------------------------------------
// PE conv (grouped quaternion 3x3, pad 1) + residual (unchanged)
// ---------------------------------------------------------------------------
__global__ void pe_kernel(const float* __restrict__ I, const float* __restrict__ pw,
                          const float* __restrict__ pb, float* __restrict__ Out) {
    int idx = blockIdx.x * 256 + threadIdx.x;
    if (idx >= 4 * 256 * 1024) return;
    int p = idx & 1023;
    int m = (idx >> 10) & 255;
    int b = idx >> 18;
    int h = p >> 5, w = p & 31;
    int co = m >> 2, t = m & 3, g = co >> 2;
    const float* Ib = I + (long)b * 256 * 1024;
    float acc = Ib[m * 1024 + p] + pb[m];
#pragma unroll
    for (int s = 0; s < 4; s++) {
        float sg = c_sgn[t * 4 + s];
        const float* wc = pw + ((long)c_cmp[t * 4 + s] * 64 + co) * 36;
#pragma unroll
        for (int cil = 0; cil < 4; cil++) {
            const float* in = Ib + ((g * 4 + cil) * 4 + s) * 1024;
            const float* wk = wc + cil * 9;
            float part = 0.f;
#pragma unroll
            for (int kh = 0; kh < 3; kh++) {
                int hh = h + kh - 1;
                if (hh < 0 || hh > 31) continue;
#pragma unroll
                for (int kw = 0; kw < 3; kw++) {
                    int ww = w + kw - 1;
                    if (ww < 0 || ww > 31) continue;
                    part += in[hh * 32 + ww] * wk[kh * 3 + kw];
                }
            }
            acc += sg * part;
        }
    }
    Out[idx] = acc;
}

// ---------------------------------------------------------------------------
extern "C" void kernel_launch(void* const* d_in, const int* in_sizes, int n_in,
                              void* d_out, int out_size) {
    const float* x      = (const float*)d_in[0];
    const float* cv1_w  = (const float*)d_in[1];
    const float* bn1_g  = (const float*)d_in[2];
    const float* bn1_b  = (const float*)d_in[3];
    const float* qkv_w  = (const float*)d_in[4];
    const float* qkv_b  = (const float*)d_in[5];
    const float* proj_w = (const float*)d_in[6];
    const float* proj_b = (const float*)d_in[7];
    const float* pe_w   = (const float*)d_in[8];
    const float* pe_b   = (const float*)d_in[9];
    const float* ang    = (const float*)d_in[10];
    const float* anb    = (const float*)d_in[11];
    const float* f1w    = (const float*)d_in[12];
    const float* f1g    = (const float*)d_in[13];
    const float* f1b    = (const float*)d_in[14];
    const float* f2w    = (const float*)d_in[15];
    const float* f2g    = (const float*)d_in[16];
    const float* f2b    = (const float*)d_in[17];
    const float* cv2_w  = (const float*)d_in[18];
    const float* bn2_g  = (const float*)d_in[19];
    const float* bn2_b  = (const float*)d_in[20];

    float *buf1, *buf2, *buf3, *buf4, *Wx, *scale, *shift;
    cudaGetSymbolAddress((void**)&buf1, g_buf1);
    cudaGetSymbolAddress((void**)&buf2, g_buf2);
    cudaGetSymbolAddress((void**)&buf3, g_buf3);
    cudaGetSymbolAddress((void**)&buf4, g_buf4);
    cudaGetSymbolAddress((void**)&Wx,   g_W);
    cudaGetSymbolAddress((void**)&scale, g_scale);
    cudaGetSymbolAddress((void**)&shift, g_shift);

    const long S512 = 512L * 1024, S768 = 768L * 1024, S256 = 256L * 1024;

    cudaFuncSetAttribute(attn_kernel, cudaFuncAttributeMaxDynamicSharedMemorySize,
                         ATTN_SMEM_FLOATS * 4);

    // Expand all quaternion weights in one launch
    expand_all_kernel<<<dim3(32, 6), 256>>>(cv1_w, qkv_w, proj_w, f1w, f2w, cv2_w, Wx);

    // Stage 1: cv1 + iqbn + relu
    mma_gemm_kernel<<<dim3(8, 4, 4), 256>>>(Wx + OFF_W1, x, buf1, nullptr, 512, 512, S512, S512);
    stats_kernel<<<512, 256>>>(buf1, S512, bn1_g, bn1_b, scale, shift);
    bn_apply_kernel<<<8192, 256>>>(buf1, buf1, scale, shift, 512, S512, S512, 1);

    // qkv
    mma_gemm_kernel<<<dim3(8, 6, 4), 256>>>(Wx + OFF_WQ, buf1, buf2, qkv_b, 768, 256, S512, S768);

    // attention
    attn_kernel<<<dim3(32, 16, 4), 256, ATTN_SMEM_FLOATS * 4>>>(buf2, buf3);

    // pe conv + residual
    pe_kernel<<<4096, 256>>>(buf3, pe_w, pe_b, buf4);

    // proj + attn_norm
    mma_gemm_kernel<<<dim3(8, 2, 4), 256>>>(Wx + OFF_WP, buf4, buf3, proj_b, 256, 256, S256, S256);
    stats_kernel<<<256, 256>>>(buf3, S256, ang, anb, scale, shift);
    bn_apply_kernel<<<4096, 256>>>(buf3, buf3, scale, shift, 256, S256, S256, 0);

    // ffn1 + bn + relu
    mma_gemm_kernel<<<dim3(8, 4, 4), 256>>>(Wx + OFF_F1, buf3, buf2, nullptr, 512, 256, S256, S512);
    stats_kernel<<<512, 256>>>(buf2, S512, f1g, f1b, scale, shift);
    bn_apply_kernel<<<8192, 256>>>(buf2, buf2, scale, shift, 512, S512, S512, 1);

    // ffn2 + bn
    mma_gemm_kernel<<<dim3(8, 2, 4), 256>>>(Wx + OFF_F2, buf2, buf1, nullptr, 256, 512, S512, S512);
    stats_kernel<<<256, 256>>>(buf1, S512, f2g, f2b, scale, shift);
    bn_apply_kernel<<<4096, 256>>>(buf1, buf1, scale, shift, 256, S512, S512, 0);

    // cv2 on concat [a; b] + bn + relu -> d_out
    mma_gemm_kernel<<<dim3(8, 4, 4), 256>>>(Wx + OFF_C2, buf1, buf2, nullptr, 512, 512, S512, S512);
    stats_kernel<<<512, 256>>>(buf2, S512, bn2_g, bn2_b, scale, shift);
    bn_apply_kernel<<<8192, 256>>>(buf2, (float*)d_out, scale, shift, 512, S512, S512, 1);
}

// round 4
// speedup vs baseline: 1.4507x; 1.3574x over previous
#include <cuda_runtime.h>
#include <cuda_bf16.h>
#include <cstdint>

// ---------------------------------------------------------------------------
// Quaternion Hamilton-product tables
// ---------------------------------------------------------------------------
__constant__ int   c_cmp[16] = {0,1,2,3,  1,0,3,2,  2,3,0,1,  3,2,1,0};
__constant__ float c_sgn[16] = {1.f,-1.f,-1.f,-1.f,
                                1.f, 1.f, 1.f,-1.f,
                                1.f,-1.f, 1.f, 1.f,
                                1.f, 1.f,-1.f, 1.f};

// ---------------------------------------------------------------------------
// Scratch (device globals)
// ---------------------------------------------------------------------------
__device__ float g_buf1[4*512*1024];
__device__ float g_buf2[4*768*1024];
__device__ float g_buf3[4*256*1024];
__device__ float g_buf4[4*256*1024];
__device__ float g_W[1048576];
__device__ float g_scale[768];
__device__ float g_shift[768];

#define OFF_W1 0
#define OFF_WQ (OFF_W1 + 512*512)
#define OFF_WP (OFF_WQ + 768*256)
#define OFF_F1 (OFF_WP + 256*256)
#define OFF_F2 (OFF_F1 + 512*256)
#define OFF_C2 (OFF_F2 + 256*512)

// ---------------------------------------------------------------------------
// One fused expansion kernel for all six quaternion weights
// ---------------------------------------------------------------------------
__global__ void expand_all_kernel(const float* __restrict__ w0, const float* __restrict__ w1,
                                  const float* __restrict__ w2, const float* __restrict__ w3,
                                  const float* __restrict__ w4, const float* __restrict__ w5,
                                  float* __restrict__ W4base) {
    const int Couts[6] = {128,192,64,128,64,128};
    const int Cins [6] = {128, 64,64, 64,128,128};
    const int offs [6] = {OFF_W1,OFF_WQ,OFF_WP,OFF_F1,OFF_F2,OFF_C2};
    const float* srcs[6] = {w0,w1,w2,w3,w4,w5};
    int q = blockIdx.y;
    int Cout = Couts[q], Cin = Cins[q];
    const float* w = srcs[q];
    float* W4 = W4base + offs[q];
    int total = 16 * Cout * Cin;
    for (int i = blockIdx.x * blockDim.x + threadIdx.x; i < total;
         i += gridDim.x * blockDim.x) {
        int s = i & 3, t = (i >> 2) & 3;
        int rest = i >> 4;
        int ci = rest % Cin, co = rest / Cin;
        W4[(co*4 + t) * (4*Cin) + ci*4 + s] =
            c_sgn[t*4 + s] * w[c_cmp[t*4 + s] * Cout * Cin + co * Cin + ci];
    }
}

// ---------------------------------------------------------------------------
// HMMA bf16-split GEMM, 64x64 CTA tile, 4 warps (2m x 2n), warp tile 32x32,
// K-chunk 32, register prefetch of next chunk. N = 1024 fixed.
// ---------------------------------------------------------------------------
#define PITCH 40

__device__ __forceinline__ void split2(float x, float y, uint32_t& hi, uint32_t& lo) {
    __nv_bfloat16 hx = __float2bfloat16(x);
    __nv_bfloat16 hy = __float2bfloat16(y);
    float rx = x - __bfloat162float(hx);
    float ry = y - __bfloat162float(hy);
    __nv_bfloat16 lx = __float2bfloat16(rx);
    __nv_bfloat16 ly = __float2bfloat16(ry);
    hi = (uint32_t)*(unsigned short*)&hx | ((uint32_t)*(unsigned short*)&hy << 16);
    lo = (uint32_t)*(unsigned short*)&lx | ((uint32_t)*(unsigned short*)&ly << 16);
}

__device__ __forceinline__ void mma16816(float* d, uint32_t a0, uint32_t a1,
                                         uint32_t a2, uint32_t a3,
                                         uint32_t b0, uint32_t b1) {
    asm volatile(
        "mma.sync.aligned.m16n8k16.row.col.f32.bf16.bf16.f32 "
        "{%0,%1,%2,%3}, {%4,%5,%6,%7}, {%8,%9}, {%0,%1,%2,%3};"
        : "+f"(d[0]), "+f"(d[1]), "+f"(d[2]), "+f"(d[3])
        : "r"(a0), "r"(a1), "r"(a2), "r"(a3), "r"(b0), "r"(b1));
}

__global__ __launch_bounds__(128) void mma_gemm_kernel(
    const float* __restrict__ W, const float* __restrict__ X, float* __restrict__ Y,
    const float* __restrict__ bias, int M, int K, long sX, long sY)
{
    __shared__ __nv_bfloat16 sm[4 * 64 * PITCH];
    __nv_bfloat16* AsH = sm;
    __nv_bfloat16* AsL = sm + 64 * PITCH;
    __nv_bfloat16* BsH = sm + 2 * 64 * PITCH;
    __nv_bfloat16* BsL = sm + 3 * 64 * PITCH;

    const int tid = threadIdx.x;
    const int wid = tid >> 5, lane = tid & 31;
    const int wm = wid & 1, wn = wid >> 1;
    const int g = lane >> 2, tg = lane & 3;
    const int mo = blockIdx.y * 64, no = blockIdx.x * 64;
    const float* Xb = X + blockIdx.z * sX;
    float* Yb = Y + blockIdx.z * sY;

    const int am = tid >> 1, ak = (tid & 1) * 16;
    float acc[2][4][4] = {};
    const int nch = K >> 5;

    float4 ar4[4];
    float4 br4[2][2];

    // prefetch chunk 0
    {
        const float* Ap = W + (long)(mo + am) * K + ak;
#pragma unroll
        for (int j = 0; j < 4; j++) ar4[j] = *(const float4*)(Ap + j * 4);
#pragma unroll
        for (int it = 0; it < 2; it++) {
            int u = tid + it * 128;
            int kk = (u & 15) * 2, nn = (u >> 4) * 4;
            br4[it][0] = *(const float4*)(Xb + (long)kk * 1024 + no + nn);
            br4[it][1] = *(const float4*)(Xb + (long)(kk + 1) * 1024 + no + nn);
        }
    }

    for (int ch = 0; ch < nch; ch++) {
        __syncthreads();   // previous chunk's compute done (smem free)

        // ---- convert + store A ----
        {
            uint32_t h[8], l[8];
            const float* f = (const float*)ar4;
#pragma unroll
            for (int p = 0; p < 8; p++) split2(f[2*p], f[2*p+1], h[p], l[p]);
            uint32_t* dH = (uint32_t*)(AsH + am * PITCH + ak);
            uint32_t* dL = (uint32_t*)(AsL + am * PITCH + ak);
            *(uint4*)dH     = make_uint4(h[0], h[1], h[2], h[3]);
            *(uint4*)(dH+4) = make_uint4(h[4], h[5], h[6], h[7]);
            *(uint4*)dL     = make_uint4(l[0], l[1], l[2], l[3]);
            *(uint4*)(dL+4) = make_uint4(l[4], l[5], l[6], l[7]);
        }
        // ---- convert + store B (transpose 2k x 4n) ----
#pragma unroll
        for (int it = 0; it < 2; it++) {
            int u = tid + it * 128;
            int kk = (u & 15) * 2, nn = (u >> 4) * 4;
            const float* f0 = (const float*)&br4[it][0];
            const float* f1 = (const float*)&br4[it][1];
#pragma unroll
            for (int j = 0; j < 4; j++) {
                uint32_t h, l;
                split2(f0[j], f1[j], h, l);
                *(uint32_t*)(BsH + (nn + j) * PITCH + kk) = h;
                *(uint32_t*)(BsL + (nn + j) * PITCH + kk) = l;
            }
        }
        __syncthreads();

        // ---- prefetch next chunk (overlaps with compute below) ----
        if (ch + 1 < nch) {
            int kt = (ch + 1) * 32;
            const float* Ap = W + (long)(mo + am) * K + kt + ak;
#pragma unroll
            for (int j = 0; j < 4; j++) ar4[j] = *(const float4*)(Ap + j * 4);
#pragma unroll
            for (int it = 0; it < 2; it++) {
                int u = tid + it * 128;
                int kk = (u & 15) * 2, nn = (u >> 4) * 4;
                br4[it][0] = *(const float4*)(Xb + (long)(kt + kk) * 1024 + no + nn);
                br4[it][1] = *(const float4*)(Xb + (long)(kt + kk + 1) * 1024 + no + nn);
            }
        }

        // ---- compute ----
#pragma unroll
        for (int k0 = 0; k0 < 32; k0 += 16) {
            uint32_t ah[2][4], al[2][4];
#pragma unroll
            for (int mt = 0; mt < 2; mt++) {
                int r = wm * 32 + mt * 16;
                const __nv_bfloat16* pH = AsH + k0 + 2 * tg;
                const __nv_bfloat16* pL = AsL + k0 + 2 * tg;
                ah[mt][0] = *(const uint32_t*)(pH + (r + g) * PITCH);
                ah[mt][1] = *(const uint32_t*)(pH + (r + g + 8) * PITCH);
                ah[mt][2] = *(const uint32_t*)(pH + (r + g) * PITCH + 8);
                ah[mt][3] = *(const uint32_t*)(pH + (r + g + 8) * PITCH + 8);
                al[mt][0] = *(const uint32_t*)(pL + (r + g) * PITCH);
                al[mt][1] = *(const uint32_t*)(pL + (r + g + 8) * PITCH);
                al[mt][2] = *(const uint32_t*)(pL + (r + g) * PITCH + 8);
                al[mt][3] = *(const uint32_t*)(pL + (r + g + 8) * PITCH + 8);
            }
#pragma unroll
            for (int nt = 0; nt < 4; nt++) {
                int nb = wn * 32 + nt * 8 + g;
                uint32_t bh0 = *(const uint32_t*)(BsH + nb * PITCH + k0 + 2 * tg);
                uint32_t bh1 = *(const uint32_t*)(BsH + nb * PITCH + k0 + 2 * tg + 8);
                uint32_t bl0 = *(const uint32_t*)(BsL + nb * PITCH + k0 + 2 * tg);
                uint32_t bl1 = *(const uint32_t*)(BsL + nb * PITCH + k0 + 2 * tg + 8);
#pragma unroll
                for (int mt = 0; mt < 2; mt++) {
                    mma16816(acc[mt][nt], ah[mt][0], ah[mt][1], ah[mt][2], ah[mt][3], bh0, bh1);
                    mma16816(acc[mt][nt], al[mt][0], al[mt][1], al[mt][2], al[mt][3], bh0, bh1);
                    mma16816(acc[mt][nt], ah[mt][0], ah[mt][1], ah[mt][2], ah[mt][3], bl0, bl1);
                }
            }
        }
    }

    // ---- epilogue ----
#pragma unroll
    for (int mt = 0; mt < 2; mt++) {
        int r0 = mo + wm * 32 + mt * 16 + g;
        int r1 = r0 + 8;
        float bv0 = bias ? bias[r0] : 0.f;
        float bv1 = bias ? bias[r1] : 0.f;
#pragma unroll
        for (int nt = 0; nt < 4; nt++) {
            int c = no + wn * 32 + nt * 8 + 2 * tg;
            float* d = acc[mt][nt];
            *(float2*)(Yb + (long)r0 * 1024 + c) = make_float2(d[0] + bv0, d[1] + bv0);
            *(float2*)(Yb + (long)r1 * 1024 + c) = make_float2(d[2] + bv1, d[3] + bv1);
        }
    }
}

// ---------------------------------------------------------------------------
// Batchnorm stats: one CTA per row, float4, warp+smem reduce.
// ---------------------------------------------------------------------------
__global__ __launch_bounds__(256) void stats_kernel(
    const float* __restrict__ X, long bstride,
    const float* __restrict__ g, const float* __restrict__ be,
    float* __restrict__ scale, float* __restrict__ shift)
{
    int m = blockIdx.x, tid = threadIdx.x;
    float s = 0.f, sq = 0.f;
#pragma unroll
    for (int b = 0; b < 4; b++) {
        float4 v = *(const float4*)(X + b * bstride + (long)m * 1024 + tid * 4);
        s  += v.x + v.y + v.z + v.w;
        sq += v.x*v.x + v.y*v.y + v.z*v.z + v.w*v.w;
    }
#pragma unroll
    for (int o = 16; o; o >>= 1) {
        s  += __shfl_xor_sync(0xffffffffu, s, o);
        sq += __shfl_xor_sync(0xffffffffu, sq, o);
    }
    __shared__ float ps[8], pq[8];
    if ((tid & 31) == 0) { ps[tid >> 5] = s; pq[tid >> 5] = sq; }
    __syncthreads();
    if (tid == 0) {
        s = 0.f; sq = 0.f;
#pragma unroll
        for (int i = 0; i < 8; i++) { s += ps[i]; sq += pq[i]; }
        float mean = s * (1.f / 4096.f);
        float var  = sq * (1.f / 4096.f) - mean * mean;
        float rstd = rsqrtf(var + 1e-5f);
        float sc = g[m] * rstd;
        scale[m] = sc;
        shift[m] = be[m] - mean * sc;
    }
}

// ---------------------------------------------------------------------------
// BN apply: grid (M, 4), one float4 per thread (one row per block).
// ---------------------------------------------------------------------------
__global__ __launch_bounds__(256) void bn_apply_kernel(
    const float* __restrict__ X, float* __restrict__ Y,
    const float* __restrict__ scale, const float* __restrict__ shift,
    long bsX, long bsY, int relu)
{
    int m = blockIdx.x, b = blockIdx.y, tid = threadIdx.x;
    float sc = scale[m], sh = shift[m];
    float4 v = *(const float4*)(X + (long)b * bsX + (long)m * 1024 + tid * 4);
    v.x = v.x * sc + sh; v.y = v.y * sc + sh;
    v.z = v.z * sc + sh; v.w = v.w * sc + sh;
    if (relu) {
        v.x = fmaxf(v.x, 0.f); v.y = fmaxf(v.y, 0.f);
        v.z = fmaxf(v.z, 0.f); v.w = fmaxf(v.w, 0.f);
    }
    *(float4*)(Y + (long)b * bsY + (long)m * 1024 + tid * 4) = v;
}

// ---------------------------------------------------------------------------
// Flash attention: online softmax over 128-col chunks. 27KB static smem,
// 8 CTAs/SM. grid (32 row-tiles, head*4+t, batch), 256 threads.
// ---------------------------------------------------------------------------
__global__ __launch_bounds__(256) void attn_kernel(const float* __restrict__ Yq,
                                                   float* __restrict__ O) {
    __shared__ float qs[32 * 16];
    __shared__ float kv[16 * 128];
    __shared__ float Sc[32 * 132];
    __shared__ float fac_s[32], rsum_s[32];

    int b = blockIdx.z;
    int head = blockIdx.y >> 2, t = blockIdx.y & 3;
    int r0 = blockIdx.x * 32;
    const float* Yb = Yq + (long)b * 768 * 1024;
    int tid = threadIdx.x;
    int lane = tid & 31, warp = tid >> 5;
    int ty = tid >> 4, tx = tid & 15;
    int pr = tid & 31, pd = tid >> 5;

    // load Q (32 queries x 16 d)
    for (int i = tid; i < 512; i += 256) {
        int dd = i >> 5, n = i & 31;
        qs[n * 16 + dd] = Yb[(head * 192 + dd * 4 + t) * 1024 + r0 + n];
    }

    float o0 = 0.f, o1 = 0.f;
    float rm[4] = {-1e30f, -1e30f, -1e30f, -1e30f};
    float rs[4] = {0.f, 0.f, 0.f, 0.f};
    const float sc = 0.25f;

    for (int ch = 0; ch < 8; ch++) {
        __syncthreads();     // prev PV done; Q ready on first iter
        // load K chunk (16 d x 128 m)
        for (int i = tid; i < 2048; i += 256) {
            int dd = i >> 7, mm = i & 127;
            kv[i] = Yb[(head * 192 + 64 + dd * 4 + t) * 1024 + ch * 128 + mm];
        }
        __syncthreads();

        // compute S chunk (rows ty, ty+16 x cols tx*8..+7)
        {
            float a0[8] = {}, a1[8] = {};
#pragma unroll
            for (int dd = 0; dd < 16; dd++) {
                float q0 = qs[ty * 16 + dd];
                float q1 = qs[(ty + 16) * 16 + dd];
                float4 kA = *(float4*)&kv[dd * 128 + tx * 8];
                float4 kB = *(float4*)&kv[dd * 128 + tx * 8 + 4];
                float kk[8] = {kA.x, kA.y, kA.z, kA.w, kB.x, kB.y, kB.z, kB.w};
#pragma unroll
                for (int j = 0; j < 8; j++) { a0[j] += q0 * kk[j]; a1[j] += q1 * kk[j]; }
            }
            int base0 = ty * 132 + tx * 8;
            int base1 = (ty + 16) * 132 + tx * 8;
            *(float4*)&Sc[base0]     = make_float4(a0[0]*sc, a0[1]*sc, a0[2]*sc, a0[3]*sc);
            *(float4*)&Sc[base0 + 4] = make_float4(a0[4]*sc, a0[5]*sc, a0[6]*sc, a0[7]*sc);
            *(float4*)&Sc[base1]     = make_float4(a1[0]*sc, a1[1]*sc, a1[2]*sc, a1[3]*sc);
            *(float4*)&Sc[base1 + 4] = make_float4(a1[4]*sc, a1[5]*sc, a1[6]*sc, a1[7]*sc);
        }
        __syncthreads();

        // online softmax update (warp w owns rows w, w+8, w+16, w+24)
#pragma unroll
        for (int j = 0; j < 4; j++) {
            int rr = warp + j * 8;
            float* Sr = Sc + rr * 132;
            float v0 = Sr[lane], v1 = Sr[lane + 32], v2 = Sr[lane + 64], v3 = Sr[lane + 96];
            float mx = fmaxf(fmaxf(v0, v1), fmaxf(v2, v3));
#pragma unroll
            for (int o = 16; o; o >>= 1) mx = fmaxf(mx, __shfl_xor_sync(0xffffffffu, mx, o));
            float nm = fmaxf(rm[j], mx);
            float f  = __expf(rm[j] - nm);
            float e0 = __expf(v0 - nm), e1 = __expf(v1 - nm);
            float e2 = __expf(v2 - nm), e3 = __expf(v3 - nm);
            Sr[lane] = e0; Sr[lane + 32] = e1; Sr[lane + 64] = e2; Sr[lane + 96] = e3;
            float sum = e0 + e1 + e2 + e3;
#pragma unroll
            for (int o = 16; o; o >>= 1) sum += __shfl_xor_sync(0xffffffffu, sum, o);
            rs[j] = rs[j] * f + sum;
            rm[j] = nm;
            if (lane == 0) { fac_s[rr] = f; rsum_s[rr] = rs[j]; }
        }
        // load V chunk (kv free: S compute done)
        for (int i = tid; i < 2048; i += 256) {
            int dd = i >> 7, mm = i & 127;
            kv[i] = Yb[(head * 192 + 128 + dd * 4 + t) * 1024 + ch * 128 + mm];
        }
        __syncthreads();

        // PV: thread (pr row, pd & pd+8 dims)
        {
            float f = fac_s[pr];
            float p0 = 0.f, p1 = 0.f;
            float* Sr = Sc + pr * 132;
#pragma unroll
            for (int m4 = 0; m4 < 128; m4 += 4) {
                float4 p  = *(float4*)&Sr[m4];
                float4 w0 = *(float4*)&kv[pd * 128 + m4];
                float4 w1 = *(float4*)&kv[(pd + 8) * 128 + m4];
                p0 += p.x*w0.x + p.y*w0.y + p.z*w0.z + p.w*w0.w;
                p1 += p.x*w1.x + p.y*w1.y + p.z*w1.z + p.w*w1.w;
            }
            o0 = o0 * f + p0;
            o1 = o1 * f + p1;
        }
    }

    float inv = 1.f / rsum_s[pr];
    float* Ob = O + (long)b * 256 * 1024;
    Ob[(head * 64 + pd * 4 + t) * 1024 + r0 + pr]       = o0 * inv;
    Ob[(head * 64 + (pd + 8) * 4 + t) * 1024 + r0 + pr] = o1 * inv;
}

// ---------------------------------------------------------------------------
// PE conv (grouped quaternion 3x3, pad 1) + residual (unchanged)
// ---------------------------------------------------------------------------
__global__ void pe_kernel(const float* __restrict__ I, const float* __restrict__ pw,
                          const float* __restrict__ pb, float* __restrict__ Out) {
    int idx = blockIdx.x * 256 + threadIdx.x;
    if (idx >= 4 * 256 * 1024) return;
    int p = idx & 1023;
    int m = (idx >> 10) & 255;
    int b = idx >> 18;
    int h = p >> 5, w = p & 31;
    int co = m >> 2, t = m & 3, g = co >> 2;
    const float* Ib = I + (long)b * 256 * 1024;
    float acc = Ib[m * 1024 + p] + pb[m];
#pragma unroll
    for (int s = 0; s < 4; s++) {
        float sg = c_sgn[t * 4 + s];
        const float* wc = pw + ((long)c_cmp[t * 4 + s] * 64 + co) * 36;
#pragma unroll
        for (int cil = 0; cil < 4; cil++) {
            const float* in = Ib + ((g * 4 + cil) * 4 + s) * 1024;
            const float* wk = wc + cil * 9;
            float part = 0.f;
#pragma unroll
            for (int kh = 0; kh < 3; kh++) {
                int hh = h + kh - 1;
                if (hh < 0 || hh > 31) continue;
#pragma unroll
                for (int kw = 0; kw < 3; kw++) {
                    int ww = w + kw - 1;
                    if (ww < 0 || ww > 31) continue;
                    part += in[hh * 32 + ww] * wk[kh * 3 + kw];
                }
            }
            acc += sg * part;
        }
    }
    Out[idx] = acc;
}

// ---------------------------------------------------------------------------
extern "C" void kernel_launch(void* const* d_in, const int* in_sizes, int n_in,
                              void* d_out, int out_size) {
    const float* x      = (const float*)d_in[0];
    const float* cv1_w  = (const float*)d_in[1];
    const float* bn1_g  = (const float*)d_in[2];
    const float* bn1_b  = (const float*)d_in[3];
    const float* qkv_w  = (const float*)d_in[4];
    const float* qkv_b  = (const float*)d_in[5];
    const float* proj_w = (const float*)d_in[6];
    const float* proj_b = (const float*)d_in[7];
    const float* pe_w   = (const float*)d_in[8];
    const float* pe_b   = (const float*)d_in[9];
    const float* ang    = (const float*)d_in[10];
    const float* anb    = (const float*)d_in[11];
    const float* f1w    = (const float*)d_in[12];
    const float* f1g    = (const float*)d_in[13];
    const float* f1b    = (const float*)d_in[14];
    const float* f2w    = (const float*)d_in[15];
    const float* f2g    = (const float*)d_in[16];
    const float* f2b    = (const float*)d_in[17];
    const float* cv2_w  = (const float*)d_in[18];
    const float* bn2_g  = (const float*)d_in[19];
    const float* bn2_b  = (const float*)d_in[20];

    float *buf1, *buf2, *buf3, *buf4, *Wx, *scale, *shift;
    cudaGetSymbolAddress((void**)&buf1, g_buf1);
    cudaGetSymbolAddress((void**)&buf2, g_buf2);
    cudaGetSymbolAddress((void**)&buf3, g_buf3);
    cudaGetSymbolAddress((void**)&buf4, g_buf4);
    cudaGetSymbolAddress((void**)&Wx,   g_W);
    cudaGetSymbolAddress((void**)&scale, g_scale);
    cudaGetSymbolAddress((void**)&shift, g_shift);

    const long S512 = 512L * 1024, S768 = 768L * 1024, S256 = 256L * 1024;

    // Expand all quaternion weights in one launch
    expand_all_kernel<<<dim3(32, 6), 256>>>(cv1_w, qkv_w, proj_w, f1w, f2w, cv2_w, Wx);

    // Stage 1: cv1 + iqbn + relu
    mma_gemm_kernel<<<dim3(16, 8, 4), 128>>>(Wx + OFF_W1, x, buf1, nullptr, 512, 512, S512, S512);
    stats_kernel<<<512, 256>>>(buf1, S512, bn1_g, bn1_b, scale, shift);
    bn_apply_kernel<<<dim3(512, 4), 256>>>(buf1, buf1, scale, shift, S512, S512, 1);

    // qkv
    mma_gemm_kernel<<<dim3(16, 12, 4), 128>>>(Wx + OFF_WQ, buf1, buf2, qkv_b, 768, 256, S512, S768);

    // attention
    attn_kernel<<<dim3(32, 16, 4), 256>>>(buf2, buf3);

    // pe conv + residual
    pe_kernel<<<4096, 256>>>(buf3, pe_w, pe_b, buf4);

    // proj + attn_norm
    mma_gemm_kernel<<<dim3(16, 4, 4), 128>>>(Wx + OFF_WP, buf4, buf3, proj_b, 256, 256, S256, S256);
    stats_kernel<<<256, 256>>>(buf3, S256, ang, anb, scale, shift);
    bn_apply_kernel<<<dim3(256, 4), 256>>>(buf3, buf3, scale, shift, S256, S256, 0);

    // ffn1 + bn + relu
    mma_gemm_kernel<<<dim3(16, 8, 4), 128>>>(Wx + OFF_F1, buf3, buf2, nullptr, 512, 256, S256, S512);
    stats_kernel<<<512, 256>>>(buf2, S512, f1g, f1b, scale, shift);
    bn_apply_kernel<<<dim3(512, 4), 256>>>(buf2, buf2, scale, shift, S512, S512, 1);

    // ffn2 + bn
    mma_gemm_kernel<<<dim3(16, 4, 4), 128>>>(Wx + OFF_F2, buf2, buf1, nullptr, 256, 512, S512, S512);
    stats_kernel<<<256, 256>>>(buf1, S512, f2g, f2b, scale, shift);
    bn_apply_kernel<<<dim3(256, 4), 256>>>(buf1, buf1, scale, shift, S512, S512, 0);

    // cv2 on concat [a; b] + bn + relu -> d_out
    mma_gemm_kernel<<<dim3(16, 8, 4), 128>>>(Wx + OFF_C2, buf1, buf2, nullptr, 512, 512, S512, S512);
    stats_kernel<<<512, 256>>>(buf2, S512, bn2_g, bn2_b, scale, shift);
    bn_apply_kernel<<<dim3(512, 4), 256>>>(buf2, (float*)d_out, scale, shift, S512, S512, 1);
}

// round 5
// speedup vs baseline: 1.4736x; 1.0158x over previous
#include <cuda_runtime.h>
#include <cuda_bf16.h>
#include <cstdint>

// ---------------------------------------------------------------------------
// Quaternion Hamilton-product tables
// ---------------------------------------------------------------------------
__constant__ int   c_cmp[16] = {0,1,2,3,  1,0,3,2,  2,3,0,1,  3,2,1,0};
__constant__ float c_sgn[16] = {1.f,-1.f,-1.f,-1.f,
                                1.f, 1.f, 1.f,-1.f,
                                1.f,-1.f, 1.f, 1.f,
                                1.f, 1.f,-1.f, 1.f};

// ---------------------------------------------------------------------------
// Scratch (device globals)
// ---------------------------------------------------------------------------
__device__ float g_buf1[4*512*1024];
__device__ float g_buf2[4*768*1024];
__device__ float g_buf3[4*256*1024];
__device__ __align__(16) __nv_bfloat16 g_xh0[4*512*1024];
__device__ __align__(16) __nv_bfloat16 g_xl0[4*512*1024];
__device__ __align__(16) __nv_bfloat16 g_xh1[4*512*1024];
__device__ __align__(16) __nv_bfloat16 g_xl1[4*512*1024];
__device__ __align__(16) __nv_bfloat16 g_Wh[1048576];
__device__ __align__(16) __nv_bfloat16 g_Wl[1048576];
__device__ float g_scale[768];
__device__ float g_shift[768];

#define OFF_W1 0
#define OFF_WQ (OFF_W1 + 512*512)
#define OFF_WP (OFF_WQ + 768*256)
#define OFF_F1 (OFF_WP + 256*256)
#define OFF_F2 (OFF_F1 + 512*256)
#define OFF_C2 (OFF_F2 + 256*512)

__device__ __forceinline__ void splitf(float v, __nv_bfloat16& h, __nv_bfloat16& l) {
    h = __float2bfloat16(v);
    l = __float2bfloat16(v - __bfloat162float(h));
}

// ---------------------------------------------------------------------------
// Fused expansion: quaternion weights -> dense bf16 hi/lo GEMM weights
// ---------------------------------------------------------------------------
__global__ void expand_all_kernel(const float* __restrict__ w0, const float* __restrict__ w1,
                                  const float* __restrict__ w2, const float* __restrict__ w3,
                                  const float* __restrict__ w4, const float* __restrict__ w5,
                                  __nv_bfloat16* __restrict__ Wh, __nv_bfloat16* __restrict__ Wl) {
    const int Couts[6] = {128,192,64,128,64,128};
    const int Cins [6] = {128, 64,64, 64,128,128};
    const int offs [6] = {OFF_W1,OFF_WQ,OFF_WP,OFF_F1,OFF_F2,OFF_C2};
    const float* srcs[6] = {w0,w1,w2,w3,w4,w5};
    int q = blockIdx.y;
    int Cout = Couts[q], Cin = Cins[q];
    const float* w = srcs[q];
    int off = offs[q];
    int total = 16 * Cout * Cin;
    for (int i = blockIdx.x * blockDim.x + threadIdx.x; i < total;
         i += gridDim.x * blockDim.x) {
        int s = i & 3, t = (i >> 2) & 3;
        int rest = i >> 4;
        int ci = rest % Cin, co = rest / Cin;
        float val = c_sgn[t*4 + s] * w[c_cmp[t*4 + s] * Cout * Cin + co * Cin + ci];
        __nv_bfloat16 h, l;
        splitf(val, h, l);
        int idx = off + (co*4 + t) * (4*Cin) + ci*4 + s;
        Wh[idx] = h;
        Wl[idx] = l;
    }
}

// ---------------------------------------------------------------------------
// Plain fp32 -> bf16 hi/lo split (for the network input x)
// ---------------------------------------------------------------------------
__global__ __launch_bounds__(256) void split_x_kernel(const float* __restrict__ X,
                                                      __nv_bfloat16* __restrict__ H,
                                                      __nv_bfloat16* __restrict__ L) {
    int i = blockIdx.x * 256 + threadIdx.x;   // one float4 per thread
    float4 v = ((const float4*)X)[i];
    __nv_bfloat16 h[4], l[4];
    splitf(v.x, h[0], l[0]); splitf(v.y, h[1], l[1]);
    splitf(v.z, h[2], l[2]); splitf(v.w, h[3], l[3]);
    *(uint2*)(H + (long)i * 4) = *(uint2*)h;
    *(uint2*)(L + (long)i * 4) = *(uint2*)l;
}

// ---------------------------------------------------------------------------
// HMMA bf16-split GEMM, 64x64 CTA tile, 4 warps, warp tile 32x32, K-chunk 32.
// Operands pre-split into bf16 hi/lo planes -> zero conversion in-loop.
// ---------------------------------------------------------------------------
#define PITCH 40

__device__ __forceinline__ uint32_t prmt(uint32_t a, uint32_t b, uint32_t s) {
    uint32_t d;
    asm("prmt.b32 %0,%1,%2,%3;" : "=r"(d) : "r"(a), "r"(b), "r"(s));
    return d;
}

__device__ __forceinline__ void mma16816(float* d, uint32_t a0, uint32_t a1,
                                         uint32_t a2, uint32_t a3,
                                         uint32_t b0, uint32_t b1) {
    asm volatile(
        "mma.sync.aligned.m16n8k16.row.col.f32.bf16.bf16.f32 "
        "{%0,%1,%2,%3}, {%4,%5,%6,%7}, {%8,%9}, {%0,%1,%2,%3};"
        : "+f"(d[0]), "+f"(d[1]), "+f"(d[2]), "+f"(d[3])
        : "r"(a0), "r"(a1), "r"(a2), "r"(a3), "r"(b0), "r"(b1));
}

__global__ __launch_bounds__(128) void mma_gemm_kernel(
    const __nv_bfloat16* __restrict__ Wh, const __nv_bfloat16* __restrict__ Wl,
    const __nv_bfloat16* __restrict__ Xh, const __nv_bfloat16* __restrict__ Xl,
    float* __restrict__ Y, const float* __restrict__ bias,
    int M, int K, long sX, long sY)
{
    __shared__ __nv_bfloat16 sm[4 * 64 * PITCH];
    __nv_bfloat16* AsH = sm;
    __nv_bfloat16* AsL = sm + 64 * PITCH;
    __nv_bfloat16* BsH = sm + 2 * 64 * PITCH;
    __nv_bfloat16* BsL = sm + 3 * 64 * PITCH;

    const int tid = threadIdx.x;
    const int wid = tid >> 5, lane = tid & 31;
    const int wm = wid & 1, wn = wid >> 1;
    const int g = lane >> 2, tg = lane & 3;
    const int mo = blockIdx.y * 64, no = blockIdx.x * 64;
    const __nv_bfloat16* Xhb = Xh + blockIdx.z * sX;
    const __nv_bfloat16* Xlb = Xl + blockIdx.z * sX;
    float* Yb = Y + blockIdx.z * sY;

    const int am = tid >> 1, ak = (tid & 1) * 16;
    float acc[2][4][4] = {};
    const int nch = K >> 5;

    uint4 awh[2], awl[2];
    uint2 bwh[2][2], bwl[2][2];   // [it][k-row]

    // prefetch chunk 0
    {
        const __nv_bfloat16* Ah = Wh + (long)(mo + am) * K + ak;
        const __nv_bfloat16* Al = Wl + (long)(mo + am) * K + ak;
        awh[0] = *(const uint4*)Ah; awh[1] = *(const uint4*)(Ah + 8);
        awl[0] = *(const uint4*)Al; awl[1] = *(const uint4*)(Al + 8);
#pragma unroll
        for (int it = 0; it < 2; it++) {
            int u = tid + it * 128;
            int nn = (u & 15) * 4, kk = (u >> 4) * 2;
            const __nv_bfloat16* Bh = Xhb + (long)kk * 1024 + no + nn;
            const __nv_bfloat16* Bl = Xlb + (long)kk * 1024 + no + nn;
            bwh[it][0] = *(const uint2*)Bh; bwh[it][1] = *(const uint2*)(Bh + 1024);
            bwl[it][0] = *(const uint2*)Bl; bwl[it][1] = *(const uint2*)(Bl + 1024);
        }
    }

    for (int ch = 0; ch < nch; ch++) {
        __syncthreads();   // previous chunk's compute done

        // ---- store A (no conversion) ----
        {
            uint32_t* dH = (uint32_t*)(AsH + am * PITCH + ak);
            uint32_t* dL = (uint32_t*)(AsL + am * PITCH + ak);
            *(uint4*)dH = awh[0]; *(uint4*)(dH + 4) = awh[1];
            *(uint4*)dL = awl[0]; *(uint4*)(dL + 4) = awl[1];
        }
        // ---- store B: transpose 2k x 4n via PRMT ----
#pragma unroll
        for (int it = 0; it < 2; it++) {
            int u = tid + it * 128;
            int nn = (u & 15) * 4, kk = (u >> 4) * 2;
            uint32_t a0 = bwh[it][0].x, a1 = bwh[it][0].y;
            uint32_t b0 = bwh[it][1].x, b1 = bwh[it][1].y;
            *(uint32_t*)(BsH + (nn + 0) * PITCH + kk) = prmt(a0, b0, 0x5410);
            *(uint32_t*)(BsH + (nn + 1) * PITCH + kk) = prmt(a0, b0, 0x7632);
            *(uint32_t*)(BsH + (nn + 2) * PITCH + kk) = prmt(a1, b1, 0x5410);
            *(uint32_t*)(BsH + (nn + 3) * PITCH + kk) = prmt(a1, b1, 0x7632);
            a0 = bwl[it][0].x; a1 = bwl[it][0].y;
            b0 = bwl[it][1].x; b1 = bwl[it][1].y;
            *(uint32_t*)(BsL + (nn + 0) * PITCH + kk) = prmt(a0, b0, 0x5410);
            *(uint32_t*)(BsL + (nn + 1) * PITCH + kk) = prmt(a0, b0, 0x7632);
            *(uint32_t*)(BsL + (nn + 2) * PITCH + kk) = prmt(a1, b1, 0x5410);
            *(uint32_t*)(BsL + (nn + 3) * PITCH + kk) = prmt(a1, b1, 0x7632);
        }
        __syncthreads();

        // ---- prefetch next chunk (overlaps compute) ----
        if (ch + 1 < nch) {
            int kt = (ch + 1) * 32;
            const __nv_bfloat16* Ah = Wh + (long)(mo + am) * K + kt + ak;
            const __nv_bfloat16* Al = Wl + (long)(mo + am) * K + kt + ak;
            awh[0] = *(const uint4*)Ah; awh[1] = *(const uint4*)(Ah + 8);
            awl[0] = *(const uint4*)Al; awl[1] = *(const uint4*)(Al + 8);
#pragma unroll
            for (int it = 0; it < 2; it++) {
                int u = tid + it * 128;
                int nn = (u & 15) * 4, kk = (u >> 4) * 2;
                const __nv_bfloat16* Bh = Xhb + (long)(kt + kk) * 1024 + no + nn;
                const __nv_bfloat16* Bl = Xlb + (long)(kt + kk) * 1024 + no + nn;
                bwh[it][0] = *(const uint2*)Bh; bwh[it][1] = *(const uint2*)(Bh + 1024);
                bwl[it][0] = *(const uint2*)Bl; bwl[it][1] = *(const uint2*)(Bl + 1024);
            }
        }

        // ---- compute ----
#pragma unroll
        for (int k0 = 0; k0 < 32; k0 += 16) {
            uint32_t ah[2][4], al[2][4];
#pragma unroll
            for (int mt = 0; mt < 2; mt++) {
                int r = wm * 32 + mt * 16;
                const __nv_bfloat16* pH = AsH + k0 + 2 * tg;
                const __nv_bfloat16* pL = AsL + k0 + 2 * tg;
                ah[mt][0] = *(const uint32_t*)(pH + (r + g) * PITCH);
                ah[mt][1] = *(const uint32_t*)(pH + (r + g + 8) * PITCH);
                ah[mt][2] = *(const uint32_t*)(pH + (r + g) * PITCH + 8);
                ah[mt][3] = *(const uint32_t*)(pH + (r + g + 8) * PITCH + 8);
                al[mt][0] = *(const uint32_t*)(pL + (r + g) * PITCH);
                al[mt][1] = *(const uint32_t*)(pL + (r + g + 8) * PITCH);
                al[mt][2] = *(const uint32_t*)(pL + (r + g) * PITCH + 8);
                al[mt][3] = *(const uint32_t*)(pL + (r + g + 8) * PITCH + 8);
            }
#pragma unroll
            for (int nt = 0; nt < 4; nt++) {
                int nb = wn * 32 + nt * 8 + g;
                uint32_t bh0 = *(const uint32_t*)(BsH + nb * PITCH + k0 + 2 * tg);
                uint32_t bh1 = *(const uint32_t*)(BsH + nb * PITCH + k0 + 2 * tg + 8);
                uint32_t bl0 = *(const uint32_t*)(BsL + nb * PITCH + k0 + 2 * tg);
                uint32_t bl1 = *(const uint32_t*)(BsL + nb * PITCH + k0 + 2 * tg + 8);
#pragma unroll
                for (int mt = 0; mt < 2; mt++) {
                    mma16816(acc[mt][nt], ah[mt][0], ah[mt][1], ah[mt][2], ah[mt][3], bh0, bh1);
                    mma16816(acc[mt][nt], al[mt][0], al[mt][1], al[mt][2], al[mt][3], bh0, bh1);
                    mma16816(acc[mt][nt], ah[mt][0], ah[mt][1], ah[mt][2], ah[mt][3], bl0, bl1);
                }
            }
        }
    }

    // ---- epilogue ----
#pragma unroll
    for (int mt = 0; mt < 2; mt++) {
        int r0 = mo + wm * 32 + mt * 16 + g;
        int r1 = r0 + 8;
        float bv0 = bias ? bias[r0] : 0.f;
        float bv1 = bias ? bias[r1] : 0.f;
#pragma unroll
        for (int nt = 0; nt < 4; nt++) {
            int c = no + wn * 32 + nt * 8 + 2 * tg;
            float* d = acc[mt][nt];
            *(float2*)(Yb + (long)r0 * 1024 + c) = make_float2(d[0] + bv0, d[1] + bv0);
            *(float2*)(Yb + (long)r1 * 1024 + c) = make_float2(d[2] + bv1, d[3] + bv1);
        }
    }
}

// ---------------------------------------------------------------------------
// Batchnorm stats (unchanged)
// ---------------------------------------------------------------------------
__global__ __launch_bounds__(256) void stats_kernel(
    const float* __restrict__ X, long bstride,
    const float* __restrict__ g, const float* __restrict__ be,
    float* __restrict__ scale, float* __restrict__ shift)
{
    int m = blockIdx.x, tid = threadIdx.x;
    float s = 0.f, sq = 0.f;
#pragma unroll
    for (int b = 0; b < 4; b++) {
        float4 v = *(const float4*)(X + b * bstride + (long)m * 1024 + tid * 4);
        s  += v.x + v.y + v.z + v.w;
        sq += v.x*v.x + v.y*v.y + v.z*v.z + v.w*v.w;
    }
#pragma unroll
    for (int o = 16; o; o >>= 1) {
        s  += __shfl_xor_sync(0xffffffffu, s, o);
        sq += __shfl_xor_sync(0xffffffffu, sq, o);
    }
    __shared__ float ps[8], pq[8];
    if ((tid & 31) == 0) { ps[tid >> 5] = s; pq[tid >> 5] = sq; }
    __syncthreads();
    if (tid == 0) {
        s = 0.f; sq = 0.f;
#pragma unroll
        for (int i = 0; i < 8; i++) { s += ps[i]; sq += pq[i]; }
        float mean = s * (1.f / 4096.f);
        float var  = sq * (1.f / 4096.f) - mean * mean;
        float rstd = rsqrtf(var + 1e-5f);
        float sc = g[m] * rstd;
        scale[m] = sc;
        shift[m] = be[m] - mean * sc;
    }
}

// ---------------------------------------------------------------------------
// BN apply -> bf16 hi/lo planes (+optional relu). grid (M, 4).
// ---------------------------------------------------------------------------
__global__ __launch_bounds__(256) void bn_split_kernel(
    const float* __restrict__ X, __nv_bfloat16* __restrict__ H,
    __nv_bfloat16* __restrict__ L,
    const float* __restrict__ scale, const float* __restrict__ shift,
    long bsX, long bsP, int relu)
{
    int m = blockIdx.x, b = blockIdx.y, tid = threadIdx.x;
    float sc = scale[m], sh = shift[m];
    float4 v = *(const float4*)(X + (long)b * bsX + (long)m * 1024 + tid * 4);
    v.x = v.x * sc + sh; v.y = v.y * sc + sh;
    v.z = v.z * sc + sh; v.w = v.w * sc + sh;
    if (relu) {
        v.x = fmaxf(v.x, 0.f); v.y = fmaxf(v.y, 0.f);
        v.z = fmaxf(v.z, 0.f); v.w = fmaxf(v.w, 0.f);
    }
    __nv_bfloat16 h[4], l[4];
    splitf(v.x, h[0], l[0]); splitf(v.y, h[1], l[1]);
    splitf(v.z, h[2], l[2]); splitf(v.w, h[3], l[3]);
    long o = (long)b * bsP + (long)m * 1024 + tid * 4;
    *(uint2*)(H + o) = *(uint2*)h;
    *(uint2*)(L + o) = *(uint2*)l;
}

// ---------------------------------------------------------------------------
// Final BN apply (fp32 out, relu) — for d_out
// ---------------------------------------------------------------------------
__global__ __launch_bounds__(256) void bn_apply_kernel(
    const float* __restrict__ X, float* __restrict__ Y,
    const float* __restrict__ scale, const float* __restrict__ shift,
    long bsX, long bsY, int relu)
{
    int m = blockIdx.x, b = blockIdx.y, tid = threadIdx.x;
    float sc = scale[m], sh = shift[m];
    float4 v = *(const float4*)(X + (long)b * bsX + (long)m * 1024 + tid * 4);
    v.x = v.x * sc + sh; v.y = v.y * sc + sh;
    v.z = v.z * sc + sh; v.w = v.w * sc + sh;
    if (relu) {
        v.x = fmaxf(v.x, 0.f); v.y = fmaxf(v.y, 0.f);
        v.z = fmaxf(v.z, 0.f); v.w = fmaxf(v.w, 0.f);
    }
    *(float4*)(Y + (long)b * bsY + (long)m * 1024 + tid * 4) = v;
}

// ---------------------------------------------------------------------------
// Flash attention (unchanged from R4 — known good)
// ---------------------------------------------------------------------------
__global__ __launch_bounds__(256) void attn_kernel(const float* __restrict__ Yq,
                                                   float* __restrict__ O) {
    __shared__ float qs[32 * 16];
    __shared__ float kv[16 * 128];
    __shared__ float Sc[32 * 132];
    __shared__ float fac_s[32], rsum_s[32];

    int b = blockIdx.z;
    int head = blockIdx.y >> 2, t = blockIdx.y & 3;
    int r0 = blockIdx.x * 32;
    const float* Yb = Yq + (long)b * 768 * 1024;
    int tid = threadIdx.x;
    int lane = tid & 31, warp = tid >> 5;
    int ty = tid >> 4, tx = tid & 15;
    int pr = tid & 31, pd = tid >> 5;

    for (int i = tid; i < 512; i += 256) {
        int dd = i >> 5, n = i & 31;
        qs[n * 16 + dd] = Yb[(head * 192 + dd * 4 + t) * 1024 + r0 + n];
    }

    float o0 = 0.f, o1 = 0.f;
    float rm[4] = {-1e30f, -1e30f, -1e30f, -1e30f};
    float rs[4] = {0.f, 0.f, 0.f, 0.f};
    const float sc = 0.25f;

    for (int ch = 0; ch < 8; ch++) {
        __syncthreads();
        for (int i = tid; i < 2048; i += 256) {
            int dd = i >> 7, mm = i & 127;
            kv[i] = Yb[(head * 192 + 64 + dd * 4 + t) * 1024 + ch * 128 + mm];
        }
        __syncthreads();

        {
            float a0[8] = {}, a1[8] = {};
#pragma unroll
            for (int dd = 0; dd < 16; dd++) {
                float q0 = qs[ty * 16 + dd];
                float q1 = qs[(ty + 16) * 16 + dd];
                float4 kA = *(float4*)&kv[dd * 128 + tx * 8];
                float4 kB = *(float4*)&kv[dd * 128 + tx * 8 + 4];
                float kk[8] = {kA.x, kA.y, kA.z, kA.w, kB.x, kB.y, kB.z, kB.w};
#pragma unroll
                for (int j = 0; j < 8; j++) { a0[j] += q0 * kk[j]; a1[j] += q1 * kk[j]; }
            }
            int base0 = ty * 132 + tx * 8;
            int base1 = (ty + 16) * 132 + tx * 8;
            *(float4*)&Sc[base0]     = make_float4(a0[0]*sc, a0[1]*sc, a0[2]*sc, a0[3]*sc);
            *(float4*)&Sc[base0 + 4] = make_float4(a0[4]*sc, a0[5]*sc, a0[6]*sc, a0[7]*sc);
            *(float4*)&Sc[base1]     = make_float4(a1[0]*sc, a1[1]*sc, a1[2]*sc, a1[3]*sc);
            *(float4*)&Sc[base1 + 4] = make_float4(a1[4]*sc, a1[5]*sc, a1[6]*sc, a1[7]*sc);
        }
        __syncthreads();

#pragma unroll
        for (int j = 0; j < 4; j++) {
            int rr = warp + j * 8;
            float* Sr = Sc + rr * 132;
            float v0 = Sr[lane], v1 = Sr[lane + 32], v2 = Sr[lane + 64], v3 = Sr[lane + 96];
            float mx = fmaxf(fmaxf(v0, v1), fmaxf(v2, v3));
#pragma unroll
            for (int o = 16; o; o >>= 1) mx = fmaxf(mx, __shfl_xor_sync(0xffffffffu, mx, o));
            float nm = fmaxf(rm[j], mx);
            float f  = __expf(rm[j] - nm);
            float e0 = __expf(v0 - nm), e1 = __expf(v1 - nm);
            float e2 = __expf(v2 - nm), e3 = __expf(v3 - nm);
            Sr[lane] = e0; Sr[lane + 32] = e1; Sr[lane + 64] = e2; Sr[lane + 96] = e3;
            float sum = e0 + e1 + e2 + e3;
#pragma unroll
            for (int o = 16; o; o >>= 1) sum += __shfl_xor_sync(0xffffffffu, sum, o);
            rs[j] = rs[j] * f + sum;
            rm[j] = nm;
            if (lane == 0) { fac_s[rr] = f; rsum_s[rr] = rs[j]; }
        }
        for (int i = tid; i < 2048; i += 256) {
            int dd = i >> 7, mm = i & 127;
            kv[i] = Yb[(head * 192 + 128 + dd * 4 + t) * 1024 + ch * 128 + mm];
        }
        __syncthreads();

        {
            float f = fac_s[pr];
            float p0 = 0.f, p1 = 0.f;
            float* Sr = Sc + pr * 132;
#pragma unroll
            for (int m4 = 0; m4 < 128; m4 += 4) {
                float4 p  = *(float4*)&Sr[m4];
                float4 w0 = *(float4*)&kv[pd * 128 + m4];
                float4 w1 = *(float4*)&kv[(pd + 8) * 128 + m4];
                p0 += p.x*w0.x + p.y*w0.y + p.z*w0.z + p.w*w0.w;
                p1 += p.x*w1.x + p.y*w1.y + p.z*w1.z + p.w*w1.w;
            }
            o0 = o0 * f + p0;
            o1 = o1 * f + p1;
        }
    }

    float inv = 1.f / rsum_s[pr];
    float* Ob = O + (long)b * 256 * 1024;
    Ob[(head * 64 + pd * 4 + t) * 1024 + r0 + pr]       = o0 * inv;
    Ob[(head * 64 + (pd + 8) * 4 + t) * 1024 + r0 + pr] = o1 * inv;
}

// ---------------------------------------------------------------------------
// PE conv + residual; emits bf16 hi/lo split planes (stride bsP per batch)
// ---------------------------------------------------------------------------
__global__ void pe_kernel(const float* __restrict__ I, const float* __restrict__ pw,
                          const float* __restrict__ pb,
                          __nv_bfloat16* __restrict__ H, __nv_bfloat16* __restrict__ L,
                          long bsP) {
    int idx = blockIdx.x * 256 + threadIdx.x;
    if (idx >= 4 * 256 * 1024) return;
    int p = idx & 1023;
    int m = (idx >> 10) & 255;
    int b = idx >> 18;
    int h = p >> 5, w = p & 31;
    int co = m >> 2, t = m & 3, g = co >> 2;
    const float* Ib = I + (long)b * 256 * 1024;
    float acc = Ib[m * 1024 + p] + pb[m];
#pragma unroll
    for (int s = 0; s < 4; s++) {
        float sg = c_sgn[t * 4 + s];
        const float* wc = pw + ((long)c_cmp[t * 4 + s] * 64 + co) * 36;
#pragma unroll
        for (int cil = 0; cil < 4; cil++) {
            const float* in = Ib + ((g * 4 + cil) * 4 + s) * 1024;
            const float* wk = wc + cil * 9;
            float part = 0.f;
#pragma unroll
            for (int kh = 0; kh < 3; kh++) {
                int hh = h + kh - 1;
                if (hh < 0 || hh > 31) continue;
#pragma unroll
                for (int kw = 0; kw < 3; kw++) {
                    int ww = w + kw - 1;
                    if (ww < 0 || ww > 31) continue;
                    part += in[hh * 32 + ww] * wk[kh * 3 + kw];
                }
            }
            acc += sg * part;
        }
    }
    __nv_bfloat16 hh, ll;
    splitf(acc, hh, ll);
    long o = (long)b * bsP + (long)m * 1024 + p;
    H[o] = hh;
    L[o] = ll;
}

// ---------------------------------------------------------------------------
extern "C" void kernel_launch(void* const* d_in, const int* in_sizes, int n_in,
                              void* d_out, int out_size) {
    const float* x      = (const float*)d_in[0];
    const float* cv1_w  = (const float*)d_in[1];
    const float* bn1_g  = (const float*)d_in[2];
    const float* bn1_b  = (const float*)d_in[3];
    const float* qkv_w  = (const float*)d_in[4];
    const float* qkv_b  = (const float*)d_in[5];
    const float* proj_w = (const float*)d_in[6];
    const float* proj_b = (const float*)d_in[7];
    const float* pe_w   = (const float*)d_in[8];
    const float* pe_b   = (const float*)d_in[9];
    const float* ang    = (const float*)d_in[10];
    const float* anb    = (const float*)d_in[11];
    const float* f1w    = (const float*)d_in[12];
    const float* f1g    = (const float*)d_in[13];
    const float* f1b    = (const float*)d_in[14];
    const float* f2w    = (const float*)d_in[15];
    const float* f2g    = (const float*)d_in[16];
    const float* f2b    = (const float*)d_in[17];
    const float* cv2_w  = (const float*)d_in[18];
    const float* bn2_g  = (const float*)d_in[19];
    const float* bn2_b  = (const float*)d_in[20];

    float *buf1, *buf2, *buf3, *scale, *shift;
    __nv_bfloat16 *xh0, *xl0, *xh1, *xl1, *Wh, *Wl;
    cudaGetSymbolAddress((void**)&buf1, g_buf1);
    cudaGetSymbolAddress((void**)&buf2, g_buf2);
    cudaGetSymbolAddress((void**)&buf3, g_buf3);
    cudaGetSymbolAddress((void**)&xh0,  g_xh0);
    cudaGetSymbolAddress((void**)&xl0,  g_xl0);
    cudaGetSymbolAddress((void**)&xh1,  g_xh1);
    cudaGetSymbolAddress((void**)&xl1,  g_xl1);
    cudaGetSymbolAddress((void**)&Wh,   g_Wh);
    cudaGetSymbolAddress((void**)&Wl,   g_Wl);
    cudaGetSymbolAddress((void**)&scale, g_scale);
    cudaGetSymbolAddress((void**)&shift, g_shift);

    const long S512 = 512L * 1024, S768 = 768L * 1024, S256 = 256L * 1024;

    // Expand quaternion weights -> bf16 hi/lo planes
    expand_all_kernel<<<dim3(32, 6), 256>>>(cv1_w, qkv_w, proj_w, f1w, f2w, cv2_w, Wh, Wl);
    // Split input x -> P0
    split_x_kernel<<<2048, 256>>>(x, xh0, xl0);

    // cv1 + iqbn(+relu) -> P1 (512 rows; b half stays for cv2)
    mma_gemm_kernel<<<dim3(16, 8, 4), 128>>>(Wh + OFF_W1, Wl + OFF_W1, xh0, xl0,
                                             buf1, nullptr, 512, 512, S512, S512);
    stats_kernel<<<512, 256>>>(buf1, S512, bn1_g, bn1_b, scale, shift);
    bn_split_kernel<<<dim3(512, 4), 256>>>(buf1, xh1, xl1, scale, shift, S512, S512, 1);

    // qkv (reads P1 rows 0..255)
    mma_gemm_kernel<<<dim3(16, 12, 4), 128>>>(Wh + OFF_WQ, Wl + OFF_WQ, xh1, xl1,
                                              buf2, qkv_b, 768, 256, S512, S768);

    // attention
    attn_kernel<<<dim3(32, 16, 4), 256>>>(buf2, buf3);

    // pe conv + residual -> P0 (256 rows)
    pe_kernel<<<4096, 256>>>(buf3, pe_w, pe_b, xh0, xl0, S512);

    // proj + attn_norm -> P0
    mma_gemm_kernel<<<dim3(16, 4, 4), 128>>>(Wh + OFF_WP, Wl + OFF_WP, xh0, xl0,
                                             buf3, proj_b, 256, 256, S512, S256);
    stats_kernel<<<256, 256>>>(buf3, S256, ang, anb, scale, shift);
    bn_split_kernel<<<dim3(256, 4), 256>>>(buf3, xh0, xl0, scale, shift, S256, S512, 0);

    // ffn1 + bn(+relu) -> P0
    mma_gemm_kernel<<<dim3(16, 8, 4), 128>>>(Wh + OFF_F1, Wl + OFF_F1, xh0, xl0,
                                             buf2, nullptr, 512, 256, S512, S512);
    stats_kernel<<<512, 256>>>(buf2, S512, f1g, f1b, scale, shift);
    bn_split_kernel<<<dim3(512, 4), 256>>>(buf2, xh0, xl0, scale, shift, S512, S512, 1);

    // ffn2 + bn -> P1 rows 0..255 (rows 256..511 = b from bn1)
    mma_gemm_kernel<<<dim3(16, 4, 4), 128>>>(Wh + OFF_F2, Wl + OFF_F2, xh0, xl0,
                                             buf3, nullptr, 256, 512, S512, S256);
    stats_kernel<<<256, 256>>>(buf3, S256, f2g, f2b, scale, shift);
    bn_split_kernel<<<dim3(256, 4), 256>>>(buf3, xh1, xl1, scale, shift, S256, S512, 0);

    // cv2 on concat + bn + relu -> d_out
    mma_gemm_kernel<<<dim3(16, 8, 4), 128>>>(Wh + OFF_C2, Wl + OFF_C2, xh1, xl1,
                                             buf2, nullptr, 512, 512, S512, S512);
    stats_kernel<<<512, 256>>>(buf2, S512, bn2_g, bn2_b, scale, shift);
    bn_apply_kernel<<<dim3(512, 4), 256>>>(buf2, (float*)d_out, scale, shift, S512, S512, 1);
}

// round 8
// speedup vs baseline: 1.4995x; 1.0176x over previous
#include <cuda_runtime.h>
#include <cuda_bf16.h>
#include <cstdint>

// ---------------------------------------------------------------------------
// Quaternion Hamilton-product tables
// ---------------------------------------------------------------------------
__constant__ int   c_cmp[16] = {0,1,2,3,  1,0,3,2,  2,3,0,1,  3,2,1,0};
__constant__ float c_sgn[16] = {1.f,-1.f,-1.f,-1.f,
                                1.f, 1.f, 1.f,-1.f,
                                1.f,-1.f, 1.f, 1.f,
                                1.f, 1.f,-1.f, 1.f};

// ---------------------------------------------------------------------------
// Scratch (device globals)
// ---------------------------------------------------------------------------
__device__ float g_buf1[4*512*1024];
__device__ float g_buf2[4*768*1024];
__device__ float g_buf3[4*256*1024];
__device__ __align__(16) __nv_bfloat16 g_xh0[4*512*1024];
__device__ __align__(16) __nv_bfloat16 g_xl0[4*512*1024];
__device__ __align__(16) __nv_bfloat16 g_xh1[4*512*1024];
__device__ __align__(16) __nv_bfloat16 g_xl1[4*512*1024];
__device__ __align__(16) __nv_bfloat16 g_Wh[1048576];
__device__ __align__(16) __nv_bfloat16 g_Wl[1048576];

#define OFF_W1 0
#define OFF_WQ (OFF_W1 + 512*512)
#define OFF_WP (OFF_WQ + 768*256)
#define OFF_F1 (OFF_WP + 256*256)
#define OFF_F2 (OFF_F1 + 512*256)
#define OFF_C2 (OFF_F2 + 256*512)

__device__ __forceinline__ void splitf(float v, __nv_bfloat16& h, __nv_bfloat16& l) {
    h = __float2bfloat16(v);
    l = __float2bfloat16(v - __bfloat162float(h));
}

// ---------------------------------------------------------------------------
// Fused expansion: quaternion weights -> dense bf16 hi/lo GEMM weights
// ---------------------------------------------------------------------------
__global__ void expand_all_kernel(const float* __restrict__ w0, const float* __restrict__ w1,
                                  const float* __restrict__ w2, const float* __restrict__ w3,
                                  const float* __restrict__ w4, const float* __restrict__ w5,
                                  __nv_bfloat16* __restrict__ Wh, __nv_bfloat16* __restrict__ Wl) {
    const int Couts[6] = {128,192,64,128,64,128};
    const int Cins [6] = {128, 64,64, 64,128,128};
    const int offs [6] = {OFF_W1,OFF_WQ,OFF_WP,OFF_F1,OFF_F2,OFF_C2};
    const float* srcs[6] = {w0,w1,w2,w3,w4,w5};
    int q = blockIdx.y;
    int Cout = Couts[q], Cin = Cins[q];
    const float* w = srcs[q];
    int off = offs[q];
    int total = 16 * Cout * Cin;
    for (int i = blockIdx.x * blockDim.x + threadIdx.x; i < total;
         i += gridDim.x * blockDim.x) {
        int s = i & 3, t = (i >> 2) & 3;
        int rest = i >> 4;
        int ci = rest % Cin, co = rest / Cin;
        float val = c_sgn[t*4 + s] * w[c_cmp[t*4 + s] * Cout * Cin + co * Cin + ci];
        __nv_bfloat16 h, l;
        splitf(val, h, l);
        int idx = off + (co*4 + t) * (4*Cin) + ci*4 + s;
        Wh[idx] = h;
        Wl[idx] = l;
    }
}

// ---------------------------------------------------------------------------
// Plain fp32 -> bf16 hi/lo split (network input x)
// ---------------------------------------------------------------------------
__global__ __launch_bounds__(256) void split_x_kernel(const float* __restrict__ X,
                                                      __nv_bfloat16* __restrict__ H,
                                                      __nv_bfloat16* __restrict__ L) {
    int i = blockIdx.x * 256 + threadIdx.x;
    float4 v = ((const float4*)X)[i];
    __nv_bfloat16 h[4], l[4];
    splitf(v.x, h[0], l[0]); splitf(v.y, h[1], l[1]);
    splitf(v.z, h[2], l[2]); splitf(v.w, h[3], l[3]);
    *(uint2*)(H + (long)i * 4) = *(uint2*)h;
    *(uint2*)(L + (long)i * 4) = *(uint2*)l;
}

// ---------------------------------------------------------------------------
// mma helpers
// ---------------------------------------------------------------------------
__device__ __forceinline__ void mma16816(float* d, uint32_t a0, uint32_t a1,
                                         uint32_t a2, uint32_t a3,
                                         uint32_t b0, uint32_t b1) {
    asm volatile(
        "mma.sync.aligned.m16n8k16.row.col.f32.bf16.bf16.f32 "
        "{%0,%1,%2,%3}, {%4,%5,%6,%7}, {%8,%9}, {%0,%1,%2,%3};"
        : "+f"(d[0]), "+f"(d[1]), "+f"(d[2]), "+f"(d[3])
        : "r"(a0), "r"(a1), "r"(a2), "r"(a3), "r"(b0), "r"(b1));
}
__device__ __forceinline__ uint32_t prmt(uint32_t a, uint32_t b, uint32_t s) {
    uint32_t d;
    asm("prmt.b32 %0,%1,%2,%3;" : "=r"(d) : "r"(a), "r"(b), "r"(s));
    return d;
}

// ---------------------------------------------------------------------------
// HMMA bf16-split GEMM, 64x64 tile, 4 warps, K-chunk 32, DOUBLE-BUFFERED smem.
// B loader: 128 threads x 2 units covering the FULL 64n x 32k tile (R5 semantics).
// ---------------------------------------------------------------------------
#define PITCH 40

__global__ __launch_bounds__(128) void mma_gemm_kernel(
    const __nv_bfloat16* __restrict__ Wh, const __nv_bfloat16* __restrict__ Wl,
    const __nv_bfloat16* __restrict__ Xh, const __nv_bfloat16* __restrict__ Xl,
    float* __restrict__ Y, const float* __restrict__ bias,
    int M, int K, long sX, long sY)
{
    __shared__ __nv_bfloat16 sm[2][4 * 64 * PITCH];

    const int tid = threadIdx.x;
    const int wid = tid >> 5, lane = tid & 31;
    const int wm = wid & 1, wn = wid >> 1;
    const int g = lane >> 2, tg = lane & 3;
    const int mo = blockIdx.y * 64, no = blockIdx.x * 64;
    const __nv_bfloat16* Xhb = Xh + blockIdx.z * sX;
    const __nv_bfloat16* Xlb = Xl + blockIdx.z * sX;
    float* Yb = Y + blockIdx.z * sY;

    const int am = tid >> 1, ak = (tid & 1) * 16;
    // B-loader unit coords for it = 0,1 (u = tid + it*128 covers 256 units)
    const int bnn0 = (tid & 15) * 4,          bkk0 = (tid >> 4) * 2;
    const int bnn1 = ((tid + 128) & 15) * 4,  bkk1 = ((tid + 128) >> 4) * 2;
    float acc[2][4][4] = {};
    const int nch = K >> 5;

    uint4 awh[2], awl[2];
    uint2 bwh[2][2], bwl[2][2];   // [it][k-row]

#define LOAD_REGS(kt)                                                           \
    {                                                                           \
        const __nv_bfloat16* Ah = Wh + (long)(mo + am) * K + (kt) + ak;         \
        const __nv_bfloat16* Al = Wl + (long)(mo + am) * K + (kt) + ak;         \
        awh[0] = *(const uint4*)Ah; awh[1] = *(const uint4*)(Ah + 8);           \
        awl[0] = *(const uint4*)Al; awl[1] = *(const uint4*)(Al + 8);           \
        const __nv_bfloat16* Bh0 = Xhb + (long)((kt) + bkk0) * 1024 + no + bnn0;\
        const __nv_bfloat16* Bl0 = Xlb + (long)((kt) + bkk0) * 1024 + no + bnn0;\
        bwh[0][0] = *(const uint2*)Bh0; bwh[0][1] = *(const uint2*)(Bh0 + 1024);\
        bwl[0][0] = *(const uint2*)Bl0; bwl[0][1] = *(const uint2*)(Bl0 + 1024);\
        const __nv_bfloat16* Bh1 = Xhb + (long)((kt) + bkk1) * 1024 + no + bnn1;\
        const __nv_bfloat16* Bl1 = Xlb + (long)((kt) + bkk1) * 1024 + no + bnn1;\
        bwh[1][0] = *(const uint2*)Bh1; bwh[1][1] = *(const uint2*)(Bh1 + 1024);\
        bwl[1][0] = *(const uint2*)Bl1; bwl[1][1] = *(const uint2*)(Bl1 + 1024);\
    }

#define STORE_B_UNIT(BsH, BsL, it, nn, kk)                                      \
    {                                                                           \
        uint32_t a0 = bwh[it][0].x, a1 = bwh[it][0].y;                          \
        uint32_t b0 = bwh[it][1].x, b1 = bwh[it][1].y;                          \
        *(uint32_t*)((BsH) + ((nn) + 0) * PITCH + (kk)) = prmt(a0, b0, 0x5410); \
        *(uint32_t*)((BsH) + ((nn) + 1) * PITCH + (kk)) = prmt(a0, b0, 0x7632); \
        *(uint32_t*)((BsH) + ((nn) + 2) * PITCH + (kk)) = prmt(a1, b1, 0x5410); \
        *(uint32_t*)((BsH) + ((nn) + 3) * PITCH + (kk)) = prmt(a1, b1, 0x7632); \
        a0 = bwl[it][0].x; a1 = bwl[it][0].y;                                   \
        b0 = bwl[it][1].x; b1 = bwl[it][1].y;                                   \
        *(uint32_t*)((BsL) + ((nn) + 0) * PITCH + (kk)) = prmt(a0, b0, 0x5410); \
        *(uint32_t*)((BsL) + ((nn) + 1) * PITCH + (kk)) = prmt(a0, b0, 0x7632); \
        *(uint32_t*)((BsL) + ((nn) + 2) * PITCH + (kk)) = prmt(a1, b1, 0x5410); \
        *(uint32_t*)((BsL) + ((nn) + 3) * PITCH + (kk)) = prmt(a1, b1, 0x7632); \
    }

#define STORE_SMEM(buf)                                                         \
    {                                                                           \
        __nv_bfloat16* AsH = sm[buf];                                           \
        __nv_bfloat16* AsL = sm[buf] + 64 * PITCH;                              \
        __nv_bfloat16* BsH = sm[buf] + 2 * 64 * PITCH;                          \
        __nv_bfloat16* BsL = sm[buf] + 3 * 64 * PITCH;                          \
        uint32_t* dH = (uint32_t*)(AsH + am * PITCH + ak);                      \
        uint32_t* dL = (uint32_t*)(AsL + am * PITCH + ak);                      \
        *(uint4*)dH = awh[0]; *(uint4*)(dH + 4) = awh[1];                       \
        *(uint4*)dL = awl[0]; *(uint4*)(dL + 4) = awl[1];                       \
        STORE_B_UNIT(BsH, BsL, 0, bnn0, bkk0)                                   \
        STORE_B_UNIT(BsH, BsL, 1, bnn1, bkk1)                                   \
    }

    LOAD_REGS(0);
    STORE_SMEM(0);
    if (nch > 1) LOAD_REGS(32);
    __syncthreads();

    for (int ch = 0; ch < nch; ch++) {
        if (ch + 1 < nch) STORE_SMEM((ch + 1) & 1);
        if (ch + 2 < nch) LOAD_REGS((ch + 2) * 32);

        const __nv_bfloat16* AsH = sm[ch & 1];
        const __nv_bfloat16* AsL = AsH + 64 * PITCH;
        const __nv_bfloat16* BsH = AsH + 2 * 64 * PITCH;
        const __nv_bfloat16* BsL = AsH + 3 * 64 * PITCH;

#pragma unroll
        for (int k0 = 0; k0 < 32; k0 += 16) {
            uint32_t ah[2][4], al[2][4];
#pragma unroll
            for (int mt = 0; mt < 2; mt++) {
                int r = wm * 32 + mt * 16;
                const __nv_bfloat16* pH = AsH + k0 + 2 * tg;
                const __nv_bfloat16* pL = AsL + k0 + 2 * tg;
                ah[mt][0] = *(const uint32_t*)(pH + (r + g) * PITCH);
                ah[mt][1] = *(const uint32_t*)(pH + (r + g + 8) * PITCH);
                ah[mt][2] = *(const uint32_t*)(pH + (r + g) * PITCH + 8);
                ah[mt][3] = *(const uint32_t*)(pH + (r + g + 8) * PITCH + 8);
                al[mt][0] = *(const uint32_t*)(pL + (r + g) * PITCH);
                al[mt][1] = *(const uint32_t*)(pL + (r + g + 8) * PITCH);
                al[mt][2] = *(const uint32_t*)(pL + (r + g) * PITCH + 8);
                al[mt][3] = *(const uint32_t*)(pL + (r + g + 8) * PITCH + 8);
            }
#pragma unroll
            for (int nt = 0; nt < 4; nt++) {
                int nb = wn * 32 + nt * 8 + g;
                uint32_t bh0 = *(const uint32_t*)(BsH + nb * PITCH + k0 + 2 * tg);
                uint32_t bh1 = *(const uint32_t*)(BsH + nb * PITCH + k0 + 2 * tg + 8);
                uint32_t bl0 = *(const uint32_t*)(BsL + nb * PITCH + k0 + 2 * tg);
                uint32_t bl1 = *(const uint32_t*)(BsL + nb * PITCH + k0 + 2 * tg + 8);
#pragma unroll
                for (int mt = 0; mt < 2; mt++) {
                    mma16816(acc[mt][nt], ah[mt][0], ah[mt][1], ah[mt][2], ah[mt][3], bh0, bh1);
                    mma16816(acc[mt][nt], al[mt][0], al[mt][1], al[mt][2], al[mt][3], bh0, bh1);
                    mma16816(acc[mt][nt], ah[mt][0], ah[mt][1], ah[mt][2], ah[mt][3], bl0, bl1);
                }
            }
        }
        if (ch + 1 < nch) __syncthreads();
    }

#pragma unroll
    for (int mt = 0; mt < 2; mt++) {
        int r0 = mo + wm * 32 + mt * 16 + g;
        int r1 = r0 + 8;
        float bv0 = bias ? bias[r0] : 0.f;
        float bv1 = bias ? bias[r1] : 0.f;
#pragma unroll
        for (int nt = 0; nt < 4; nt++) {
            int c = no + wn * 32 + nt * 8 + 2 * tg;
            float* d = acc[mt][nt];
            *(float2*)(Yb + (long)r0 * 1024 + c) = make_float2(d[0] + bv0, d[1] + bv0);
            *(float2*)(Yb + (long)r1 * 1024 + c) = make_float2(d[2] + bv1, d[3] + bv1);
        }
    }
#undef LOAD_REGS
#undef STORE_B_UNIT
#undef STORE_SMEM
}

// ---------------------------------------------------------------------------
// Fused BN: stats + apply + bf16 split in ONE kernel. One CTA per row.
// ---------------------------------------------------------------------------
__global__ __launch_bounds__(256) void bn_fused_split(
    const float* __restrict__ X, __nv_bfloat16* __restrict__ H,
    __nv_bfloat16* __restrict__ L,
    const float* __restrict__ g, const float* __restrict__ be,
    long bsX, long bsP, int relu)
{
    int m = blockIdx.x, tid = threadIdx.x;
    float4 v[4];
    float s = 0.f, sq = 0.f;
#pragma unroll
    for (int b = 0; b < 4; b++) {
        v[b] = *(const float4*)(X + b * bsX + (long)m * 1024 + tid * 4);
        s  += v[b].x + v[b].y + v[b].z + v[b].w;
        sq += v[b].x*v[b].x + v[b].y*v[b].y + v[b].z*v[b].z + v[b].w*v[b].w;
    }
#pragma unroll
    for (int o = 16; o; o >>= 1) {
        s  += __shfl_xor_sync(0xffffffffu, s, o);
        sq += __shfl_xor_sync(0xffffffffu, sq, o);
    }
    __shared__ float ps[8], pq[8], bsc[1], bsh[1];
    if ((tid & 31) == 0) { ps[tid >> 5] = s; pq[tid >> 5] = sq; }
    __syncthreads();
    if (tid == 0) {
        s = 0.f; sq = 0.f;
#pragma unroll
        for (int i = 0; i < 8; i++) { s += ps[i]; sq += pq[i]; }
        float mean = s * (1.f / 4096.f);
        float var  = sq * (1.f / 4096.f) - mean * mean;
        float rstd = rsqrtf(var + 1e-5f);
        float sc = g[m] * rstd;
        bsc[0] = sc;
        bsh[0] = be[m] - mean * sc;
    }
    __syncthreads();
    float sc = bsc[0], sh = bsh[0];
#pragma unroll
    for (int b = 0; b < 4; b++) {
        float4 w = v[b];
        w.x = w.x * sc + sh; w.y = w.y * sc + sh;
        w.z = w.z * sc + sh; w.w = w.w * sc + sh;
        if (relu) {
            w.x = fmaxf(w.x, 0.f); w.y = fmaxf(w.y, 0.f);
            w.z = fmaxf(w.z, 0.f); w.w = fmaxf(w.w, 0.f);
        }
        __nv_bfloat16 h[4], l[4];
        splitf(w.x, h[0], l[0]); splitf(w.y, h[1], l[1]);
        splitf(w.z, h[2], l[2]); splitf(w.w, h[3], l[3]);
        long o = (long)b * bsP + (long)m * 1024 + tid * 4;
        *(uint2*)(H + o) = *(uint2*)h;
        *(uint2*)(L + o) = *(uint2*)l;
    }
}

// Final fused BN -> fp32 out (+relu)
__global__ __launch_bounds__(256) void bn_fused_out(
    const float* __restrict__ X, float* __restrict__ Y,
    const float* __restrict__ g, const float* __restrict__ be,
    long bsX, long bsY, int relu)
{
    int m = blockIdx.x, tid = threadIdx.x;
    float4 v[4];
    float s = 0.f, sq = 0.f;
#pragma unroll
    for (int b = 0; b < 4; b++) {
        v[b] = *(const float4*)(X + b * bsX + (long)m * 1024 + tid * 4);
        s  += v[b].x + v[b].y + v[b].z + v[b].w;
        sq += v[b].x*v[b].x + v[b].y*v[b].y + v[b].z*v[b].z + v[b].w*v[b].w;
    }
#pragma unroll
    for (int o = 16; o; o >>= 1) {
        s  += __shfl_xor_sync(0xffffffffu, s, o);
        sq += __shfl_xor_sync(0xffffffffu, sq, o);
    }
    __shared__ float ps[8], pq[8], bsc[1], bsh[1];
    if ((tid & 31) == 0) { ps[tid >> 5] = s; pq[tid >> 5] = sq; }
    __syncthreads();
    if (tid == 0) {
        s = 0.f; sq = 0.f;
#pragma unroll
        for (int i = 0; i < 8; i++) { s += ps[i]; sq += pq[i]; }
        float mean = s * (1.f / 4096.f);
        float var  = sq * (1.f / 4096.f) - mean * mean;
        float rstd = rsqrtf(var + 1e-5f);
        float sc = g[m] * rstd;
        bsc[0] = sc;
        bsh[0] = be[m] - mean * sc;
    }
    __syncthreads();
    float sc = bsc[0], sh = bsh[0];
#pragma unroll
    for (int b = 0; b < 4; b++) {
        float4 w = v[b];
        w.x = w.x * sc + sh; w.y = w.y * sc + sh;
        w.z = w.z * sc + sh; w.w = w.w * sc + sh;
        if (relu) {
            w.x = fmaxf(w.x, 0.f); w.y = fmaxf(w.y, 0.f);
            w.z = fmaxf(w.z, 0.f); w.w = fmaxf(w.w, 0.f);
        }
        *(float4*)(Y + (long)b * bsY + (long)m * 1024 + tid * 4) = w;
    }
}

// ---------------------------------------------------------------------------
// Flash attention — R5 SIMT version, verbatim (known good).
// ---------------------------------------------------------------------------
__global__ __launch_bounds__(256) void attn_kernel(const float* __restrict__ Yq,
                                                   float* __restrict__ O) {
    __shared__ float qs[32 * 16];
    __shared__ float kv[16 * 128];
    __shared__ float Sc[32 * 132];
    __shared__ float fac_s[32], rsum_s[32];

    int b = blockIdx.z;
    int head = blockIdx.y >> 2, t = blockIdx.y & 3;
    int r0 = blockIdx.x * 32;
    const float* Yb = Yq + (long)b * 768 * 1024;
    int tid = threadIdx.x;
    int lane = tid & 31, warp = tid >> 5;
    int ty = tid >> 4, tx = tid & 15;
    int pr = tid & 31, pd = tid >> 5;

    for (int i = tid; i < 512; i += 256) {
        int dd = i >> 5, n = i & 31;
        qs[n * 16 + dd] = Yb[(head * 192 + dd * 4 + t) * 1024 + r0 + n];
    }

    float o0 = 0.f, o1 = 0.f;
    float rm[4] = {-1e30f, -1e30f, -1e30f, -1e30f};
    float rs[4] = {0.f, 0.f, 0.f, 0.f};
    const float sc = 0.25f;

    for (int ch = 0; ch < 8; ch++) {
        __syncthreads();
        for (int i = tid; i < 2048; i += 256) {
            int dd = i >> 7, mm = i & 127;
            kv[i] = Yb[(head * 192 + 64 + dd * 4 + t) * 1024 + ch * 128 + mm];
        }
        __syncthreads();

        {
            float a0[8] = {}, a1[8] = {};
#pragma unroll
            for (int dd = 0; dd < 16; dd++) {
                float q0 = qs[ty * 16 + dd];
                float q1 = qs[(ty + 16) * 16 + dd];
                float4 kA = *(float4*)&kv[dd * 128 + tx * 8];
                float4 kB = *(float4*)&kv[dd * 128 + tx * 8 + 4];
                float kk[8] = {kA.x, kA.y, kA.z, kA.w, kB.x, kB.y, kB.z, kB.w};
#pragma unroll
                for (int j = 0; j < 8; j++) { a0[j] += q0 * kk[j]; a1[j] += q1 * kk[j]; }
            }
            int base0 = ty * 132 + tx * 8;
            int base1 = (ty + 16) * 132 + tx * 8;
            *(float4*)&Sc[base0]     = make_float4(a0[0]*sc, a0[1]*sc, a0[2]*sc, a0[3]*sc);
            *(float4*)&Sc[base0 + 4] = make_float4(a0[4]*sc, a0[5]*sc, a0[6]*sc, a0[7]*sc);
            *(float4*)&Sc[base1]     = make_float4(a1[0]*sc, a1[1]*sc, a1[2]*sc, a1[3]*sc);
            *(float4*)&Sc[base1 + 4] = make_float4(a1[4]*sc, a1[5]*sc, a1[6]*sc, a1[7]*sc);
        }
        __syncthreads();

#pragma unroll
        for (int j = 0; j < 4; j++) {
            int rr = warp + j * 8;
            float* Sr = Sc + rr * 132;
            float v0 = Sr[lane], v1 = Sr[lane + 32], v2 = Sr[lane + 64], v3 = Sr[lane + 96];
            float mx = fmaxf(fmaxf(v0, v1), fmaxf(v2, v3));
#pragma unroll
            for (int o = 16; o; o >>= 1) mx = fmaxf(mx, __shfl_xor_sync(0xffffffffu, mx, o));
            float nm = fmaxf(rm[j], mx);
            float f  = __expf(rm[j] - nm);
            float e0 = __expf(v0 - nm), e1 = __expf(v1 - nm);
            float e2 = __expf(v2 - nm), e3 = __expf(v3 - nm);
            Sr[lane] = e0; Sr[lane + 32] = e1; Sr[lane + 64] = e2; Sr[lane + 96] = e3;
            float sum = e0 + e1 + e2 + e3;
#pragma unroll
            for (int o = 16; o; o >>= 1) sum += __shfl_xor_sync(0xffffffffu, sum, o);
            rs[j] = rs[j] * f + sum;
            rm[j] = nm;
            if (lane == 0) { fac_s[rr] = f; rsum_s[rr] = rs[j]; }
        }
        for (int i = tid; i < 2048; i += 256) {
            int dd = i >> 7, mm = i & 127;
            kv[i] = Yb[(head * 192 + 128 + dd * 4 + t) * 1024 + ch * 128 + mm];
        }
        __syncthreads();

        {
            float f = fac_s[pr];
            float p0 = 0.f, p1 = 0.f;
            float* Sr = Sc + pr * 132;
#pragma unroll
            for (int m4 = 0; m4 < 128; m4 += 4) {
                float4 p  = *(float4*)&Sr[m4];
                float4 w0 = *(float4*)&kv[pd * 128 + m4];
                float4 w1 = *(float4*)&kv[(pd + 8) * 128 + m4];
                p0 += p.x*w0.x + p.y*w0.y + p.z*w0.z + p.w*w0.w;
                p1 += p.x*w1.x + p.y*w1.y + p.z*w1.z + p.w*w1.w;
            }
            o0 = o0 * f + p0;
            o1 = o1 * f + p1;
        }
    }

    float inv = 1.f / rsum_s[pr];
    float* Ob = O + (long)b * 256 * 1024;
    Ob[(head * 64 + pd * 4 + t) * 1024 + r0 + pr]       = o0 * inv;
    Ob[(head * 64 + (pd + 8) * 4 + t) * 1024 + r0 + pr] = o1 * inv;
}

// ---------------------------------------------------------------------------
// PE conv + residual; emits bf16 hi/lo split planes
// ---------------------------------------------------------------------------
__global__ void pe_kernel(const float* __restrict__ I, const float* __restrict__ pw,
                          const float* __restrict__ pb,
                          __nv_bfloat16* __restrict__ H, __nv_bfloat16* __restrict__ L,
                          long bsP) {
    int idx = blockIdx.x * 256 + threadIdx.x;
    if (idx >= 4 * 256 * 1024) return;
    int p = idx & 1023;
    int m = (idx >> 10) & 255;
    int b = idx >> 18;
    int h = p >> 5, w = p & 31;
    int co = m >> 2, t = m & 3, g = co >> 2;
    const float* Ib = I + (long)b * 256 * 1024;
    float acc = Ib[m * 1024 + p] + pb[m];
#pragma unroll
    for (int s = 0; s < 4; s++) {
        float sg = c_sgn[t * 4 + s];
        const float* wc = pw + ((long)c_cmp[t * 4 + s] * 64 + co) * 36;
#pragma unroll
        for (int cil = 0; cil < 4; cil++) {
            const float* in = Ib + ((g * 4 + cil) * 4 + s) * 1024;
            const float* wk = wc + cil * 9;
            float part = 0.f;
#pragma unroll
            for (int kh = 0; kh < 3; kh++) {
                int hh = h + kh - 1;
                if (hh < 0 || hh > 31) continue;
#pragma unroll
                for (int kw = 0; kw < 3; kw++) {
                    int ww = w + kw - 1;
                    if (ww < 0 || ww > 31) continue;
                    part += in[hh * 32 + ww] * wk[kh * 3 + kw];
                }
            }
            acc += sg * part;
        }
    }
    __nv_bfloat16 hh, ll;
    splitf(acc, hh, ll);
    long o = (long)b * bsP + (long)m * 1024 + p;
    H[o] = hh;
    L[o] = ll;
}

// ---------------------------------------------------------------------------
extern "C" void kernel_launch(void* const* d_in, const int* in_sizes, int n_in,
                              void* d_out, int out_size) {
    const float* x      = (const float*)d_in[0];
    const float* cv1_w  = (const float*)d_in[1];
    const float* bn1_g  = (const float*)d_in[2];
    const float* bn1_b  = (const float*)d_in[3];
    const float* qkv_w  = (const float*)d_in[4];
    const float* qkv_b  = (const float*)d_in[5];
    const float* proj_w = (const float*)d_in[6];
    const float* proj_b = (const float*)d_in[7];
    const float* pe_w   = (const float*)d_in[8];
    const float* pe_b   = (const float*)d_in[9];
    const float* ang    = (const float*)d_in[10];
    const float* anb    = (const float*)d_in[11];
    const float* f1w    = (const float*)d_in[12];
    const float* f1g    = (const float*)d_in[13];
    const float* f1b    = (const float*)d_in[14];
    const float* f2w    = (const float*)d_in[15];
    const float* f2g    = (const float*)d_in[16];
    const float* f2b    = (const float*)d_in[17];
    const float* cv2_w  = (const float*)d_in[18];
    const float* bn2_g  = (const float*)d_in[19];
    const float* bn2_b  = (const float*)d_in[20];

    float *buf1, *buf2, *buf3;
    __nv_bfloat16 *xh0, *xl0, *xh1, *xl1, *Wh, *Wl;
    cudaGetSymbolAddress((void**)&buf1, g_buf1);
    cudaGetSymbolAddress((void**)&buf2, g_buf2);
    cudaGetSymbolAddress((void**)&buf3, g_buf3);
    cudaGetSymbolAddress((void**)&xh0,  g_xh0);
    cudaGetSymbolAddress((void**)&xl0,  g_xl0);
    cudaGetSymbolAddress((void**)&xh1,  g_xh1);
    cudaGetSymbolAddress((void**)&xl1,  g_xl1);
    cudaGetSymbolAddress((void**)&Wh,   g_Wh);
    cudaGetSymbolAddress((void**)&Wl,   g_Wl);

    const long S512 = 512L * 1024, S768 = 768L * 1024, S256 = 256L * 1024;

    expand_all_kernel<<<dim3(32, 6), 256>>>(cv1_w, qkv_w, proj_w, f1w, f2w, cv2_w, Wh, Wl);
    split_x_kernel<<<2048, 256>>>(x, xh0, xl0);

    // cv1 + iqbn(+relu) -> P1 (512 rows)
    mma_gemm_kernel<<<dim3(16, 8, 4), 128>>>(Wh + OFF_W1, Wl + OFF_W1, xh0, xl0,
                                             buf1, nullptr, 512, 512, S512, S512);
    bn_fused_split<<<512, 256>>>(buf1, xh1, xl1, bn1_g, bn1_b, S512, S512, 1);

    // qkv
    mma_gemm_kernel<<<dim3(16, 12, 4), 128>>>(Wh + OFF_WQ, Wl + OFF_WQ, xh1, xl1,
                                              buf2, qkv_b, 768, 256, S512, S768);

    // attention (SIMT flash — known good)
    attn_kernel<<<dim3(32, 16, 4), 256>>>(buf2, buf3);

    // pe conv + residual -> P0
    pe_kernel<<<4096, 256>>>(buf3, pe_w, pe_b, xh0, xl0, S512);

    // proj + attn_norm -> P0
    mma_gemm_kernel<<<dim3(16, 4, 4), 128>>>(Wh + OFF_WP, Wl + OFF_WP, xh0, xl0,
                                             buf3, proj_b, 256, 256, S512, S256);
    bn_fused_split<<<256, 256>>>(buf3, xh0, xl0, ang, anb, S256, S512, 0);

    // ffn1 + bn(+relu) -> P0
    mma_gemm_kernel<<<dim3(16, 8, 4), 128>>>(Wh + OFF_F1, Wl + OFF_F1, xh0, xl0,
                                             buf2, nullptr, 512, 256, S512, S512);
    bn_fused_split<<<512, 256>>>(buf2, xh0, xl0, f1g, f1b, S512, S512, 1);

    // ffn2 + bn -> P1 rows 0..255 (rows 256..511 = b from bn1)
    mma_gemm_kernel<<<dim3(16, 4, 4), 128>>>(Wh + OFF_F2, Wl + OFF_F2, xh0, xl0,
                                             buf3, nullptr, 256, 512, S512, S256);
    bn_fused_split<<<256, 256>>>(buf3, xh1, xl1, f2g, f2b, S256, S512, 0);

    // cv2 on concat + bn + relu -> d_out
    mma_gemm_kernel<<<dim3(16, 8, 4), 128>>>(Wh + OFF_C2, Wl + OFF_C2, xh1, xl1,
                                             buf2, nullptr, 512, 512, S512, S512);
    bn_fused_out<<<512, 256>>>(buf2, (float*)d_out, bn2_g, bn2_b, S512, S512, 1);
}

// round 9
// speedup vs baseline: 2.2173x; 1.4786x over previous
#include <cuda_runtime.h>
#include <cuda_bf16.h>
#include <cstdint>

// ---------------------------------------------------------------------------
// Quaternion Hamilton-product tables
// ---------------------------------------------------------------------------
__constant__ int   c_cmp[16] = {0,1,2,3,  1,0,3,2,  2,3,0,1,  3,2,1,0};
__constant__ float c_sgn[16] = {1.f,-1.f,-1.f,-1.f,
                                1.f, 1.f, 1.f,-1.f,
                                1.f,-1.f, 1.f, 1.f,
                                1.f, 1.f,-1.f, 1.f};

// ---------------------------------------------------------------------------
// Scratch (device globals)
// ---------------------------------------------------------------------------
__device__ float g_buf1[4*512*1024];
__device__ float g_buf2[4*768*1024];
__device__ float g_buf3[4*256*1024];
__device__ __align__(16) __nv_bfloat16 g_xh0[4*512*1024];
__device__ __align__(16) __nv_bfloat16 g_xl0[4*512*1024];
__device__ __align__(16) __nv_bfloat16 g_xh1[4*512*1024];
__device__ __align__(16) __nv_bfloat16 g_xl1[4*512*1024];
__device__ __align__(16) __nv_bfloat16 g_Wh[1048576];
__device__ __align__(16) __nv_bfloat16 g_Wl[1048576];

#define OFF_W1 0
#define OFF_WQ (OFF_W1 + 512*512)
#define OFF_WP (OFF_WQ + 768*256)
#define OFF_F1 (OFF_WP + 256*256)
#define OFF_F2 (OFF_F1 + 512*256)
#define OFF_C2 (OFF_F2 + 256*512)

__device__ __forceinline__ void splitf(float v, __nv_bfloat16& h, __nv_bfloat16& l) {
    h = __float2bfloat16(v);
    l = __float2bfloat16(v - __bfloat162float(h));
}
__device__ __forceinline__ void pack2(float x, float y, uint32_t& h, uint32_t& l) {
    __nv_bfloat16 hx, lx, hy, ly;
    splitf(x, hx, lx); splitf(y, hy, ly);
    h = (uint32_t)*(unsigned short*)&hx | ((uint32_t)*(unsigned short*)&hy << 16);
    l = (uint32_t)*(unsigned short*)&lx | ((uint32_t)*(unsigned short*)&ly << 16);
}

// ---------------------------------------------------------------------------
// Fused expansion: quaternion weights -> dense bf16 hi/lo GEMM weights
// ---------------------------------------------------------------------------
__global__ void expand_all_kernel(const float* __restrict__ w0, const float* __restrict__ w1,
                                  const float* __restrict__ w2, const float* __restrict__ w3,
                                  const float* __restrict__ w4, const float* __restrict__ w5,
                                  __nv_bfloat16* __restrict__ Wh, __nv_bfloat16* __restrict__ Wl) {
    const int Couts[6] = {128,192,64,128,64,128};
    const int Cins [6] = {128, 64,64, 64,128,128};
    const int offs [6] = {OFF_W1,OFF_WQ,OFF_WP,OFF_F1,OFF_F2,OFF_C2};
    const float* srcs[6] = {w0,w1,w2,w3,w4,w5};
    int q = blockIdx.y;
    int Cout = Couts[q], Cin = Cins[q];
    const float* w = srcs[q];
    int off = offs[q];
    int total = 16 * Cout * Cin;
    for (int i = blockIdx.x * blockDim.x + threadIdx.x; i < total;
         i += gridDim.x * blockDim.x) {
        int s = i & 3, t = (i >> 2) & 3;
        int rest = i >> 4;
        int ci = rest % Cin, co = rest / Cin;
        float val = c_sgn[t*4 + s] * w[c_cmp[t*4 + s] * Cout * Cin + co * Cin + ci];
        __nv_bfloat16 h, l;
        splitf(val, h, l);
        int idx = off + (co*4 + t) * (4*Cin) + ci*4 + s;
        Wh[idx] = h;
        Wl[idx] = l;
    }
}

// ---------------------------------------------------------------------------
// Plain fp32 -> bf16 hi/lo split (network input x)
// ---------------------------------------------------------------------------
__global__ __launch_bounds__(256) void split_x_kernel(const float* __restrict__ X,
                                                      __nv_bfloat16* __restrict__ H,
                                                      __nv_bfloat16* __restrict__ L) {
    int i = blockIdx.x * 256 + threadIdx.x;
    float4 v = ((const float4*)X)[i];
    __nv_bfloat16 h[4], l[4];
    splitf(v.x, h[0], l[0]); splitf(v.y, h[1], l[1]);
    splitf(v.z, h[2], l[2]); splitf(v.w, h[3], l[3]);
    *(uint2*)(H + (long)i * 4) = *(uint2*)h;
    *(uint2*)(L + (long)i * 4) = *(uint2*)l;
}

// ---------------------------------------------------------------------------
// mma helpers
// ---------------------------------------------------------------------------
__device__ __forceinline__ void mma16816(float* d, uint32_t a0, uint32_t a1,
                                         uint32_t a2, uint32_t a3,
                                         uint32_t b0, uint32_t b1) {
    asm volatile(
        "mma.sync.aligned.m16n8k16.row.col.f32.bf16.bf16.f32 "
        "{%0,%1,%2,%3}, {%4,%5,%6,%7}, {%8,%9}, {%0,%1,%2,%3};"
        : "+f"(d[0]), "+f"(d[1]), "+f"(d[2]), "+f"(d[3])
        : "r"(a0), "r"(a1), "r"(a2), "r"(a3), "r"(b0), "r"(b1));
}
__device__ __forceinline__ uint32_t prmt(uint32_t a, uint32_t b, uint32_t s) {
    uint32_t d;
    asm("prmt.b32 %0,%1,%2,%3;" : "=r"(d) : "r"(a), "r"(b), "r"(s));
    return d;
}

// ---------------------------------------------------------------------------
// HMMA bf16-split GEMM, 64x64 tile, 4 warps, K-chunk 32, DOUBLE-BUFFERED smem.
// (passing R8 version, unchanged)
// ---------------------------------------------------------------------------
#define PITCH 40

__global__ __launch_bounds__(128) void mma_gemm_kernel(
    const __nv_bfloat16* __restrict__ Wh, const __nv_bfloat16* __restrict__ Wl,
    const __nv_bfloat16* __restrict__ Xh, const __nv_bfloat16* __restrict__ Xl,
    float* __restrict__ Y, const float* __restrict__ bias,
    int M, int K, long sX, long sY)
{
    __shared__ __nv_bfloat16 sm[2][4 * 64 * PITCH];

    const int tid = threadIdx.x;
    const int wid = tid >> 5, lane = tid & 31;
    const int wm = wid & 1, wn = wid >> 1;
    const int g = lane >> 2, tg = lane & 3;
    const int mo = blockIdx.y * 64, no = blockIdx.x * 64;
    const __nv_bfloat16* Xhb = Xh + blockIdx.z * sX;
    const __nv_bfloat16* Xlb = Xl + blockIdx.z * sX;
    float* Yb = Y + blockIdx.z * sY;

    const int am = tid >> 1, ak = (tid & 1) * 16;
    const int bnn0 = (tid & 15) * 4,          bkk0 = (tid >> 4) * 2;
    const int bnn1 = ((tid + 128) & 15) * 4,  bkk1 = ((tid + 128) >> 4) * 2;
    float acc[2][4][4] = {};
    const int nch = K >> 5;

    uint4 awh[2], awl[2];
    uint2 bwh[2][2], bwl[2][2];

#define LOAD_REGS(kt)                                                           \
    {                                                                           \
        const __nv_bfloat16* Ah = Wh + (long)(mo + am) * K + (kt) + ak;         \
        const __nv_bfloat16* Al = Wl + (long)(mo + am) * K + (kt) + ak;         \
        awh[0] = *(const uint4*)Ah; awh[1] = *(const uint4*)(Ah + 8);           \
        awl[0] = *(const uint4*)Al; awl[1] = *(const uint4*)(Al + 8);           \
        const __nv_bfloat16* Bh0 = Xhb + (long)((kt) + bkk0) * 1024 + no + bnn0;\
        const __nv_bfloat16* Bl0 = Xlb + (long)((kt) + bkk0) * 1024 + no + bnn0;\
        bwh[0][0] = *(const uint2*)Bh0; bwh[0][1] = *(const uint2*)(Bh0 + 1024);\
        bwl[0][0] = *(const uint2*)Bl0; bwl[0][1] = *(const uint2*)(Bl0 + 1024);\
        const __nv_bfloat16* Bh1 = Xhb + (long)((kt) + bkk1) * 1024 + no + bnn1;\
        const __nv_bfloat16* Bl1 = Xlb + (long)((kt) + bkk1) * 1024 + no + bnn1;\
        bwh[1][0] = *(const uint2*)Bh1; bwh[1][1] = *(const uint2*)(Bh1 + 1024);\
        bwl[1][0] = *(const uint2*)Bl1; bwl[1][1] = *(const uint2*)(Bl1 + 1024);\
    }

#define STORE_B_UNIT(BsH, BsL, it, nn, kk)                                      \
    {                                                                           \
        uint32_t a0 = bwh[it][0].x, a1 = bwh[it][0].y;                          \
        uint32_t b0 = bwh[it][1].x, b1 = bwh[it][1].y;                          \
        *(uint32_t*)((BsH) + ((nn) + 0) * PITCH + (kk)) = prmt(a0, b0, 0x5410); \
        *(uint32_t*)((BsH) + ((nn) + 1) * PITCH + (kk)) = prmt(a0, b0, 0x7632); \
        *(uint32_t*)((BsH) + ((nn) + 2) * PITCH + (kk)) = prmt(a1, b1, 0x5410); \
        *(uint32_t*)((BsH) + ((nn) + 3) * PITCH + (kk)) = prmt(a1, b1, 0x7632); \
        a0 = bwl[it][0].x; a1 = bwl[it][0].y;                                   \
        b0 = bwl[it][1].x; b1 = bwl[it][1].y;                                   \
        *(uint32_t*)((BsL) + ((nn) + 0) * PITCH + (kk)) = prmt(a0, b0, 0x5410); \
        *(uint32_t*)((BsL) + ((nn) + 1) * PITCH + (kk)) = prmt(a0, b0, 0x7632); \
        *(uint32_t*)((BsL) + ((nn) + 2) * PITCH + (kk)) = prmt(a1, b1, 0x5410); \
        *(uint32_t*)((BsL) + ((nn) + 3) * PITCH + (kk)) = prmt(a1, b1, 0x7632); \
    }

#define STORE_SMEM(buf)                                                         \
    {                                                                           \
        __nv_bfloat16* AsH = sm[buf];                                           \
        __nv_bfloat16* AsL = sm[buf] + 64 * PITCH;                              \
        __nv_bfloat16* BsH = sm[buf] + 2 * 64 * PITCH;                          \
        __nv_bfloat16* BsL = sm[buf] + 3 * 64 * PITCH;                          \
        uint32_t* dH = (uint32_t*)(AsH + am * PITCH + ak);                      \
        uint32_t* dL = (uint32_t*)(AsL + am * PITCH + ak);                      \
        *(uint4*)dH = awh[0]; *(uint4*)(dH + 4) = awh[1];                       \
        *(uint4*)dL = awl[0]; *(uint4*)(dL + 4) = awl[1];                       \
        STORE_B_UNIT(BsH, BsL, 0, bnn0, bkk0)                                   \
        STORE_B_UNIT(BsH, BsL, 1, bnn1, bkk1)                                   \
    }

    LOAD_REGS(0);
    STORE_SMEM(0);
    if (nch > 1) LOAD_REGS(32);
    __syncthreads();

    for (int ch = 0; ch < nch; ch++) {
        if (ch + 1 < nch) STORE_SMEM((ch + 1) & 1);
        if (ch + 2 < nch) LOAD_REGS((ch + 2) * 32);

        const __nv_bfloat16* AsH = sm[ch & 1];
        const __nv_bfloat16* AsL = AsH + 64 * PITCH;
        const __nv_bfloat16* BsH = AsH + 2 * 64 * PITCH;
        const __nv_bfloat16* BsL = AsH + 3 * 64 * PITCH;

#pragma unroll
        for (int k0 = 0; k0 < 32; k0 += 16) {
            uint32_t ah[2][4], al[2][4];
#pragma unroll
            for (int mt = 0; mt < 2; mt++) {
                int r = wm * 32 + mt * 16;
                const __nv_bfloat16* pH = AsH + k0 + 2 * tg;
                const __nv_bfloat16* pL = AsL + k0 + 2 * tg;
                ah[mt][0] = *(const uint32_t*)(pH + (r + g) * PITCH);
                ah[mt][1] = *(const uint32_t*)(pH + (r + g + 8) * PITCH);
                ah[mt][2] = *(const uint32_t*)(pH + (r + g) * PITCH + 8);
                ah[mt][3] = *(const uint32_t*)(pH + (r + g + 8) * PITCH + 8);
                al[mt][0] = *(const uint32_t*)(pL + (r + g) * PITCH);
                al[mt][1] = *(const uint32_t*)(pL + (r + g + 8) * PITCH);
                al[mt][2] = *(const uint32_t*)(pL + (r + g) * PITCH + 8);
                al[mt][3] = *(const uint32_t*)(pL + (r + g + 8) * PITCH + 8);
            }
#pragma unroll
            for (int nt = 0; nt < 4; nt++) {
                int nb = wn * 32 + nt * 8 + g;
                uint32_t bh0 = *(const uint32_t*)(BsH + nb * PITCH + k0 + 2 * tg);
                uint32_t bh1 = *(const uint32_t*)(BsH + nb * PITCH + k0 + 2 * tg + 8);
                uint32_t bl0 = *(const uint32_t*)(BsL + nb * PITCH + k0 + 2 * tg);
                uint32_t bl1 = *(const uint32_t*)(BsL + nb * PITCH + k0 + 2 * tg + 8);
#pragma unroll
                for (int mt = 0; mt < 2; mt++) {
                    mma16816(acc[mt][nt], ah[mt][0], ah[mt][1], ah[mt][2], ah[mt][3], bh0, bh1);
                    mma16816(acc[mt][nt], al[mt][0], al[mt][1], al[mt][2], al[mt][3], bh0, bh1);
                    mma16816(acc[mt][nt], ah[mt][0], ah[mt][1], ah[mt][2], ah[mt][3], bl0, bl1);
                }
            }
        }
        if (ch + 1 < nch) __syncthreads();
    }

#pragma unroll
    for (int mt = 0; mt < 2; mt++) {
        int r0 = mo + wm * 32 + mt * 16 + g;
        int r1 = r0 + 8;
        float bv0 = bias ? bias[r0] : 0.f;
        float bv1 = bias ? bias[r1] : 0.f;
#pragma unroll
        for (int nt = 0; nt < 4; nt++) {
            int c = no + wn * 32 + nt * 8 + 2 * tg;
            float* d = acc[mt][nt];
            *(float2*)(Yb + (long)r0 * 1024 + c) = make_float2(d[0] + bv0, d[1] + bv0);
            *(float2*)(Yb + (long)r1 * 1024 + c) = make_float2(d[2] + bv1, d[3] + bv1);
        }
    }
#undef LOAD_REGS
#undef STORE_B_UNIT
#undef STORE_SMEM
}

// ---------------------------------------------------------------------------
// Fused BN: stats + apply + bf16 split (passing R8 version, unchanged)
// ---------------------------------------------------------------------------
__global__ __launch_bounds__(256) void bn_fused_split(
    const float* __restrict__ X, __nv_bfloat16* __restrict__ H,
    __nv_bfloat16* __restrict__ L,
    const float* __restrict__ g, const float* __restrict__ be,
    long bsX, long bsP, int relu)
{
    int m = blockIdx.x, tid = threadIdx.x;
    float4 v[4];
    float s = 0.f, sq = 0.f;
#pragma unroll
    for (int b = 0; b < 4; b++) {
        v[b] = *(const float4*)(X + b * bsX + (long)m * 1024 + tid * 4);
        s  += v[b].x + v[b].y + v[b].z + v[b].w;
        sq += v[b].x*v[b].x + v[b].y*v[b].y + v[b].z*v[b].z + v[b].w*v[b].w;
    }
#pragma unroll
    for (int o = 16; o; o >>= 1) {
        s  += __shfl_xor_sync(0xffffffffu, s, o);
        sq += __shfl_xor_sync(0xffffffffu, sq, o);
    }
    __shared__ float ps[8], pq[8], bsc[1], bsh[1];
    if ((tid & 31) == 0) { ps[tid >> 5] = s; pq[tid >> 5] = sq; }
    __syncthreads();
    if (tid == 0) {
        s = 0.f; sq = 0.f;
#pragma unroll
        for (int i = 0; i < 8; i++) { s += ps[i]; sq += pq[i]; }
        float mean = s * (1.f / 4096.f);
        float var  = sq * (1.f / 4096.f) - mean * mean;
        float rstd = rsqrtf(var + 1e-5f);
        float sc = g[m] * rstd;
        bsc[0] = sc;
        bsh[0] = be[m] - mean * sc;
    }
    __syncthreads();
    float sc = bsc[0], sh = bsh[0];
#pragma unroll
    for (int b = 0; b < 4; b++) {
        float4 w = v[b];
        w.x = w.x * sc + sh; w.y = w.y * sc + sh;
        w.z = w.z * sc + sh; w.w = w.w * sc + sh;
        if (relu) {
            w.x = fmaxf(w.x, 0.f); w.y = fmaxf(w.y, 0.f);
            w.z = fmaxf(w.z, 0.f); w.w = fmaxf(w.w, 0.f);
        }
        __nv_bfloat16 h[4], l[4];
        splitf(w.x, h[0], l[0]); splitf(w.y, h[1], l[1]);
        splitf(w.z, h[2], l[2]); splitf(w.w, h[3], l[3]);
        long o = (long)b * bsP + (long)m * 1024 + tid * 4;
        *(uint2*)(H + o) = *(uint2*)h;
        *(uint2*)(L + o) = *(uint2*)l;
    }
}

__global__ __launch_bounds__(256) void bn_fused_out(
    const float* __restrict__ X, float* __restrict__ Y,
    const float* __restrict__ g, const float* __restrict__ be,
    long bsX, long bsY, int relu)
{
    int m = blockIdx.x, tid = threadIdx.x;
    float4 v[4];
    float s = 0.f, sq = 0.f;
#pragma unroll
    for (int b = 0; b < 4; b++) {
        v[b] = *(const float4*)(X + b * bsX + (long)m * 1024 + tid * 4);
        s  += v[b].x + v[b].y + v[b].z + v[b].w;
        sq += v[b].x*v[b].x + v[b].y*v[b].y + v[b].z*v[b].z + v[b].w*v[b].w;
    }
#pragma unroll
    for (int o = 16; o; o >>= 1) {
        s  += __shfl_xor_sync(0xffffffffu, s, o);
        sq += __shfl_xor_sync(0xffffffffu, sq, o);
    }
    __shared__ float ps[8], pq[8], bsc[1], bsh[1];
    if ((tid & 31) == 0) { ps[tid >> 5] = s; pq[tid >> 5] = sq; }
    __syncthreads();
    if (tid == 0) {
        s = 0.f; sq = 0.f;
#pragma unroll
        for (int i = 0; i < 8; i++) { s += ps[i]; sq += pq[i]; }
        float mean = s * (1.f / 4096.f);
        float var  = sq * (1.f / 4096.f) - mean * mean;
        float rstd = rsqrtf(var + 1e-5f);
        float sc = g[m] * rstd;
        bsc[0] = sc;
        bsh[0] = be[m] - mean * sc;
    }
    __syncthreads();
    float sc = bsc[0], sh = bsh[0];
#pragma unroll
    for (int b = 0; b < 4; b++) {
        float4 w = v[b];
        w.x = w.x * sc + sh; w.y = w.y * sc + sh;
        w.z = w.z * sc + sh; w.w = w.w * sc + sh;
        if (relu) {
            w.x = fmaxf(w.x, 0.f); w.y = fmaxf(w.y, 0.f);
            w.z = fmaxf(w.z, 0.f); w.w = fmaxf(w.w, 0.f);
        }
        *(float4*)(Y + (long)b * bsY + (long)m * 1024 + tid * 4) = w;
    }
}

// ---------------------------------------------------------------------------
// Tensor-core flash attention. CTA = 32 queries x 1024 keys for one
// (batch, head, component) slice. 8 warps: wm in {0,1} (16-query halves),
// wn in {0..3} (32-key slices per 128-key chunk). bf16 3-term splits,
// fp32 accum, online softmax, cross-warp O reduce.
// ---------------------------------------------------------------------------
#define QP 24
#define KP 24
#define VP 136

__global__ __launch_bounds__(256) void attn_kernel(const float* __restrict__ Yq,
                                                   float* __restrict__ O) {
    __shared__ __nv_bfloat16 QH[32*QP], QL[32*QP];
    __shared__ __nv_bfloat16 KH[128*KP], KL[128*KP];
    __shared__ __nv_bfloat16 VH[16*VP], VL[16*VP];
    __shared__ float redmax[4][32], redsum[4][32];
    __shared__ float Of[4][2][16][17];
    __shared__ float rsinv[32];

    int b = blockIdx.z, head = blockIdx.y >> 2, t = blockIdx.y & 3;
    int r0 = blockIdx.x * 32;
    const float* Yb = Yq + (long)b * 768 * 1024;
    int tid = threadIdx.x, lane = tid & 31, wid = tid >> 5;
    int wm = wid & 1, wn = wid >> 1;
    int g = lane >> 2, tg = lane & 3;

    // stage Q (32 q x 16 d), transposed + split
    for (int i = tid; i < 512; i += 256) {
        int dd = i >> 5, q = i & 31;
        float v = Yb[(head * 192 + dd * 4 + t) * 1024 + r0 + q];
        __nv_bfloat16 h, l; splitf(v, h, l);
        QH[q * QP + dd] = h;
        QL[q * QP + dd] = l;
    }
    __syncthreads();

    uint32_t qh[4], ql[4];
    {
        int r = wm * 16 + g;
        qh[0] = *(uint32_t*)&QH[r * QP + 2*tg];
        qh[1] = *(uint32_t*)&QH[(r + 8) * QP + 2*tg];
        qh[2] = *(uint32_t*)&QH[r * QP + 2*tg + 8];
        qh[3] = *(uint32_t*)&QH[(r + 8) * QP + 2*tg + 8];
        ql[0] = *(uint32_t*)&QL[r * QP + 2*tg];
        ql[1] = *(uint32_t*)&QL[(r + 8) * QP + 2*tg];
        ql[2] = *(uint32_t*)&QL[r * QP + 2*tg + 8];
        ql[3] = *(uint32_t*)&QL[(r + 8) * QP + 2*tg + 8];
    }

    float od[2][4] = {};
    float rm_lo = -1e30f, rm_hi = -1e30f, rs_lo = 0.f, rs_hi = 0.f;
    const float sc = 0.25f;
    const int rlo = wm * 16 + g, rhi = rlo + 8;

    for (int ch = 0; ch < 8; ch++) {
        __syncthreads();   // prior chunk's K/V reads done
        for (int i = tid; i < 2048; i += 256) {
            int dd = i >> 7, key = i & 127;
            float kval = Yb[(head * 192 + 64 + dd * 4 + t) * 1024 + ch * 128 + key];
            __nv_bfloat16 h, l; splitf(kval, h, l);
            KH[key * KP + dd] = h; KL[key * KP + dd] = l;
            float vval = Yb[(head * 192 + 128 + dd * 4 + t) * 1024 + ch * 128 + key];
            splitf(vval, h, l);
            VH[dd * VP + key] = h; VL[dd * VP + key] = l;
        }
        __syncthreads();

        // ---- S = Q K^T (warp's 16 x 32 block) ----
        float sacc[4][4] = {};
#pragma unroll
        for (int nt = 0; nt < 4; nt++) {
            int nb = wn * 32 + nt * 8 + g;
            uint32_t kb0 = *(uint32_t*)&KH[nb * KP + 2*tg];
            uint32_t kb1 = *(uint32_t*)&KH[nb * KP + 2*tg + 8];
            uint32_t kc0 = *(uint32_t*)&KL[nb * KP + 2*tg];
            uint32_t kc1 = *(uint32_t*)&KL[nb * KP + 2*tg + 8];
            mma16816(sacc[nt], qh[0], qh[1], qh[2], qh[3], kb0, kb1);
            mma16816(sacc[nt], ql[0], ql[1], ql[2], ql[3], kb0, kb1);
            mma16816(sacc[nt], qh[0], qh[1], qh[2], qh[3], kc0, kc1);
        }
        float mx_lo = -1e30f, mx_hi = -1e30f;
#pragma unroll
        for (int nt = 0; nt < 4; nt++) {
            sacc[nt][0] *= sc; sacc[nt][1] *= sc;
            sacc[nt][2] *= sc; sacc[nt][3] *= sc;
            mx_lo = fmaxf(mx_lo, fmaxf(sacc[nt][0], sacc[nt][1]));
            mx_hi = fmaxf(mx_hi, fmaxf(sacc[nt][2], sacc[nt][3]));
        }
        mx_lo = fmaxf(mx_lo, __shfl_xor_sync(0xffffffffu, mx_lo, 1));
        mx_lo = fmaxf(mx_lo, __shfl_xor_sync(0xffffffffu, mx_lo, 2));
        mx_hi = fmaxf(mx_hi, __shfl_xor_sync(0xffffffffu, mx_hi, 1));
        mx_hi = fmaxf(mx_hi, __shfl_xor_sync(0xffffffffu, mx_hi, 2));
        if (tg == 0) { redmax[wn][rlo] = mx_lo; redmax[wn][rhi] = mx_hi; }
        __syncthreads();

        float cm_lo = fmaxf(fmaxf(redmax[0][rlo], redmax[1][rlo]),
                            fmaxf(redmax[2][rlo], redmax[3][rlo]));
        float cm_hi = fmaxf(fmaxf(redmax[0][rhi], redmax[1][rhi]),
                            fmaxf(redmax[2][rhi], redmax[3][rhi]));
        float nm_lo = fmaxf(rm_lo, cm_lo), f_lo = __expf(rm_lo - nm_lo);
        float nm_hi = fmaxf(rm_hi, cm_hi), f_hi = __expf(rm_hi - nm_hi);
        rm_lo = nm_lo; rm_hi = nm_hi;

        float e[4][4];
        float sum_lo = 0.f, sum_hi = 0.f;
#pragma unroll
        for (int nt = 0; nt < 4; nt++) {
            e[nt][0] = __expf(sacc[nt][0] - nm_lo);
            e[nt][1] = __expf(sacc[nt][1] - nm_lo);
            e[nt][2] = __expf(sacc[nt][2] - nm_hi);
            e[nt][3] = __expf(sacc[nt][3] - nm_hi);
            sum_lo += e[nt][0] + e[nt][1];
            sum_hi += e[nt][2] + e[nt][3];
        }
        sum_lo += __shfl_xor_sync(0xffffffffu, sum_lo, 1);
        sum_lo += __shfl_xor_sync(0xffffffffu, sum_lo, 2);
        sum_hi += __shfl_xor_sync(0xffffffffu, sum_hi, 1);
        sum_hi += __shfl_xor_sync(0xffffffffu, sum_hi, 2);
        if (tg == 0) { redsum[wn][rlo] = sum_lo; redsum[wn][rhi] = sum_hi; }
        __syncthreads();

        rs_lo = rs_lo * f_lo + redsum[0][rlo] + redsum[1][rlo] + redsum[2][rlo] + redsum[3][rlo];
        rs_hi = rs_hi * f_hi + redsum[0][rhi] + redsum[1][rhi] + redsum[2][rhi] + redsum[3][rhi];

        // ---- rescale O, pack P (C-frag pairs == A-frag regs), PV mmas ----
#pragma unroll
        for (int dn = 0; dn < 2; dn++) {
            od[dn][0] *= f_lo; od[dn][1] *= f_lo;
            od[dn][2] *= f_hi; od[dn][3] *= f_hi;
        }
        uint32_t ph[2][4], pl[2][4];
#pragma unroll
        for (int ks = 0; ks < 2; ks++) {
            pack2(e[2*ks][0],   e[2*ks][1],   ph[ks][0], pl[ks][0]);
            pack2(e[2*ks][2],   e[2*ks][3],   ph[ks][1], pl[ks][1]);
            pack2(e[2*ks+1][0], e[2*ks+1][1], ph[ks][2], pl[ks][2]);
            pack2(e[2*ks+1][2], e[2*ks+1][3], ph[ks][3], pl[ks][3]);
        }
#pragma unroll
        for (int ks = 0; ks < 2; ks++) {
#pragma unroll
            for (int dn = 0; dn < 2; dn++) {
                int vrow = dn * 8 + g;
                int kk = wn * 32 + ks * 16;
                uint32_t vb0 = *(uint32_t*)&VH[vrow * VP + kk + 2*tg];
                uint32_t vb1 = *(uint32_t*)&VH[vrow * VP + kk + 2*tg + 8];
                uint32_t vc0 = *(uint32_t*)&VL[vrow * VP + kk + 2*tg];
                uint32_t vc1 = *(uint32_t*)&VL[vrow * VP + kk + 2*tg + 8];
                mma16816(od[dn], ph[ks][0], ph[ks][1], ph[ks][2], ph[ks][3], vb0, vb1);
                mma16816(od[dn], pl[ks][0], pl[ks][1], pl[ks][2], pl[ks][3], vb0, vb1);
                mma16816(od[dn], ph[ks][0], ph[ks][1], ph[ks][2], ph[ks][3], vc0, vc1);
            }
        }
    }

    // ---- cross-warp O reduce + transposed output ----
#pragma unroll
    for (int dn = 0; dn < 2; dn++) {
        Of[wn][wm][g][dn*8 + 2*tg]       = od[dn][0];
        Of[wn][wm][g][dn*8 + 2*tg + 1]   = od[dn][1];
        Of[wn][wm][g+8][dn*8 + 2*tg]     = od[dn][2];
        Of[wn][wm][g+8][dn*8 + 2*tg + 1] = od[dn][3];
    }
    if (tg == 0 && wn == 0) {
        rsinv[rlo] = 1.f / rs_lo;
        rsinv[rhi] = 1.f / rs_hi;
    }
    __syncthreads();

    int q = tid & 31, dd = tid >> 5;
    float inv = rsinv[q];
    int qm = q >> 4, qr = q & 15;
    float* Ob = O + (long)b * 256 * 1024;
#pragma unroll
    for (int h2 = 0; h2 < 2; h2++) {
        int D = dd + h2 * 8;
        float v = (Of[0][qm][qr][D] + Of[1][qm][qr][D] +
                   Of[2][qm][qr][D] + Of[3][qm][qr][D]) * inv;
        Ob[(head * 64 + D * 4 + t) * 1024 + r0 + q] = v;
    }
}

// ---------------------------------------------------------------------------
// PE conv + residual; emits bf16 hi/lo split planes
// ---------------------------------------------------------------------------
__global__ void pe_kernel(const float* __restrict__ I, const float* __restrict__ pw,
                          const float* __restrict__ pb,
                          __nv_bfloat16* __restrict__ H, __nv_bfloat16* __restrict__ L,
                          long bsP) {
    int idx = blockIdx.x * 256 + threadIdx.x;
    if (idx >= 4 * 256 * 1024) return;
    int p = idx & 1023;
    int m = (idx >> 10) & 255;
    int b = idx >> 18;
    int h = p >> 5, w = p & 31;
    int co = m >> 2, t = m & 3, g = co >> 2;
    const float* Ib = I + (long)b * 256 * 1024;
    float acc = Ib[m * 1024 + p] + pb[m];
#pragma unroll
    for (int s = 0; s < 4; s++) {
        float sg = c_sgn[t * 4 + s];
        const float* wc = pw + ((long)c_cmp[t * 4 + s] * 64 + co) * 36;
#pragma unroll
        for (int cil = 0; cil < 4; cil++) {
            const float* in = Ib + ((g * 4 + cil) * 4 + s) * 1024;
            const float* wk = wc + cil * 9;
            float part = 0.f;
#pragma unroll
            for (int kh = 0; kh < 3; kh++) {
                int hh = h + kh - 1;
                if (hh < 0 || hh > 31) continue;
#pragma unroll
                for (int kw = 0; kw < 3; kw++) {
                    int ww = w + kw - 1;
                    if (ww < 0 || ww > 31) continue;
                    part += in[hh * 32 + ww] * wk[kh * 3 + kw];
                }
            }
            acc += sg * part;
        }
    }
    __nv_bfloat16 hh, ll;
    splitf(acc, hh, ll);
    long o = (long)b * bsP + (long)m * 1024 + p;
    H[o] = hh;
    L[o] = ll;
}

// ---------------------------------------------------------------------------
extern "C" void kernel_launch(void* const* d_in, const int* in_sizes, int n_in,
                              void* d_out, int out_size) {
    const float* x      = (const float*)d_in[0];
    const float* cv1_w  = (const float*)d_in[1];
    const float* bn1_g  = (const float*)d_in[2];
    const float* bn1_b  = (const float*)d_in[3];
    const float* qkv_w  = (const float*)d_in[4];
    const float* qkv_b  = (const float*)d_in[5];
    const float* proj_w = (const float*)d_in[6];
    const float* proj_b = (const float*)d_in[7];
    const float* pe_w   = (const float*)d_in[8];
    const float* pe_b   = (const float*)d_in[9];
    const float* ang    = (const float*)d_in[10];
    const float* anb    = (const float*)d_in[11];
    const float* f1w    = (const float*)d_in[12];
    const float* f1g    = (const float*)d_in[13];
    const float* f1b    = (const float*)d_in[14];
    const float* f2w    = (const float*)d_in[15];
    const float* f2g    = (const float*)d_in[16];
    const float* f2b    = (const float*)d_in[17];
    const float* cv2_w  = (const float*)d_in[18];
    const float* bn2_g  = (const float*)d_in[19];
    const float* bn2_b  = (const float*)d_in[20];

    float *buf1, *buf2, *buf3;
    __nv_bfloat16 *xh0, *xl0, *xh1, *xl1, *Wh, *Wl;
    cudaGetSymbolAddress((void**)&buf1, g_buf1);
    cudaGetSymbolAddress((void**)&buf2, g_buf2);
    cudaGetSymbolAddress((void**)&buf3, g_buf3);
    cudaGetSymbolAddress((void**)&xh0,  g_xh0);
    cudaGetSymbolAddress((void**)&xl0,  g_xl0);
    cudaGetSymbolAddress((void**)&xh1,  g_xh1);
    cudaGetSymbolAddress((void**)&xl1,  g_xl1);
    cudaGetSymbolAddress((void**)&Wh,   g_Wh);
    cudaGetSymbolAddress((void**)&Wl,   g_Wl);

    const long S512 = 512L * 1024, S768 = 768L * 1024, S256 = 256L * 1024;

    expand_all_kernel<<<dim3(32, 6), 256>>>(cv1_w, qkv_w, proj_w, f1w, f2w, cv2_w, Wh, Wl);
    split_x_kernel<<<2048, 256>>>(x, xh0, xl0);

    // cv1 + iqbn(+relu) -> P1 (512 rows)
    mma_gemm_kernel<<<dim3(16, 8, 4), 128>>>(Wh + OFF_W1, Wl + OFF_W1, xh0, xl0,
                                             buf1, nullptr, 512, 512, S512, S512);
    bn_fused_split<<<512, 256>>>(buf1, xh1, xl1, bn1_g, bn1_b, S512, S512, 1);

    // qkv
    mma_gemm_kernel<<<dim3(16, 12, 4), 128>>>(Wh + OFF_WQ, Wl + OFF_WQ, xh1, xl1,
                                              buf2, qkv_b, 768, 256, S512, S768);

    // attention (tensor cores — single change this round)
    attn_kernel<<<dim3(32, 16, 4), 256>>>(buf2, buf3);

    // pe conv + residual -> P0
    pe_kernel<<<4096, 256>>>(buf3, pe_w, pe_b, xh0, xl0, S512);

    // proj + attn_norm -> P0
    mma_gemm_kernel<<<dim3(16, 4, 4), 128>>>(Wh + OFF_WP, Wl + OFF_WP, xh0, xl0,
                                             buf3, proj_b, 256, 256, S512, S256);
    bn_fused_split<<<256, 256>>>(buf3, xh0, xl0, ang, anb, S256, S512, 0);

    // ffn1 + bn(+relu) -> P0
    mma_gemm_kernel<<<dim3(16, 8, 4), 128>>>(Wh + OFF_F1, Wl + OFF_F1, xh0, xl0,
                                             buf2, nullptr, 512, 256, S512, S512);
    bn_fused_split<<<512, 256>>>(buf2, xh0, xl0, f1g, f1b, S512, S512, 1);

    // ffn2 + bn -> P1 rows 0..255 (rows 256..511 = b from bn1)
    mma_gemm_kernel<<<dim3(16, 4, 4), 128>>>(Wh + OFF_F2, Wl + OFF_F2, xh0, xl0,
                                             buf3, nullptr, 256, 512, S512, S256);
    bn_fused_split<<<256, 256>>>(buf3, xh1, xl1, f2g, f2b, S256, S512, 0);

    // cv2 on concat + bn + relu -> d_out
    mma_gemm_kernel<<<dim3(16, 8, 4), 128>>>(Wh + OFF_C2, Wl + OFF_C2, xh1, xl1,
                                             buf2, nullptr, 512, 512, S512, S512);
    bn_fused_out<<<512, 256>>>(buf2, (float*)d_out, bn2_g, bn2_b, S512, S512, 1);
}

// round 10
// speedup vs baseline: 2.8812x; 1.2994x over previous
#include <cuda_runtime.h>
#include <cuda_bf16.h>
#include <cstdint>

// ---------------------------------------------------------------------------
// Quaternion Hamilton-product tables
// ---------------------------------------------------------------------------
__constant__ int   c_cmp[16] = {0,1,2,3,  1,0,3,2,  2,3,0,1,  3,2,1,0};
__constant__ float c_sgn[16] = {1.f,-1.f,-1.f,-1.f,
                                1.f, 1.f, 1.f,-1.f,
                                1.f,-1.f, 1.f, 1.f,
                                1.f, 1.f,-1.f, 1.f};

// ---------------------------------------------------------------------------
// Scratch (device globals)
// ---------------------------------------------------------------------------
__device__ float g_buf1[4*512*1024];
__device__ float g_buf2[4*768*1024];
__device__ float g_buf3[4*256*1024];
__device__ __align__(16) __nv_bfloat16 g_xh0[4*512*1024];
__device__ __align__(16) __nv_bfloat16 g_xl0[4*512*1024];
__device__ __align__(16) __nv_bfloat16 g_xh1[4*512*1024];
__device__ __align__(16) __nv_bfloat16 g_xl1[4*512*1024];
__device__ __align__(16) __nv_bfloat16 g_Wh[1048576];
__device__ __align__(16) __nv_bfloat16 g_Wl[1048576];

#define OFF_W1 0
#define OFF_WQ (OFF_W1 + 512*512)
#define OFF_WP (OFF_WQ + 768*256)
#define OFF_F1 (OFF_WP + 256*256)
#define OFF_F2 (OFF_F1 + 512*256)
#define OFF_C2 (OFF_F2 + 256*512)

__device__ __forceinline__ void splitf(float v, __nv_bfloat16& h, __nv_bfloat16& l) {
    h = __float2bfloat16(v);
    l = __float2bfloat16(v - __bfloat162float(h));
}
__device__ __forceinline__ void pack2(float x, float y, uint32_t& h, uint32_t& l) {
    __nv_bfloat16 hx, lx, hy, ly;
    splitf(x, hx, lx); splitf(y, hy, ly);
    h = (uint32_t)*(unsigned short*)&hx | ((uint32_t)*(unsigned short*)&hy << 16);
    l = (uint32_t)*(unsigned short*)&lx | ((uint32_t)*(unsigned short*)&ly << 16);
}

// ---------------------------------------------------------------------------
// Fused expansion: quaternion weights -> dense bf16 hi/lo GEMM weights
// ---------------------------------------------------------------------------
__global__ void expand_all_kernel(const float* __restrict__ w0, const float* __restrict__ w1,
                                  const float* __restrict__ w2, const float* __restrict__ w3,
                                  const float* __restrict__ w4, const float* __restrict__ w5,
                                  __nv_bfloat16* __restrict__ Wh, __nv_bfloat16* __restrict__ Wl) {
    const int Couts[6] = {128,192,64,128,64,128};
    const int Cins [6] = {128, 64,64, 64,128,128};
    const int offs [6] = {OFF_W1,OFF_WQ,OFF_WP,OFF_F1,OFF_F2,OFF_C2};
    const float* srcs[6] = {w0,w1,w2,w3,w4,w5};
    int q = blockIdx.y;
    int Cout = Couts[q], Cin = Cins[q];
    const float* w = srcs[q];
    int off = offs[q];
    int total = 16 * Cout * Cin;
    for (int i = blockIdx.x * blockDim.x + threadIdx.x; i < total;
         i += gridDim.x * blockDim.x) {
        int s = i & 3, t = (i >> 2) & 3;
        int rest = i >> 4;
        int ci = rest % Cin, co = rest / Cin;
        float val = c_sgn[t*4 + s] * w[c_cmp[t*4 + s] * Cout * Cin + co * Cin + ci];
        __nv_bfloat16 h, l;
        splitf(val, h, l);
        int idx = off + (co*4 + t) * (4*Cin) + ci*4 + s;
        Wh[idx] = h;
        Wl[idx] = l;
    }
}

// ---------------------------------------------------------------------------
// Plain fp32 -> bf16 hi/lo split (network input x)
// ---------------------------------------------------------------------------
__global__ __launch_bounds__(256) void split_x_kernel(const float* __restrict__ X,
                                                      __nv_bfloat16* __restrict__ H,
                                                      __nv_bfloat16* __restrict__ L) {
    int i = blockIdx.x * 256 + threadIdx.x;
    float4 v = ((const float4*)X)[i];
    __nv_bfloat16 h[4], l[4];
    splitf(v.x, h[0], l[0]); splitf(v.y, h[1], l[1]);
    splitf(v.z, h[2], l[2]); splitf(v.w, h[3], l[3]);
    *(uint2*)(H + (long)i * 4) = *(uint2*)h;
    *(uint2*)(L + (long)i * 4) = *(uint2*)l;
}

// ---------------------------------------------------------------------------
// mma / ldmatrix helpers
// ---------------------------------------------------------------------------
__device__ __forceinline__ void mma16816(float* d, uint32_t a0, uint32_t a1,
                                         uint32_t a2, uint32_t a3,
                                         uint32_t b0, uint32_t b1) {
    asm volatile(
        "mma.sync.aligned.m16n8k16.row.col.f32.bf16.bf16.f32 "
        "{%0,%1,%2,%3}, {%4,%5,%6,%7}, {%8,%9}, {%0,%1,%2,%3};"
        : "+f"(d[0]), "+f"(d[1]), "+f"(d[2]), "+f"(d[3])
        : "r"(a0), "r"(a1), "r"(a2), "r"(a3), "r"(b0), "r"(b1));
}
__device__ __forceinline__ void ldsm4(uint32_t& r0, uint32_t& r1, uint32_t& r2,
                                      uint32_t& r3, uint32_t addr) {
    asm volatile("ldmatrix.sync.aligned.m8n8.x4.shared.b16 {%0,%1,%2,%3}, [%4];"
                 : "=r"(r0), "=r"(r1), "=r"(r2), "=r"(r3) : "r"(addr));
}
__device__ __forceinline__ void ldsm4t(uint32_t& r0, uint32_t& r1, uint32_t& r2,
                                       uint32_t& r3, uint32_t addr) {
    asm volatile("ldmatrix.sync.aligned.m8n8.x4.trans.shared.b16 {%0,%1,%2,%3}, [%4];"
                 : "=r"(r0), "=r"(r1), "=r"(r2), "=r"(r3) : "r"(addr));
}

// ---------------------------------------------------------------------------
// HMMA bf16-split GEMM. CTA tile 64m x 128n, 4 warps (warp tile 32x64),
// K-chunk 32, double-buffered dynamic smem.
// A smem: [m][k] pitch 40 (ldmatrix non-trans, conflict-free).
// B smem: [k][n] pitch 136 (direct uint2 copy from gmem, conflict-free
//         stores; ldmatrix.trans conflict-free loads). No prmt.
// ---------------------------------------------------------------------------
#define APITCH 40
#define BPITCH 136
#define A_PLANE (64*APITCH)                 // 2560 units
#define B_PLANE (32*BPITCH)                 // 4352 units
#define GBUF (2*A_PLANE + 2*B_PLANE)        // 13824 units
#define GEMM_SMEM (2*GBUF*2)                // 55296 bytes

__global__ __launch_bounds__(128) void mma_gemm_kernel(
    const __nv_bfloat16* __restrict__ Wh, const __nv_bfloat16* __restrict__ Wl,
    const __nv_bfloat16* __restrict__ Xh, const __nv_bfloat16* __restrict__ Xl,
    float* __restrict__ Y, const float* __restrict__ bias,
    int M, int K, long sX, long sY)
{
    extern __shared__ __nv_bfloat16 smd[];
    const uint32_t smem_base = (uint32_t)__cvta_generic_to_shared(smd);

    const int tid = threadIdx.x;
    const int wid = tid >> 5, lane = tid & 31;
    const int wm = wid & 1, wn = wid >> 1;
    const int g = lane >> 2, tg = lane & 3;
    const int mo = blockIdx.y * 64, no = blockIdx.x * 128;
    const __nv_bfloat16* Xhb = Xh + blockIdx.z * sX;
    const __nv_bfloat16* Xlb = Xl + blockIdx.z * sX;
    float* Yb = Y + blockIdx.z * sY;

    // A loader: row am (0..63), 16 k's at ak
    const int am = tid >> 1, ak = (tid & 1) * 16;
    // B loader: 4 units/thread; unit I: rows bk0+8I, bk0+8I+1; cols bn..bn+3
    const int bn = (lane) * 4 + ((tid >> 5) & 0) * 0 + ( (tid & 31) * 0 );
    const int bcol = (tid & 31) * 4;
    const int bk0 = (tid >> 5) * 2;

    float acc[2][8][4] = {};
    const int nch = K >> 5;

    uint4 awh[2], awl[2];
    uint2 bh[4][2], bl[4][2];

#define LOAD_REGS(kt)                                                            \
    {                                                                            \
        const __nv_bfloat16* Ah = Wh + (long)(mo + am) * K + (kt) + ak;          \
        const __nv_bfloat16* Al = Wl + (long)(mo + am) * K + (kt) + ak;          \
        awh[0] = *(const uint4*)Ah; awh[1] = *(const uint4*)(Ah + 8);            \
        awl[0] = *(const uint4*)Al; awl[1] = *(const uint4*)(Al + 8);            \
        _Pragma("unroll")                                                        \
        for (int I = 0; I < 4; I++) {                                            \
            int kr = (kt) + bk0 + 8 * I;                                         \
            const __nv_bfloat16* Bh = Xhb + (long)kr * 1024 + no + bcol;         \
            const __nv_bfloat16* Bl = Xlb + (long)kr * 1024 + no + bcol;         \
            bh[I][0] = *(const uint2*)Bh; bh[I][1] = *(const uint2*)(Bh + 1024); \
            bl[I][0] = *(const uint2*)Bl; bl[I][1] = *(const uint2*)(Bl + 1024); \
        }                                                                        \
    }

#define STORE_SMEM(buf)                                                          \
    {                                                                            \
        __nv_bfloat16* base = smd + (buf) * GBUF;                                \
        uint32_t* dH = (uint32_t*)(base + am * APITCH + ak);                     \
        uint32_t* dL = (uint32_t*)(base + A_PLANE + am * APITCH + ak);           \
        *(uint4*)dH = awh[0]; *(uint4*)(dH + 4) = awh[1];                        \
        *(uint4*)dL = awl[0]; *(uint4*)(dL + 4) = awl[1];                        \
        __nv_bfloat16* BH = base + 2 * A_PLANE;                                  \
        __nv_bfloat16* BL = base + 2 * A_PLANE + B_PLANE;                        \
        _Pragma("unroll")                                                        \
        for (int I = 0; I < 4; I++) {                                            \
            int kr = bk0 + 8 * I;                                                \
            *(uint2*)(BH + kr * BPITCH + bcol)       = bh[I][0];                 \
            *(uint2*)(BH + (kr + 1) * BPITCH + bcol) = bh[I][1];                 \
            *(uint2*)(BL + kr * BPITCH + bcol)       = bl[I][0];                 \
            *(uint2*)(BL + (kr + 1) * BPITCH + bcol) = bl[I][1];                 \
        }                                                                        \
    }

    LOAD_REGS(0);
    STORE_SMEM(0);
    if (nch > 1) LOAD_REGS(32);
    __syncthreads();

    // ldmatrix lane-address components (units)
    const int a_row_l = lane & 15;          // row within 16-row block
    const int a_khalf = (lane >> 4) * 8;    // k half select
    const int b_krow  = (lane & 7) + 8 * ((lane >> 3) & 1);  // k row within 16
    const int b_nhalf = (lane >> 4) * 8;    // n half select

    for (int ch = 0; ch < nch; ch++) {
        if (ch + 1 < nch) STORE_SMEM((ch + 1) & 1);
        if (ch + 2 < nch) LOAD_REGS((ch + 2) * 32);

        uint32_t bufu = (uint32_t)((ch & 1) * GBUF) * 2u;   // bytes
        uint32_t AH = smem_base + bufu;
        uint32_t ALo = AH + A_PLANE * 2;
        uint32_t BH = AH + 4 * A_PLANE;                     // 2*A_PLANE units *2B
        uint32_t BLo = BH + B_PLANE * 2;

#pragma unroll
        for (int k0 = 0; k0 < 32; k0 += 16) {
            uint32_t ah[2][4], al[2][4];
#pragma unroll
            for (int mt = 0; mt < 2; mt++) {
                int rowb = wm * 32 + mt * 16;
                uint32_t off = (uint32_t)((rowb + a_row_l) * APITCH + k0 + a_khalf) * 2u;
                ldsm4(ah[mt][0], ah[mt][1], ah[mt][2], ah[mt][3], AH + off);
                ldsm4(al[mt][0], al[mt][1], al[mt][2], al[mt][3], ALo + off);
            }
#pragma unroll
            for (int ntp = 0; ntp < 4; ntp++) {
                int nbase = wn * 64 + ntp * 16;
                uint32_t off = (uint32_t)((k0 + b_krow) * BPITCH + nbase + b_nhalf) * 2u;
                uint32_t bh0, bh1, bh2, bh3, bl0, bl1, bl2, bl3;
                ldsm4t(bh0, bh1, bh2, bh3, BH + off);
                ldsm4t(bl0, bl1, bl2, bl3, BLo + off);
#pragma unroll
                for (int mt = 0; mt < 2; mt++) {
                    float* d0 = acc[mt][ntp * 2];
                    float* d1 = acc[mt][ntp * 2 + 1];
                    mma16816(d0, ah[mt][0], ah[mt][1], ah[mt][2], ah[mt][3], bh0, bh1);
                    mma16816(d0, al[mt][0], al[mt][1], al[mt][2], al[mt][3], bh0, bh1);
                    mma16816(d0, ah[mt][0], ah[mt][1], ah[mt][2], ah[mt][3], bl0, bl1);
                    mma16816(d1, ah[mt][0], ah[mt][1], ah[mt][2], ah[mt][3], bh2, bh3);
                    mma16816(d1, al[mt][0], al[mt][1], al[mt][2], al[mt][3], bh2, bh3);
                    mma16816(d1, ah[mt][0], ah[mt][1], ah[mt][2], ah[mt][3], bl2, bl3);
                }
            }
        }
        if (ch + 1 < nch) __syncthreads();
    }

#pragma unroll
    for (int mt = 0; mt < 2; mt++) {
        int r0 = mo + wm * 32 + mt * 16 + g;
        int r1 = r0 + 8;
        float bv0 = bias ? bias[r0] : 0.f;
        float bv1 = bias ? bias[r1] : 0.f;
#pragma unroll
        for (int nt = 0; nt < 8; nt++) {
            int c = no + wn * 64 + nt * 8 + 2 * tg;
            float* d = acc[mt][nt];
            *(float2*)(Yb + (long)r0 * 1024 + c) = make_float2(d[0] + bv0, d[1] + bv0);
            *(float2*)(Yb + (long)r1 * 1024 + c) = make_float2(d[2] + bv1, d[3] + bv1);
        }
    }
#undef LOAD_REGS
#undef STORE_SMEM
}

// ---------------------------------------------------------------------------
// Fused BN: stats + apply + bf16 split (passing R9 version, unchanged)
// ---------------------------------------------------------------------------
__global__ __launch_bounds__(256) void bn_fused_split(
    const float* __restrict__ X, __nv_bfloat16* __restrict__ H,
    __nv_bfloat16* __restrict__ L,
    const float* __restrict__ g, const float* __restrict__ be,
    long bsX, long bsP, int relu)
{
    int m = blockIdx.x, tid = threadIdx.x;
    float4 v[4];
    float s = 0.f, sq = 0.f;
#pragma unroll
    for (int b = 0; b < 4; b++) {
        v[b] = *(const float4*)(X + b * bsX + (long)m * 1024 + tid * 4);
        s  += v[b].x + v[b].y + v[b].z + v[b].w;
        sq += v[b].x*v[b].x + v[b].y*v[b].y + v[b].z*v[b].z + v[b].w*v[b].w;
    }
#pragma unroll
    for (int o = 16; o; o >>= 1) {
        s  += __shfl_xor_sync(0xffffffffu, s, o);
        sq += __shfl_xor_sync(0xffffffffu, sq, o);
    }
    __shared__ float ps[8], pq[8], bsc[1], bsh[1];
    if ((tid & 31) == 0) { ps[tid >> 5] = s; pq[tid >> 5] = sq; }
    __syncthreads();
    if (tid == 0) {
        s = 0.f; sq = 0.f;
#pragma unroll
        for (int i = 0; i < 8; i++) { s += ps[i]; sq += pq[i]; }
        float mean = s * (1.f / 4096.f);
        float var  = sq * (1.f / 4096.f) - mean * mean;
        float rstd = rsqrtf(var + 1e-5f);
        float sc = g[m] * rstd;
        bsc[0] = sc;
        bsh[0] = be[m] - mean * sc;
    }
    __syncthreads();
    float sc = bsc[0], sh = bsh[0];
#pragma unroll
    for (int b = 0; b < 4; b++) {
        float4 w = v[b];
        w.x = w.x * sc + sh; w.y = w.y * sc + sh;
        w.z = w.z * sc + sh; w.w = w.w * sc + sh;
        if (relu) {
            w.x = fmaxf(w.x, 0.f); w.y = fmaxf(w.y, 0.f);
            w.z = fmaxf(w.z, 0.f); w.w = fmaxf(w.w, 0.f);
        }
        __nv_bfloat16 h[4], l[4];
        splitf(w.x, h[0], l[0]); splitf(w.y, h[1], l[1]);
        splitf(w.z, h[2], l[2]); splitf(w.w, h[3], l[3]);
        long o = (long)b * bsP + (long)m * 1024 + tid * 4;
        *(uint2*)(H + o) = *(uint2*)h;
        *(uint2*)(L + o) = *(uint2*)l;
    }
}

__global__ __launch_bounds__(256) void bn_fused_out(
    const float* __restrict__ X, float* __restrict__ Y,
    const float* __restrict__ g, const float* __restrict__ be,
    long bsX, long bsY, int relu)
{
    int m = blockIdx.x, tid = threadIdx.x;
    float4 v[4];
    float s = 0.f, sq = 0.f;
#pragma unroll
    for (int b = 0; b < 4; b++) {
        v[b] = *(const float4*)(X + b * bsX + (long)m * 1024 + tid * 4);
        s  += v[b].x + v[b].y + v[b].z + v[b].w;
        sq += v[b].x*v[b].x + v[b].y*v[b].y + v[b].z*v[b].z + v[b].w*v[b].w;
    }
#pragma unroll
    for (int o = 16; o; o >>= 1) {
        s  += __shfl_xor_sync(0xffffffffu, s, o);
        sq += __shfl_xor_sync(0xffffffffu, sq, o);
    }
    __shared__ float ps[8], pq[8], bsc[1], bsh[1];
    if ((tid & 31) == 0) { ps[tid >> 5] = s; pq[tid >> 5] = sq; }
    __syncthreads();
    if (tid == 0) {
        s = 0.f; sq = 0.f;
#pragma unroll
        for (int i = 0; i < 8; i++) { s += ps[i]; sq += pq[i]; }
        float mean = s * (1.f / 4096.f);
        float var  = sq * (1.f / 4096.f) - mean * mean;
        float rstd = rsqrtf(var + 1e-5f);
        float sc = g[m] * rstd;
        bsc[0] = sc;
        bsh[0] = be[m] - mean * sc;
    }
    __syncthreads();
    float sc = bsc[0], sh = bsh[0];
#pragma unroll
    for (int b = 0; b < 4; b++) {
        float4 w = v[b];
        w.x = w.x * sc + sh; w.y = w.y * sc + sh;
        w.z = w.z * sc + sh; w.w = w.w * sc + sh;
        if (relu) {
            w.x = fmaxf(w.x, 0.f); w.y = fmaxf(w.y, 0.f);
            w.z = fmaxf(w.z, 0.f); w.w = fmaxf(w.w, 0.f);
        }
        *(float4*)(Y + (long)b * bsY + (long)m * 1024 + tid * 4) = w;
    }
}

// ---------------------------------------------------------------------------
// Tensor-core flash attention (passing R9 version, unchanged)
// ---------------------------------------------------------------------------
#define QP 24
#define KP 24
#define VP 136

__global__ __launch_bounds__(256) void attn_kernel(const float* __restrict__ Yq,
                                                   float* __restrict__ O) {
    __shared__ __nv_bfloat16 QH[32*QP], QL[32*QP];
    __shared__ __nv_bfloat16 KH[128*KP], KL[128*KP];
    __shared__ __nv_bfloat16 VH[16*VP], VL[16*VP];
    __shared__ float redmax[4][32], redsum[4][32];
    __shared__ float Of[4][2][16][17];
    __shared__ float rsinv[32];

    int b = blockIdx.z, head = blockIdx.y >> 2, t = blockIdx.y & 3;
    int r0 = blockIdx.x * 32;
    const float* Yb = Yq + (long)b * 768 * 1024;
    int tid = threadIdx.x, lane = tid & 31, wid = tid >> 5;
    int wm = wid & 1, wn = wid >> 1;
    int g = lane >> 2, tg = lane & 3;

    for (int i = tid; i < 512; i += 256) {
        int dd = i >> 5, q = i & 31;
        float v = Yb[(head * 192 + dd * 4 + t) * 1024 + r0 + q];
        __nv_bfloat16 h, l; splitf(v, h, l);
        QH[q * QP + dd] = h;
        QL[q * QP + dd] = l;
    }
    __syncthreads();

    uint32_t qh[4], ql[4];
    {
        int r = wm * 16 + g;
        qh[0] = *(uint32_t*)&QH[r * QP + 2*tg];
        qh[1] = *(uint32_t*)&QH[(r + 8) * QP + 2*tg];
        qh[2] = *(uint32_t*)&QH[r * QP + 2*tg + 8];
        qh[3] = *(uint32_t*)&QH[(r + 8) * QP + 2*tg + 8];
        ql[0] = *(uint32_t*)&QL[r * QP + 2*tg];
        ql[1] = *(uint32_t*)&QL[(r + 8) * QP + 2*tg];
        ql[2] = *(uint32_t*)&QL[r * QP + 2*tg + 8];
        ql[3] = *(uint32_t*)&QL[(r + 8) * QP + 2*tg + 8];
    }

    float od[2][4] = {};
    float rm_lo = -1e30f, rm_hi = -1e30f, rs_lo = 0.f, rs_hi = 0.f;
    const float sc = 0.25f;
    const int rlo = wm * 16 + g, rhi = rlo + 8;

    for (int ch = 0; ch < 8; ch++) {
        __syncthreads();
        for (int i = tid; i < 2048; i += 256) {
            int dd = i >> 7, key = i & 127;
            float kval = Yb[(head * 192 + 64 + dd * 4 + t) * 1024 + ch * 128 + key];
            __nv_bfloat16 h, l; splitf(kval, h, l);
            KH[key * KP + dd] = h; KL[key * KP + dd] = l;
            float vval = Yb[(head * 192 + 128 + dd * 4 + t) * 1024 + ch * 128 + key];
            splitf(vval, h, l);
            VH[dd * VP + key] = h; VL[dd * VP + key] = l;
        }
        __syncthreads();

        float sacc[4][4] = {};
#pragma unroll
        for (int nt = 0; nt < 4; nt++) {
            int nb = wn * 32 + nt * 8 + g;
            uint32_t kb0 = *(uint32_t*)&KH[nb * KP + 2*tg];
            uint32_t kb1 = *(uint32_t*)&KH[nb * KP + 2*tg + 8];
            uint32_t kc0 = *(uint32_t*)&KL[nb * KP + 2*tg];
            uint32_t kc1 = *(uint32_t*)&KL[nb * KP + 2*tg + 8];
            mma16816(sacc[nt], qh[0], qh[1], qh[2], qh[3], kb0, kb1);
            mma16816(sacc[nt], ql[0], ql[1], ql[2], ql[3], kb0, kb1);
            mma16816(sacc[nt], qh[0], qh[1], qh[2], qh[3], kc0, kc1);
        }
        float mx_lo = -1e30f, mx_hi = -1e30f;
#pragma unroll
        for (int nt = 0; nt < 4; nt++) {
            sacc[nt][0] *= sc; sacc[nt][1] *= sc;
            sacc[nt][2] *= sc; sacc[nt][3] *= sc;
            mx_lo = fmaxf(mx_lo, fmaxf(sacc[nt][0], sacc[nt][1]));
            mx_hi = fmaxf(mx_hi, fmaxf(sacc[nt][2], sacc[nt][3]));
        }
        mx_lo = fmaxf(mx_lo, __shfl_xor_sync(0xffffffffu, mx_lo, 1));
        mx_lo = fmaxf(mx_lo, __shfl_xor_sync(0xffffffffu, mx_lo, 2));
        mx_hi = fmaxf(mx_hi, __shfl_xor_sync(0xffffffffu, mx_hi, 1));
        mx_hi = fmaxf(mx_hi, __shfl_xor_sync(0xffffffffu, mx_hi, 2));
        if (tg == 0) { redmax[wn][rlo] = mx_lo; redmax[wn][rhi] = mx_hi; }
        __syncthreads();

        float cm_lo = fmaxf(fmaxf(redmax[0][rlo], redmax[1][rlo]),
                            fmaxf(redmax[2][rlo], redmax[3][rlo]));
        float cm_hi = fmaxf(fmaxf(redmax[0][rhi], redmax[1][rhi]),
                            fmaxf(redmax[2][rhi], redmax[3][rhi]));
        float nm_lo = fmaxf(rm_lo, cm_lo), f_lo = __expf(rm_lo - nm_lo);
        float nm_hi = fmaxf(rm_hi, cm_hi), f_hi = __expf(rm_hi - nm_hi);
        rm_lo = nm_lo; rm_hi = nm_hi;

        float e[4][4];
        float sum_lo = 0.f, sum_hi = 0.f;
#pragma unroll
        for (int nt = 0; nt < 4; nt++) {
            e[nt][0] = __expf(sacc[nt][0] - nm_lo);
            e[nt][1] = __expf(sacc[nt][1] - nm_lo);
            e[nt][2] = __expf(sacc[nt][2] - nm_hi);
            e[nt][3] = __expf(sacc[nt][3] - nm_hi);
            sum_lo += e[nt][0] + e[nt][1];
            sum_hi += e[nt][2] + e[nt][3];
        }
        sum_lo += __shfl_xor_sync(0xffffffffu, sum_lo, 1);
        sum_lo += __shfl_xor_sync(0xffffffffu, sum_lo, 2);
        sum_hi += __shfl_xor_sync(0xffffffffu, sum_hi, 1);
        sum_hi += __shfl_xor_sync(0xffffffffu, sum_hi, 2);
        if (tg == 0) { redsum[wn][rlo] = sum_lo; redsum[wn][rhi] = sum_hi; }
        __syncthreads();

        rs_lo = rs_lo * f_lo + redsum[0][rlo] + redsum[1][rlo] + redsum[2][rlo] + redsum[3][rlo];
        rs_hi = rs_hi * f_hi + redsum[0][rhi] + redsum[1][rhi] + redsum[2][rhi] + redsum[3][rhi];

#pragma unroll
        for (int dn = 0; dn < 2; dn++) {
            od[dn][0] *= f_lo; od[dn][1] *= f_lo;
            od[dn][2] *= f_hi; od[dn][3] *= f_hi;
        }
        uint32_t ph[2][4], pl[2][4];
#pragma unroll
        for (int ks = 0; ks < 2; ks++) {
            pack2(e[2*ks][0],   e[2*ks][1],   ph[ks][0], pl[ks][0]);
            pack2(e[2*ks][2],   e[2*ks][3],   ph[ks][1], pl[ks][1]);
            pack2(e[2*ks+1][0], e[2*ks+1][1], ph[ks][2], pl[ks][2]);
            pack2(e[2*ks+1][2], e[2*ks+1][3], ph[ks][3], pl[ks][3]);
        }
#pragma unroll
        for (int ks = 0; ks < 2; ks++) {
#pragma unroll
            for (int dn = 0; dn < 2; dn++) {
                int vrow = dn * 8 + g;
                int kk = wn * 32 + ks * 16;
                uint32_t vb0 = *(uint32_t*)&VH[vrow * VP + kk + 2*tg];
                uint32_t vb1 = *(uint32_t*)&VH[vrow * VP + kk + 2*tg + 8];
                uint32_t vc0 = *(uint32_t*)&VL[vrow * VP + kk + 2*tg];
                uint32_t vc1 = *(uint32_t*)&VL[vrow * VP + kk + 2*tg + 8];
                mma16816(od[dn], ph[ks][0], ph[ks][1], ph[ks][2], ph[ks][3], vb0, vb1);
                mma16816(od[dn], pl[ks][0], pl[ks][1], pl[ks][2], pl[ks][3], vb0, vb1);
                mma16816(od[dn], ph[ks][0], ph[ks][1], ph[ks][2], ph[ks][3], vc0, vc1);
            }
        }
    }

#pragma unroll
    for (int dn = 0; dn < 2; dn++) {
        Of[wn][wm][g][dn*8 + 2*tg]       = od[dn][0];
        Of[wn][wm][g][dn*8 + 2*tg + 1]   = od[dn][1];
        Of[wn][wm][g+8][dn*8 + 2*tg]     = od[dn][2];
        Of[wn][wm][g+8][dn*8 + 2*tg + 1] = od[dn][3];
    }
    if (tg == 0 && wn == 0) {
        rsinv[rlo] = 1.f / rs_lo;
        rsinv[rhi] = 1.f / rs_hi;
    }
    __syncthreads();

    int q = tid & 31, dd = tid >> 5;
    float inv = rsinv[q];
    int qm = q >> 4, qr = q & 15;
    float* Ob = O + (long)b * 256 * 1024;
#pragma unroll
    for (int h2 = 0; h2 < 2; h2++) {
        int D = dd + h2 * 8;
        float v = (Of[0][qm][qr][D] + Of[1][qm][qr][D] +
                   Of[2][qm][qr][D] + Of[3][qm][qr][D]) * inv;
        Ob[(head * 64 + D * 4 + t) * 1024 + r0 + q] = v;
    }
}

// ---------------------------------------------------------------------------
// PE conv + residual; emits bf16 hi/lo split planes (unchanged)
// ---------------------------------------------------------------------------
__global__ void pe_kernel(const float* __restrict__ I, const float* __restrict__ pw,
                          const float* __restrict__ pb,
                          __nv_bfloat16* __restrict__ H, __nv_bfloat16* __restrict__ L,
                          long bsP) {
    int idx = blockIdx.x * 256 + threadIdx.x;
    if (idx >= 4 * 256 * 1024) return;
    int p = idx & 1023;
    int m = (idx >> 10) & 255;
    int b = idx >> 18;
    int h = p >> 5, w = p & 31;
    int co = m >> 2, t = m & 3, g = co >> 2;
    const float* Ib = I + (long)b * 256 * 1024;
    float acc = Ib[m * 1024 + p] + pb[m];
#pragma unroll
    for (int s = 0; s < 4; s++) {
        float sg = c_sgn[t * 4 + s];
        const float* wc = pw + ((long)c_cmp[t * 4 + s] * 64 + co) * 36;
#pragma unroll
        for (int cil = 0; cil < 4; cil++) {
            const float* in = Ib + ((g * 4 + cil) * 4 + s) * 1024;
            const float* wk = wc + cil * 9;
            float part = 0.f;
#pragma unroll
            for (int kh = 0; kh < 3; kh++) {
                int hh = h + kh - 1;
                if (hh < 0 || hh > 31) continue;
#pragma unroll
                for (int kw = 0; kw < 3; kw++) {
                    int ww = w + kw - 1;
                    if (ww < 0 || ww > 31) continue;
                    part += in[hh * 32 + ww] * wk[kh * 3 + kw];
                }
            }
            acc += sg * part;
        }
    }
    __nv_bfloat16 hh, ll;
    splitf(acc, hh, ll);
    long o = (long)b * bsP + (long)m * 1024 + p;
    H[o] = hh;
    L[o] = ll;
}

// ---------------------------------------------------------------------------
extern "C" void kernel_launch(void* const* d_in, const int* in_sizes, int n_in,
                              void* d_out, int out_size) {
    const float* x      = (const float*)d_in[0];
    const float* cv1_w  = (const float*)d_in[1];
    const float* bn1_g  = (const float*)d_in[2];
    const float* bn1_b  = (const float*)d_in[3];
    const float* qkv_w  = (const float*)d_in[4];
    const float* qkv_b  = (const float*)d_in[5];
    const float* proj_w = (const float*)d_in[6];
    const float* proj_b = (const float*)d_in[7];
    const float* pe_w   = (const float*)d_in[8];
    const float* pe_b   = (const float*)d_in[9];
    const float* ang    = (const float*)d_in[10];
    const float* anb    = (const float*)d_in[11];
    const float* f1w    = (const float*)d_in[12];
    const float* f1g    = (const float*)d_in[13];
    const float* f1b    = (const float*)d_in[14];
    const float* f2w    = (const float*)d_in[15];
    const float* f2g    = (const float*)d_in[16];
    const float* f2b    = (const float*)d_in[17];
    const float* cv2_w  = (const float*)d_in[18];
    const float* bn2_g  = (const float*)d_in[19];
    const float* bn2_b  = (const float*)d_in[20];

    float *buf1, *buf2, *buf3;
    __nv_bfloat16 *xh0, *xl0, *xh1, *xl1, *Wh, *Wl;
    cudaGetSymbolAddress((void**)&buf1, g_buf1);
    cudaGetSymbolAddress((void**)&buf2, g_buf2);
    cudaGetSymbolAddress((void**)&buf3, g_buf3);
    cudaGetSymbolAddress((void**)&xh0,  g_xh0);
    cudaGetSymbolAddress((void**)&xl0,  g_xl0);
    cudaGetSymbolAddress((void**)&xh1,  g_xh1);
    cudaGetSymbolAddress((void**)&xl1,  g_xl1);
    cudaGetSymbolAddress((void**)&Wh,   g_Wh);
    cudaGetSymbolAddress((void**)&Wl,   g_Wl);

    const long S512 = 512L * 1024, S768 = 768L * 1024, S256 = 256L * 1024;

    cudaFuncSetAttribute(mma_gemm_kernel,
                         cudaFuncAttributeMaxDynamicSharedMemorySize, GEMM_SMEM);

    expand_all_kernel<<<dim3(32, 6), 256>>>(cv1_w, qkv_w, proj_w, f1w, f2w, cv2_w, Wh, Wl);
    split_x_kernel<<<2048, 256>>>(x, xh0, xl0);

    // cv1 + iqbn(+relu) -> P1 (512 rows)
    mma_gemm_kernel<<<dim3(8, 8, 4), 128, GEMM_SMEM>>>(Wh + OFF_W1, Wl + OFF_W1, xh0, xl0,
                                                        buf1, nullptr, 512, 512, S512, S512);
    bn_fused_split<<<512, 256>>>(buf1, xh1, xl1, bn1_g, bn1_b, S512, S512, 1);

    // qkv
    mma_gemm_kernel<<<dim3(8, 12, 4), 128, GEMM_SMEM>>>(Wh + OFF_WQ, Wl + OFF_WQ, xh1, xl1,
                                                         buf2, qkv_b, 768, 256, S512, S768);

    // attention (tensor cores)
    attn_kernel<<<dim3(32, 16, 4), 256>>>(buf2, buf3);

    // pe conv + residual -> P0
    pe_kernel<<<4096, 256>>>(buf3, pe_w, pe_b, xh0, xl0, S512);

    // proj + attn_norm -> P0
    mma_gemm_kernel<<<dim3(8, 4, 4), 128, GEMM_SMEM>>>(Wh + OFF_WP, Wl + OFF_WP, xh0, xl0,
                                                        buf3, proj_b, 256, 256, S512, S256);
    bn_fused_split<<<256, 256>>>(buf3, xh0, xl0, ang, anb, S256, S512, 0);

    // ffn1 + bn(+relu) -> P0
    mma_gemm_kernel<<<dim3(8, 8, 4), 128, GEMM_SMEM>>>(Wh + OFF_F1, Wl + OFF_F1, xh0, xl0,
                                                        buf2, nullptr, 512, 256, S512, S512);
    bn_fused_split<<<512, 256>>>(buf2, xh0, xl0, f1g, f1b, S512, S512, 1);

    // ffn2 + bn -> P1 rows 0..255 (rows 256..511 = b from bn1)
    mma_gemm_kernel<<<dim3(8, 4, 4), 128, GEMM_SMEM>>>(Wh + OFF_F2, Wl + OFF_F2, xh0, xl0,
                                                        buf3, nullptr, 256, 512, S512, S256);
    bn_fused_split<<<256, 256>>>(buf3, xh1, xl1, f2g, f2b, S256, S512, 0);

    // cv2 on concat + bn + relu -> d_out
    mma_gemm_kernel<<<dim3(8, 8, 4), 128, GEMM_SMEM>>>(Wh + OFF_C2, Wl + OFF_C2, xh1, xl1,
                                                        buf2, nullptr, 512, 512, S512, S512);
    bn_fused_out<<<512, 256>>>(buf2, (float*)d_out, bn2_g, bn2_b, S512, S512, 1);
}